// round 1
// baseline (speedup 1.0000x reference)
#include <cuda_runtime.h>
#include <math.h>
#include <stdint.h>

#define TT 2048
#define HH 2048
#define NH 16
#define NKV 4
#define HD 128
#define NE 16
#define TOPK 4
#define NGRP 4
#define GSZ 4
#define TGRP 2
#define IM 1024
#define QKVD 3072
#define ATT_SCALE 0.08838834764831845f
#define EPSV 1e-6f

// ---------------- scratch (device globals; no allocations) ----------------
__device__ float g_res1[(size_t)TT * HH];
__device__ float g_x[(size_t)TT * HH];
__device__ float g_qkv[(size_t)TT * QKVD];
__device__ float g_scores[(size_t)NH * TT * TT];     // 268 MB
__device__ float g_attn[(size_t)TT * HH];
__device__ float g_x2[(size_t)TT * HH];
__device__ float g_hbuf[(size_t)NE * TT * (2 * IM)]; // 256 MB
__device__ int   g_cnt[NE];
__device__ int   g_tok[NE * TT];
__device__ float g_wgt[NE * TT];
__device__ int   g_topk_id[TT * TOPK];
__device__ float g_topk_w[TT * TOPK];

// ---------------- residual add + rmsnorm ----------------
__global__ void k_addnorm(const float* __restrict__ hs, const float* __restrict__ res,
                          const float* __restrict__ w, float* __restrict__ res_out,
                          float* __restrict__ x_out) {
    int t = blockIdx.x;
    __shared__ float red[256];
    float ss = 0.f;
    for (int i = threadIdx.x; i < HH; i += 256) {
        float v = hs[(size_t)t * HH + i] + res[(size_t)t * HH + i];
        res_out[(size_t)t * HH + i] = v;
        ss += v * v;
    }
    red[threadIdx.x] = ss; __syncthreads();
    for (int s = 128; s > 0; s >>= 1) { if (threadIdx.x < s) red[threadIdx.x] += red[threadIdx.x + s]; __syncthreads(); }
    float inv = rsqrtf(red[0] / (float)HH + EPSV);
    for (int i = threadIdx.x; i < HH; i += 256)
        x_out[(size_t)t * HH + i] = res_out[(size_t)t * HH + i] * inv * w[i];
}

__global__ void k_norm(const float* __restrict__ in, const float* __restrict__ w,
                       float* __restrict__ x_out) {
    int t = blockIdx.x;
    __shared__ float red[256];
    float ss = 0.f;
    for (int i = threadIdx.x; i < HH; i += 256) { float v = in[(size_t)t * HH + i]; ss += v * v; }
    red[threadIdx.x] = ss; __syncthreads();
    for (int s = 128; s > 0; s >>= 1) { if (threadIdx.x < s) red[threadIdx.x] += red[threadIdx.x + s]; __syncthreads(); }
    float inv = rsqrtf(red[0] / (float)HH + EPSV);
    for (int i = threadIdx.x; i < HH; i += 256)
        x_out[(size_t)t * HH + i] = in[(size_t)t * HH + i] * inv * w[i];
}

// ---------------- RoPE (in-place on q and k heads of qkv) ----------------
__global__ void k_rope(const int* __restrict__ pos, float* __restrict__ qkv) {
    int t = blockIdx.x;
    float fp = (float)pos[t];
    for (int idx = threadIdx.x; idx < (NH + NKV) * 64; idx += 256) {
        int hh = idx >> 6;
        int d = idx & 63;
        float inv = powf(1e6f, -(float)d / 64.f);
        float ang = fp * inv;
        float c = cosf(ang), s = sinf(ang);
        float* p = qkv + (size_t)t * QKVD + hh * HD;
        float x1 = p[d], x2 = p[d + 64];
        p[d] = x1 * c - x2 * s;
        p[d + 64] = x2 * c + x1 * s;
    }
}

// ---------------- generic tiled SGEMM ----------------
// C[z] = alpha * A[z] (x) op(B[z]) with epilogue variants.
// EPI: 0 plain store, 1 causal tile-skip + store (scores), 2 add X (residual),
//      3 atomicAdd into C[gidx[r]] scaled by X[r] (MoE scatter-down).
#define BM 64
#define BN 64
#define BK 16

template <bool TB, bool GA, int EPI>
__global__ void gemm_k(const float* __restrict__ A0, int lda, long saz,
                       const float* __restrict__ B0, int ldb, long sbz, int bdiv,
                       float* __restrict__ C0, int ldc, long scz,
                       int M0, int N, int K,
                       const int* __restrict__ Mptr,
                       const int* __restrict__ gidx0, int sgz,
                       const float* __restrict__ X0, long sxz,
                       float alpha, int klimit) {
    int z = blockIdx.z;
    int M = Mptr ? Mptr[z] : M0;
    int row0 = blockIdx.y * BM, col0 = blockIdx.x * BN;
    if (row0 >= M) return;
    if (EPI == 1 && col0 > row0 + BM - 1) return;  // fully-masked causal tile

    const float* A = A0 + (long)z * saz;
    const float* B = B0 + (long)(z / bdiv) * sbz;
    float* C = C0 + (long)z * scz;
    const int* gidx = gidx0 ? gidx0 + (long)z * sgz : nullptr;
    const float* X = X0 ? X0 + (long)z * sxz : nullptr;

    int Keff = K;
    if (klimit) { int km = row0 + BM; Keff = km < K ? km : K; }

    __shared__ float As[BK][BM];
    __shared__ float Bs[BK][BN];

    int tid = threadIdx.x;
    int tx = tid & 15, ty = tid >> 4;

    // A loader coords: row m = tid/4, k chunk = (tid%4)*4
    int ar = tid >> 2, ac = (tid & 3) * 4;
    bool rvalid = (row0 + ar) < M;
    long grow;
    if (GA) grow = rvalid ? (long)gidx[row0 + ar] : 0;
    else    grow = row0 + ar;

    float acc[4][4];
#pragma unroll
    for (int i = 0; i < 4; i++)
#pragma unroll
        for (int j = 0; j < 4; j++) acc[i][j] = 0.f;

    for (int k0 = 0; k0 < Keff; k0 += BK) {
        // load A tile
#pragma unroll
        for (int i = 0; i < 4; i++) {
            int kk = k0 + ac + i;
            float v = 0.f;
            if (rvalid && kk < K) v = A[grow * lda + kk];
            As[ac + i][ar] = v;
        }
        // load B tile
        if (TB) {
            int br = tid >> 2, bc = (tid & 3) * 4; // n = br, k chunk = bc
#pragma unroll
            for (int i = 0; i < 4; i++) {
                int kk = k0 + bc + i;
                int nn = col0 + br;
                float v = 0.f;
                if (nn < N && kk < K) v = B[(long)nn * ldb + kk];
                Bs[bc + i][br] = v;
            }
        } else {
            int br = tid >> 4, bc = (tid & 15) * 4; // k = br, n chunk = bc
#pragma unroll
            for (int j = 0; j < 4; j++) {
                int kk = k0 + br;
                int nn = col0 + bc + j;
                float v = 0.f;
                if (nn < N && kk < K) v = B[(long)kk * ldb + nn];
                Bs[br][bc + j] = v;
            }
        }
        __syncthreads();
#pragma unroll
        for (int kk = 0; kk < BK; kk++) {
            float ra[4], rb[4];
#pragma unroll
            for (int i = 0; i < 4; i++) ra[i] = As[kk][ty * 4 + i];
#pragma unroll
            for (int j = 0; j < 4; j++) rb[j] = Bs[kk][tx * 4 + j];
#pragma unroll
            for (int i = 0; i < 4; i++)
#pragma unroll
                for (int j = 0; j < 4; j++) acc[i][j] += ra[i] * rb[j];
        }
        __syncthreads();
    }

#pragma unroll
    for (int i = 0; i < 4; i++) {
        int r = row0 + ty * 4 + i;
        if (r >= M) continue;
#pragma unroll
        for (int j = 0; j < 4; j++) {
            int c = col0 + tx * 4 + j;
            if (c >= N) continue;
            float v = acc[i][j] * alpha;
            if (EPI == 2) {
                C[(size_t)r * ldc + c] = v + X[(size_t)r * ldc + c];
            } else if (EPI == 3) {
                atomicAdd(&C[(size_t)gidx[r] * ldc + c], X[r] * v);
            } else {
                C[(size_t)r * ldc + c] = v;
            }
        }
    }
}

// ---------------- softmax over causal row ----------------
__global__ void k_softmax(float* __restrict__ sc) {
    int t = blockIdx.x, h = blockIdx.y;
    float* row = sc + ((size_t)h * TT + t) * TT;
    int n = t + 1;
    __shared__ float red[256];
    int tid = threadIdx.x;
    float m = -3.4e38f;
    for (int i = tid; i < n; i += 256) m = fmaxf(m, row[i]);
    red[tid] = m; __syncthreads();
    for (int s = 128; s > 0; s >>= 1) { if (tid < s) red[tid] = fmaxf(red[tid], red[tid + s]); __syncthreads(); }
    m = red[0]; __syncthreads();
    float sum = 0.f;
    for (int i = tid; i < n; i += 256) { float e = expf(row[i] - m); row[i] = e; sum += e; }
    red[tid] = sum; __syncthreads();
    for (int s = 128; s > 0; s >>= 1) { if (tid < s) red[tid] += red[tid + s]; __syncthreads(); }
    float inv = 1.f / red[0];
    for (int i = tid; i < n; i += 256) row[i] *= inv;
    for (int i = n + tid; i < TT; i += 256) row[i] = 0.f;
}

// ---------------- MoE gating (top-2 groups, top-4 experts) ----------------
__global__ void k_gate(const float* __restrict__ x2, const float* __restrict__ gw,
                       const float* __restrict__ gb,
                       int* __restrict__ ids, float* __restrict__ ws) {
    int t = blockIdx.x;
    int tid = threadIdx.x, wid = tid >> 5, lane = tid & 31;
    __shared__ float logit[NE];
    for (int e = wid; e < NE; e += 8) {
        float acc = 0.f;
        for (int i = lane; i < HH; i += 32)
            acc += x2[(size_t)t * HH + i] * gw[(size_t)e * HH + i];
#pragma unroll
        for (int o = 16; o > 0; o >>= 1) acc += __shfl_down_sync(0xffffffffu, acc, o);
        if (lane == 0) logit[e] = acc;
    }
    __syncthreads();
    if (tid == 0) {
        float s[NE], sc[NE];
        for (int e = 0; e < NE; e++) { s[e] = 1.f / (1.f + expf(-logit[e])); sc[e] = s[e] + gb[e]; }
        float gscore[NGRP];
        for (int g = 0; g < NGRP; g++) {
            float a = -3.4e38f, b = -3.4e38f;
            for (int j = 0; j < GSZ; j++) {
                float v = sc[g * GSZ + j];
                if (v > a) { b = a; a = v; } else if (v > b) b = v;
            }
            gscore[g] = a + b;
        }
        bool gsel[NGRP] = {false, false, false, false};
        for (int k = 0; k < TGRP; k++) {
            int best = -1; float bv = -3.4e38f;
            for (int g = 0; g < NGRP; g++)
                if (!gsel[g] && gscore[g] > bv) { bv = gscore[g]; best = g; }
            gsel[best] = true;
        }
        bool used[NE];
        for (int e = 0; e < NE; e++) used[e] = !gsel[e / GSZ];
        float tsum = 0.f;
        int pick[TOPK]; float pw[TOPK];
        for (int k = 0; k < TOPK; k++) {
            int best = -1; float bv = -3.4e38f;
            for (int e = 0; e < NE; e++)
                if (!used[e] && sc[e] > bv) { bv = sc[e]; best = e; }
            used[best] = true;
            pick[k] = best; pw[k] = s[best]; tsum += s[best];
        }
        float inv = 1.f / tsum;
        for (int k = 0; k < TOPK; k++) {
            ids[t * TOPK + k] = pick[k];
            ws[t * TOPK + k] = pw[k] * inv;
        }
    }
}

__global__ void k_scatter(const int* __restrict__ ids, const float* __restrict__ ws) {
    int i = blockIdx.x * 256 + threadIdx.x;
    if (i >= TT * TOPK) return;
    int e = ids[i];
    int slot = atomicAdd(&g_cnt[e], 1);
    g_tok[e * TT + slot] = i / TOPK;
    g_wgt[e * TT + slot] = ws[i];
}

// ---------------- SiLU(g)*u in-place on hbuf ----------------
__global__ void k_act() {
    int e = blockIdx.y, m = blockIdx.x;
    if (m >= g_cnt[e]) return;
    float* row = g_hbuf + ((size_t)e * TT + m) * (2 * IM);
    for (int j = threadIdx.x; j < IM; j += 256) {
        float gv = row[j], uv = row[j + IM];
        row[j] = gv / (1.f + expf(-gv)) * uv;
    }
}

// ---------------- launch ----------------
extern "C" void kernel_launch(void* const* d_in, const int* in_sizes, int n_in,
                              void* d_out_, int out_size) {
    const int*   positions = (const int*)d_in[0];
    const float* hs   = (const float*)d_in[1];
    const float* res  = (const float*)d_in[2];
    const float* wln1 = (const float*)d_in[3];
    const float* wln2 = (const float*)d_in[4];
    const float* wqkv = (const float*)d_in[5];
    const float* wo   = (const float*)d_in[6];
    const float* gw   = (const float*)d_in[7];
    const float* gb   = (const float*)d_in[8];
    const float* wgu  = (const float*)d_in[9];
    const float* wd   = (const float*)d_in[10];
    float* out  = (float*)d_out_;
    float* res2 = out + (size_t)TT * HH;

    void* p;
    float *res1, *x, *qkv, *scores, *attn, *x2, *hbuf, *wgt;
    int *cnt, *tok, *tkid; float* tkw;
    cudaGetSymbolAddress(&p, g_res1);    res1   = (float*)p;
    cudaGetSymbolAddress(&p, g_x);       x      = (float*)p;
    cudaGetSymbolAddress(&p, g_qkv);     qkv    = (float*)p;
    cudaGetSymbolAddress(&p, g_scores);  scores = (float*)p;
    cudaGetSymbolAddress(&p, g_attn);    attn   = (float*)p;
    cudaGetSymbolAddress(&p, g_x2);      x2     = (float*)p;
    cudaGetSymbolAddress(&p, g_hbuf);    hbuf   = (float*)p;
    cudaGetSymbolAddress(&p, g_cnt);     cnt    = (int*)p;
    cudaGetSymbolAddress(&p, g_tok);     tok    = (int*)p;
    cudaGetSymbolAddress(&p, g_wgt);     wgt    = (float*)p;
    cudaGetSymbolAddress(&p, g_topk_id); tkid   = (int*)p;
    cudaGetSymbolAddress(&p, g_topk_w);  tkw    = (float*)p;

    cudaMemsetAsync(out, 0, (size_t)TT * HH * sizeof(float));
    cudaMemsetAsync(cnt, 0, NE * sizeof(int));

    // 1) residual add + ln1
    k_addnorm<<<TT, 256>>>(hs, res, wln1, res1, x);

    // 2) qkv = x @ wqkv   (2048 x 3072 x 2048)
    {
        dim3 g(QKVD / BN, TT / BM, 1);
        gemm_k<false, false, 0><<<g, 256>>>(x, HH, 0, wqkv, QKVD, 0, 1,
                                            qkv, QKVD, 0, TT, QKVD, HH,
                                            nullptr, nullptr, 0, nullptr, 0, 1.f, 0);
    }

    // 3) rope on q,k
    k_rope<<<TT, 256>>>(positions, qkv);

    // 4) scores[h] = scale * q_h @ k_{h/4}^T  (causal tiles only)
    {
        dim3 g(TT / BN, TT / BM, NH);
        gemm_k<true, false, 1><<<g, 256>>>(qkv, QKVD, HD,
                                           qkv + NH * HD, QKVD, HD, 4,
                                           scores, TT, (long)TT * TT,
                                           TT, TT, HD,
                                           nullptr, nullptr, 0, nullptr, 0, ATT_SCALE, 0);
    }

    // 5) causal softmax (also zeros masked tail)
    { dim3 g(TT, NH); k_softmax<<<g, 256>>>(scores); }

    // 6) attn[:, h*128:...] = probs_h @ v_{h/4}  (K limited to causal frontier)
    {
        dim3 g(HD / BN, TT / BM, NH);
        gemm_k<false, false, 0><<<g, 256>>>(scores, TT, (long)TT * TT,
                                            qkv + (NH + NKV) * HD, QKVD, HD, 4,
                                            attn, HH, HD,
                                            TT, HD, TT,
                                            nullptr, nullptr, 0, nullptr, 0, 1.f, 1);
    }

    // 7) res2 = attn @ wo + res1
    {
        dim3 g(HH / BN, TT / BM, 1);
        gemm_k<false, false, 2><<<g, 256>>>(attn, HH, 0, wo, HH, 0, 1,
                                            res2, HH, 0, TT, HH, HH,
                                            nullptr, nullptr, 0, res1, 0, 1.f, 0);
    }

    // 8) x2 = rmsnorm(res2)
    k_norm<<<TT, 256>>>(res2, wln2, x2);

    // 9) gating + scatter into per-expert lists
    k_gate<<<TT, 256>>>(x2, gw, gb, tkid, tkw);
    k_scatter<<<(TT * TOPK + 255) / 256, 256>>>(tkid, tkw);

    // 10) per-expert gate_up: hbuf[e] = gather(x2) @ wgu[e]   (cnt[e] x 2048 x 2048)
    {
        dim3 g((2 * IM) / BN, TT / BM, NE);
        gemm_k<false, true, 0><<<g, 256>>>(x2, HH, 0, wgu, 2 * IM, (long)HH * 2 * IM, 1,
                                           hbuf, 2 * IM, (long)TT * 2 * IM,
                                           TT, 2 * IM, HH,
                                           cnt, tok, TT, nullptr, 0, 1.f, 0);
    }

    // 11) silu(g)*u in place
    { dim3 g(TT, NE); k_act<<<g, 256>>>(); }

    // 12) per-expert down + weighted scatter-add into out
    {
        dim3 g(HH / BN, TT / BM, NE);
        gemm_k<false, false, 3><<<g, 256>>>(hbuf, 2 * IM, (long)TT * 2 * IM,
                                            wd, HH, (long)IM * HH, 1,
                                            out, HH, 0,
                                            TT, HH, IM,
                                            cnt, tok, TT, wgt, TT, 1.f, 0);
    }
}

// round 2
// speedup vs baseline: 1.8292x; 1.8292x over previous
#include <cuda_runtime.h>
#include <cuda_bf16.h>
#include <math.h>
#include <stdint.h>

#define TT 2048
#define HH 2048
#define NH 16
#define NKV 4
#define HD 128
#define NE 16
#define TOPK 4
#define NGRP 4
#define GSZ 4
#define TGRP 2
#define IM 1024
#define QKVD 3072
#define ATT_SCALE 0.08838834764831845f
#define EPSV 1e-6f

// ---------------- scratch (device globals; no allocations) ----------------
__device__ float g_res1[(size_t)TT * HH];
__device__ float g_x[(size_t)TT * HH];
__device__ float g_qkv[(size_t)TT * QKVD];
__device__ float g_scores[(size_t)NH * TT * TT];
__device__ float g_attn[(size_t)TT * HH];
__device__ float g_x2[(size_t)TT * HH];
__device__ float g_hbuf[(size_t)NE * TT * (2 * IM)];
__device__ int   g_cnt[NE];
__device__ int   g_tok[NE * TT];
__device__ float g_wgt[NE * TT];
__device__ int   g_topk_id[TT * TOPK];
__device__ float g_topk_w[TT * TOPK];

// ---------------- residual add + rmsnorm ----------------
__global__ void k_addnorm(const float* __restrict__ hs, const float* __restrict__ res,
                          const float* __restrict__ w, float* __restrict__ res_out,
                          float* __restrict__ x_out) {
    int t = blockIdx.x;
    __shared__ float red[256];
    float ss = 0.f;
    for (int i = threadIdx.x; i < HH; i += 256) {
        float v = hs[(size_t)t * HH + i] + res[(size_t)t * HH + i];
        res_out[(size_t)t * HH + i] = v;
        ss += v * v;
    }
    red[threadIdx.x] = ss; __syncthreads();
    for (int s = 128; s > 0; s >>= 1) { if (threadIdx.x < s) red[threadIdx.x] += red[threadIdx.x + s]; __syncthreads(); }
    float inv = rsqrtf(red[0] / (float)HH + EPSV);
    for (int i = threadIdx.x; i < HH; i += 256)
        x_out[(size_t)t * HH + i] = res_out[(size_t)t * HH + i] * inv * w[i];
}

__global__ void k_norm(const float* __restrict__ in, const float* __restrict__ w,
                       float* __restrict__ x_out) {
    int t = blockIdx.x;
    __shared__ float red[256];
    float ss = 0.f;
    for (int i = threadIdx.x; i < HH; i += 256) { float v = in[(size_t)t * HH + i]; ss += v * v; }
    red[threadIdx.x] = ss; __syncthreads();
    for (int s = 128; s > 0; s >>= 1) { if (threadIdx.x < s) red[threadIdx.x] += red[threadIdx.x + s]; __syncthreads(); }
    float inv = rsqrtf(red[0] / (float)HH + EPSV);
    for (int i = threadIdx.x; i < HH; i += 256)
        x_out[(size_t)t * HH + i] = in[(size_t)t * HH + i] * inv * w[i];
}

// ---------------- RoPE (in-place on q and k heads of qkv) ----------------
__global__ void k_rope(const int* __restrict__ pos, float* __restrict__ qkv) {
    int t = blockIdx.x;
    float fp = (float)pos[t];
    for (int idx = threadIdx.x; idx < (NH + NKV) * 64; idx += 256) {
        int hh = idx >> 6;
        int d = idx & 63;
        float inv = powf(1e6f, -(float)d / 64.f);
        float ang = fp * inv;
        float c = cosf(ang), s = sinf(ang);
        float* p = qkv + (size_t)t * QKVD + hh * HD;
        float x1 = p[d], x2 = p[d + 64];
        p[d] = x1 * c - x2 * s;
        p[d + 64] = x2 * c + x1 * s;
    }
}

// ---------------- bf16x3 tensor-core GEMM ----------------
// C[z] = alpha * A[z] (x) op(B[z]) with epilogue variants.
// EPI: 0 plain, 1 causal tile-skip, 2 add X (residual), 3 atomicAdd scatter.
#define BM 128
#define BN 64
#define BK 32
#define PADW 20   // padded row stride in uint32 words (16 used + 4 pad; conflict-free mod 32)

__device__ __forceinline__ uint32_t pack_bf2(__nv_bfloat16 a, __nv_bfloat16 b) {
    return (uint32_t)__bfloat16_as_ushort(a) | ((uint32_t)__bfloat16_as_ushort(b) << 16);
}
__device__ __forceinline__ void split_bf(float v, __nv_bfloat16& h, __nv_bfloat16& l) {
    h = __float2bfloat16_rn(v);
    l = __float2bfloat16_rn(v - __bfloat162float(h));
}
__device__ __forceinline__ void mma16816(float* c, const uint32_t* a, const uint32_t* b) {
    asm volatile(
        "mma.sync.aligned.m16n8k16.row.col.f32.bf16.bf16.f32 "
        "{%0,%1,%2,%3},{%4,%5,%6,%7},{%8,%9},{%0,%1,%2,%3};"
        : "+f"(c[0]), "+f"(c[1]), "+f"(c[2]), "+f"(c[3])
        : "r"(a[0]), "r"(a[1]), "r"(a[2]), "r"(a[3]), "r"(b[0]), "r"(b[1]));
}

template <bool TB, bool GA, int EPI>
__global__ void __launch_bounds__(256, 2)
gemm_tc(const float* __restrict__ A0, int lda, long saz,
        const float* __restrict__ B0, int ldb, long sbz, int bdiv,
        float* __restrict__ C0, int ldc, long scz,
        int M0, int N, int K,
        const int* __restrict__ Mptr,
        const int* __restrict__ gidx0, int sgz,
        const float* __restrict__ X0, long sxz,
        float alpha, int klimit) {
    int z = blockIdx.z;
    int M = Mptr ? Mptr[z] : M0;
    int row0 = blockIdx.y * BM, col0 = blockIdx.x * BN;
    if (row0 >= M) return;
    if (EPI == 1 && col0 > row0 + BM - 1) return;

    const float* A = A0 + (long)z * saz;
    const float* B = B0 + (long)(z / bdiv) * sbz;
    float* C = C0 + (long)z * scz;
    const int* gidx = (GA || EPI == 3) ? gidx0 + (long)z * sgz : nullptr;
    const float* X = X0 ? X0 + (long)z * sxz : nullptr;

    int Keff = K;
    if (klimit) { int km = row0 + BM; Keff = km < K ? km : K; }
    int nChunks = Keff / BK;   // all K multiples of 32

    extern __shared__ uint32_t sm[];
    uint32_t* As = sm;                       // [2][2][BM][PADW]
    uint32_t* Bs = sm + 2 * 2 * BM * PADW;   // [2][2][BN][PADW]

    const int tid = threadIdx.x;
    const int lane = tid & 31, wid = tid >> 5;
    const int m0w = (wid >> 1) * 32, n0w = (wid & 1) * 32;
    const int lq = lane >> 2, lr = lane & 3;

    // A loader: row am (0..127), k-half akh (0/16)
    const int am = tid >> 1;
    const int akh = (tid & 1) * 16;
    bool rvalid = (row0 + am) < M;
    long arow;
    if (GA) arow = rvalid ? (long)gidx[row0 + am] : 0;
    else    arow = row0 + am;
    const float* Aptr = A + arow * (long)lda + akh;

    // B loader
    int bn, bk;
    const float* Bptr;
    if (TB) { bn = tid >> 2; bk = (tid & 3) * 8; Bptr = B + (long)(col0 + bn) * ldb + bk; }
    else    { bk = tid >> 3; bn = (tid & 7) * 8; Bptr = B + (long)bk * ldb + col0 + bn; }

    float acc[2][4][4];
#pragma unroll
    for (int i = 0; i < 2; i++)
#pragma unroll
        for (int j = 0; j < 4; j++)
#pragma unroll
            for (int q = 0; q < 4; q++) acc[i][j][q] = 0.f;

    float ra[16], rb[8];

    auto loadg = [&](int k0) {
        if (rvalid) {
#pragma unroll
            for (int i = 0; i < 4; i++) {
                float4 v = *(const float4*)(Aptr + k0 + i * 4);
                ra[i * 4 + 0] = v.x; ra[i * 4 + 1] = v.y; ra[i * 4 + 2] = v.z; ra[i * 4 + 3] = v.w;
            }
        } else {
#pragma unroll
            for (int i = 0; i < 16; i++) ra[i] = 0.f;
        }
        if (TB) {
#pragma unroll
            for (int i = 0; i < 2; i++) {
                float4 v = *(const float4*)(Bptr + k0 + i * 4);
                rb[i * 4 + 0] = v.x; rb[i * 4 + 1] = v.y; rb[i * 4 + 2] = v.z; rb[i * 4 + 3] = v.w;
            }
        } else {
            const float* p = Bptr + (long)k0 * ldb;
#pragma unroll
            for (int i = 0; i < 2; i++) {
                float4 v = *(const float4*)(p + i * 4);
                rb[i * 4 + 0] = v.x; rb[i * 4 + 1] = v.y; rb[i * 4 + 2] = v.z; rb[i * 4 + 3] = v.w;
            }
        }
    };

    auto sts = [&](int buf) {
        uint32_t* ah = &As[(((buf * 2 + 0) * BM) + am) * PADW + (akh >> 1)];
        uint32_t* al = &As[(((buf * 2 + 1) * BM) + am) * PADW + (akh >> 1)];
#pragma unroll
        for (int i = 0; i < 8; i++) {
            __nv_bfloat16 h0, l0, h1, l1;
            split_bf(ra[2 * i], h0, l0);
            split_bf(ra[2 * i + 1], h1, l1);
            ah[i] = pack_bf2(h0, h1);
            al[i] = pack_bf2(l0, l1);
        }
        if (TB) {
            uint32_t* bh = &Bs[(((buf * 2 + 0) * BN) + bn) * PADW + (bk >> 1)];
            uint32_t* bl = &Bs[(((buf * 2 + 1) * BN) + bn) * PADW + (bk >> 1)];
#pragma unroll
            for (int i = 0; i < 4; i++) {
                __nv_bfloat16 h0, l0, h1, l1;
                split_bf(rb[2 * i], h0, l0);
                split_bf(rb[2 * i + 1], h1, l1);
                bh[i] = pack_bf2(h0, h1);
                bl[i] = pack_bf2(l0, l1);
            }
        } else {
            __nv_bfloat16* bsh = (__nv_bfloat16*)Bs;
#pragma unroll
            for (int j = 0; j < 8; j++) {
                __nv_bfloat16 h, l;
                split_bf(rb[j], h, l);
                bsh[((((buf * 2 + 0) * BN) + bn + j) * PADW) * 2 + bk] = h;
                bsh[((((buf * 2 + 1) * BN) + bn + j) * PADW) * 2 + bk] = l;
            }
        }
    };

    auto compute = [&](int buf) {
#pragma unroll
        for (int step = 0; step < 2; step++) {
            int kw = step * 8;
            uint32_t ahf[2][4], alf[2][4], bhf[4][2], blf[4][2];
#pragma unroll
            for (int mt = 0; mt < 2; mt++) {
                int r = m0w + mt * 16 + lq;
                int b0 = (((buf * 2 + 0) * BM) + r) * PADW + kw;
                int b1 = (((buf * 2 + 0) * BM) + r + 8) * PADW + kw;
                int c0 = (((buf * 2 + 1) * BM) + r) * PADW + kw;
                int c1 = (((buf * 2 + 1) * BM) + r + 8) * PADW + kw;
                ahf[mt][0] = As[b0 + lr];     ahf[mt][1] = As[b1 + lr];
                ahf[mt][2] = As[b0 + 4 + lr]; ahf[mt][3] = As[b1 + 4 + lr];
                alf[mt][0] = As[c0 + lr];     alf[mt][1] = As[c1 + lr];
                alf[mt][2] = As[c0 + 4 + lr]; alf[mt][3] = As[c1 + 4 + lr];
            }
#pragma unroll
            for (int nt = 0; nt < 4; nt++) {
                int n = n0w + nt * 8 + lq;
                int b0 = (((buf * 2 + 0) * BN) + n) * PADW + kw;
                int c0 = (((buf * 2 + 1) * BN) + n) * PADW + kw;
                bhf[nt][0] = Bs[b0 + lr]; bhf[nt][1] = Bs[b0 + 4 + lr];
                blf[nt][0] = Bs[c0 + lr]; blf[nt][1] = Bs[c0 + 4 + lr];
            }
#pragma unroll
            for (int mt = 0; mt < 2; mt++)
#pragma unroll
                for (int nt = 0; nt < 4; nt++) {
                    mma16816(acc[mt][nt], ahf[mt], bhf[nt]);
                    mma16816(acc[mt][nt], ahf[mt], blf[nt]);
                    mma16816(acc[mt][nt], alf[mt], bhf[nt]);
                }
        }
    };

    loadg(0);
    sts(0);
    __syncthreads();
    for (int c = 0; c < nChunks; c++) {
        int nxt = c + 1;
        if (nxt < nChunks) loadg(nxt * BK);
        compute(c & 1);
        if (nxt < nChunks) {
            sts(nxt & 1);
            __syncthreads();
        }
    }

    // epilogue
#pragma unroll
    for (int mt = 0; mt < 2; mt++) {
        int r0 = row0 + m0w + mt * 16 + lq;
        int r1 = r0 + 8;
#pragma unroll
        for (int nt = 0; nt < 4; nt++) {
            int cc = col0 + n0w + nt * 8 + 2 * lr;
            float v0 = acc[mt][nt][0] * alpha;
            float v1 = acc[mt][nt][1] * alpha;
            float v2 = acc[mt][nt][2] * alpha;
            float v3 = acc[mt][nt][3] * alpha;
            if (EPI == 2) {
                if (r0 < M) {
                    C[(size_t)r0 * ldc + cc]     = v0 + X[(size_t)r0 * ldc + cc];
                    C[(size_t)r0 * ldc + cc + 1] = v1 + X[(size_t)r0 * ldc + cc + 1];
                }
                if (r1 < M) {
                    C[(size_t)r1 * ldc + cc]     = v2 + X[(size_t)r1 * ldc + cc];
                    C[(size_t)r1 * ldc + cc + 1] = v3 + X[(size_t)r1 * ldc + cc + 1];
                }
            } else if (EPI == 3) {
                if (r0 < M) {
                    long gr = gidx[r0]; float w = X[r0];
                    atomicAdd(&C[gr * ldc + cc], w * v0);
                    atomicAdd(&C[gr * ldc + cc + 1], w * v1);
                }
                if (r1 < M) {
                    long gr = gidx[r1]; float w = X[r1];
                    atomicAdd(&C[gr * ldc + cc], w * v2);
                    atomicAdd(&C[gr * ldc + cc + 1], w * v3);
                }
            } else {
                if (r0 < M) {
                    C[(size_t)r0 * ldc + cc]     = v0;
                    C[(size_t)r0 * ldc + cc + 1] = v1;
                }
                if (r1 < M) {
                    C[(size_t)r1 * ldc + cc]     = v2;
                    C[(size_t)r1 * ldc + cc + 1] = v3;
                }
            }
        }
    }
}

#define GEMM_SMEM ((2 * 2 * BM * PADW + 2 * 2 * BN * PADW) * 4)

// ---------------- softmax over causal row ----------------
__global__ void k_softmax(float* __restrict__ sc) {
    int t = blockIdx.x, h = blockIdx.y;
    float* row = sc + ((size_t)h * TT + t) * TT;
    int n = t + 1;
    __shared__ float red[256];
    int tid = threadIdx.x;
    float m = -3.4e38f;
    for (int i = tid; i < n; i += 256) m = fmaxf(m, row[i]);
    red[tid] = m; __syncthreads();
    for (int s = 128; s > 0; s >>= 1) { if (tid < s) red[tid] = fmaxf(red[tid], red[tid + s]); __syncthreads(); }
    m = red[0]; __syncthreads();
    float sum = 0.f;
    for (int i = tid; i < n; i += 256) { float e = expf(row[i] - m); row[i] = e; sum += e; }
    red[tid] = sum; __syncthreads();
    for (int s = 128; s > 0; s >>= 1) { if (tid < s) red[tid] += red[tid + s]; __syncthreads(); }
    float inv = 1.f / red[0];
    for (int i = tid; i < n; i += 256) row[i] *= inv;
    for (int i = n + tid; i < TT; i += 256) row[i] = 0.f;
}

// ---------------- MoE gating ----------------
__global__ void k_gate(const float* __restrict__ x2, const float* __restrict__ gw,
                       const float* __restrict__ gb,
                       int* __restrict__ ids, float* __restrict__ ws) {
    int t = blockIdx.x;
    int tid = threadIdx.x, wid = tid >> 5, lane = tid & 31;
    __shared__ float logit[NE];
    for (int e = wid; e < NE; e += 8) {
        float acc = 0.f;
        for (int i = lane; i < HH; i += 32)
            acc += x2[(size_t)t * HH + i] * gw[(size_t)e * HH + i];
#pragma unroll
        for (int o = 16; o > 0; o >>= 1) acc += __shfl_down_sync(0xffffffffu, acc, o);
        if (lane == 0) logit[e] = acc;
    }
    __syncthreads();
    if (tid == 0) {
        float s[NE], sc[NE];
        for (int e = 0; e < NE; e++) { s[e] = 1.f / (1.f + expf(-logit[e])); sc[e] = s[e] + gb[e]; }
        float gscore[NGRP];
        for (int g = 0; g < NGRP; g++) {
            float a = -3.4e38f, b = -3.4e38f;
            for (int j = 0; j < GSZ; j++) {
                float v = sc[g * GSZ + j];
                if (v > a) { b = a; a = v; } else if (v > b) b = v;
            }
            gscore[g] = a + b;
        }
        bool gsel[NGRP] = {false, false, false, false};
        for (int k = 0; k < TGRP; k++) {
            int best = -1; float bv = -3.4e38f;
            for (int g = 0; g < NGRP; g++)
                if (!gsel[g] && gscore[g] > bv) { bv = gscore[g]; best = g; }
            gsel[best] = true;
        }
        bool used[NE];
        for (int e = 0; e < NE; e++) used[e] = !gsel[e / GSZ];
        float tsum = 0.f;
        int pick[TOPK]; float pw[TOPK];
        for (int k = 0; k < TOPK; k++) {
            int best = -1; float bv = -3.4e38f;
            for (int e = 0; e < NE; e++)
                if (!used[e] && sc[e] > bv) { bv = sc[e]; best = e; }
            used[best] = true;
            pick[k] = best; pw[k] = s[best]; tsum += s[best];
        }
        float inv = 1.f / tsum;
        for (int k = 0; k < TOPK; k++) {
            ids[t * TOPK + k] = pick[k];
            ws[t * TOPK + k] = pw[k] * inv;
        }
    }
}

__global__ void k_scatter(const int* __restrict__ ids, const float* __restrict__ ws) {
    int i = blockIdx.x * 256 + threadIdx.x;
    if (i >= TT * TOPK) return;
    int e = ids[i];
    int slot = atomicAdd(&g_cnt[e], 1);
    g_tok[e * TT + slot] = i / TOPK;
    g_wgt[e * TT + slot] = ws[i];
}

// ---------------- SiLU(g)*u in-place on hbuf ----------------
__global__ void k_act() {
    int e = blockIdx.y, m = blockIdx.x;
    if (m >= g_cnt[e]) return;
    float* row = g_hbuf + ((size_t)e * TT + m) * (2 * IM);
    for (int j = threadIdx.x; j < IM; j += 256) {
        float gv = row[j], uv = row[j + IM];
        row[j] = gv / (1.f + expf(-gv)) * uv;
    }
}

// ---------------- launch ----------------
extern "C" void kernel_launch(void* const* d_in, const int* in_sizes, int n_in,
                              void* d_out_, int out_size) {
    const int*   positions = (const int*)d_in[0];
    const float* hs   = (const float*)d_in[1];
    const float* res  = (const float*)d_in[2];
    const float* wln1 = (const float*)d_in[3];
    const float* wln2 = (const float*)d_in[4];
    const float* wqkv = (const float*)d_in[5];
    const float* wo   = (const float*)d_in[6];
    const float* gw   = (const float*)d_in[7];
    const float* gb   = (const float*)d_in[8];
    const float* wgu  = (const float*)d_in[9];
    const float* wd   = (const float*)d_in[10];
    float* out  = (float*)d_out_;
    float* res2 = out + (size_t)TT * HH;

    void* p;
    float *res1, *x, *qkv, *scores, *attn, *x2, *hbuf, *wgt;
    int *cnt, *tok, *tkid; float* tkw;
    cudaGetSymbolAddress(&p, g_res1);    res1   = (float*)p;
    cudaGetSymbolAddress(&p, g_x);       x      = (float*)p;
    cudaGetSymbolAddress(&p, g_qkv);     qkv    = (float*)p;
    cudaGetSymbolAddress(&p, g_scores);  scores = (float*)p;
    cudaGetSymbolAddress(&p, g_attn);    attn   = (float*)p;
    cudaGetSymbolAddress(&p, g_x2);      x2     = (float*)p;
    cudaGetSymbolAddress(&p, g_hbuf);    hbuf   = (float*)p;
    cudaGetSymbolAddress(&p, g_cnt);     cnt    = (int*)p;
    cudaGetSymbolAddress(&p, g_tok);     tok    = (int*)p;
    cudaGetSymbolAddress(&p, g_wgt);     wgt    = (float*)p;
    cudaGetSymbolAddress(&p, g_topk_id); tkid   = (int*)p;
    cudaGetSymbolAddress(&p, g_topk_w);  tkw    = (float*)p;

    cudaFuncSetAttribute(gemm_tc<false, false, 0>, cudaFuncAttributeMaxDynamicSharedMemorySize, GEMM_SMEM);
    cudaFuncSetAttribute(gemm_tc<true,  false, 1>, cudaFuncAttributeMaxDynamicSharedMemorySize, GEMM_SMEM);
    cudaFuncSetAttribute(gemm_tc<false, false, 2>, cudaFuncAttributeMaxDynamicSharedMemorySize, GEMM_SMEM);
    cudaFuncSetAttribute(gemm_tc<false, true,  0>, cudaFuncAttributeMaxDynamicSharedMemorySize, GEMM_SMEM);
    cudaFuncSetAttribute(gemm_tc<false, false, 3>, cudaFuncAttributeMaxDynamicSharedMemorySize, GEMM_SMEM);

    cudaMemsetAsync(out, 0, (size_t)TT * HH * sizeof(float));
    cudaMemsetAsync(cnt, 0, NE * sizeof(int));

    // 1) residual add + ln1
    k_addnorm<<<TT, 256>>>(hs, res, wln1, res1, x);

    // 2) qkv = x @ wqkv
    {
        dim3 g(QKVD / BN, TT / BM, 1);
        gemm_tc<false, false, 0><<<g, 256, GEMM_SMEM>>>(x, HH, 0, wqkv, QKVD, 0, 1,
                                                        qkv, QKVD, 0, TT, QKVD, HH,
                                                        nullptr, nullptr, 0, nullptr, 0, 1.f, 0);
    }

    // 3) rope
    k_rope<<<TT, 256>>>(positions, qkv);

    // 4) scores (causal tiles only)
    {
        dim3 g(TT / BN, TT / BM, NH);
        gemm_tc<true, false, 1><<<g, 256, GEMM_SMEM>>>(qkv, QKVD, HD,
                                                       qkv + NH * HD, QKVD, HD, 4,
                                                       scores, TT, (long)TT * TT,
                                                       TT, TT, HD,
                                                       nullptr, nullptr, 0, nullptr, 0, ATT_SCALE, 0);
    }

    // 5) causal softmax
    { dim3 g(TT, NH); k_softmax<<<g, 256>>>(scores); }

    // 6) attn = probs @ v  (K limited to causal frontier)
    {
        dim3 g(HD / BN, TT / BM, NH);
        gemm_tc<false, false, 0><<<g, 256, GEMM_SMEM>>>(scores, TT, (long)TT * TT,
                                                        qkv + (NH + NKV) * HD, QKVD, HD, 4,
                                                        attn, HH, HD,
                                                        TT, HD, TT,
                                                        nullptr, nullptr, 0, nullptr, 0, 1.f, 1);
    }

    // 7) res2 = attn @ wo + res1
    {
        dim3 g(HH / BN, TT / BM, 1);
        gemm_tc<false, false, 2><<<g, 256, GEMM_SMEM>>>(attn, HH, 0, wo, HH, 0, 1,
                                                        res2, HH, 0, TT, HH, HH,
                                                        nullptr, nullptr, 0, res1, 0, 1.f, 0);
    }

    // 8) x2 = rmsnorm(res2)
    k_norm<<<TT, 256>>>(res2, wln2, x2);

    // 9) gating + scatter
    k_gate<<<TT, 256>>>(x2, gw, gb, tkid, tkw);
    k_scatter<<<(TT * TOPK + 255) / 256, 256>>>(tkid, tkw);

    // 10) per-expert gate_up
    {
        dim3 g((2 * IM) / BN, TT / BM, NE);
        gemm_tc<false, true, 0><<<g, 256, GEMM_SMEM>>>(x2, HH, 0, wgu, 2 * IM, (long)HH * 2 * IM, 1,
                                                       hbuf, 2 * IM, (long)TT * 2 * IM,
                                                       TT, 2 * IM, HH,
                                                       cnt, tok, TT, nullptr, 0, 1.f, 0);
    }

    // 11) silu(g)*u
    { dim3 g(TT, NE); k_act<<<g, 256>>>(); }

    // 12) per-expert down + weighted scatter-add
    {
        dim3 g(HH / BN, TT / BM, NE);
        gemm_tc<false, false, 3><<<g, 256, GEMM_SMEM>>>(hbuf, 2 * IM, (long)TT * 2 * IM,
                                                        wd, HH, (long)IM * HH, 1,
                                                        out, HH, 0,
                                                        TT, HH, IM,
                                                        cnt, tok, TT, wgt, TT, 1.f, 0);
    }
}

// round 5
// speedup vs baseline: 3.1801x; 1.7385x over previous
#include <cuda_runtime.h>
#include <cuda_bf16.h>
#include <math.h>
#include <stdint.h>

#define TT 2048
#define HH 2048
#define NH 16
#define NKV 4
#define HD 128
#define NE 16
#define TOPK 4
#define NGRP 4
#define GSZ 4
#define TGRP 2
#define IM 1024
#define QKVD 3072
#define ATT_SCALE 0.08838834764831845f
#define EPSV 1e-6f

typedef __nv_bfloat16 bf16;

// ---------------- scratch (device globals; no allocations) ----------------
__device__ float g_res1[(size_t)TT * HH];
__device__ float g_qkv[(size_t)TT * QKVD];
__device__ float g_scores[(size_t)NH * TT * TT];
__device__ float g_x2[(size_t)TT * HH];
__device__ float g_hbuf[(size_t)NE * TT * (2 * IM)];
__device__ bf16  g_xh[(size_t)TT * HH],  g_xl[(size_t)TT * HH];
__device__ bf16  g_x2h[(size_t)TT * HH], g_x2l[(size_t)TT * HH];
__device__ bf16  g_qh[(size_t)TT * (NH * HD)], g_ql[(size_t)TT * (NH * HD)];
__device__ bf16  g_ph[(size_t)NH * TT * TT], g_pl[(size_t)NH * TT * TT];
__device__ bf16  g_attnh[(size_t)TT * HH], g_attnl[(size_t)TT * HH];
__device__ bf16  g_acth[(size_t)NE * TT * IM], g_actl[(size_t)NE * TT * IM];
__device__ bf16  g_kbh[(size_t)NKV * TT * HD], g_kbl[(size_t)NKV * TT * HD];
__device__ bf16  g_vth[(size_t)NKV * HD * TT], g_vtl[(size_t)NKV * HD * TT];
__device__ bf16  g_wqkvh[(size_t)QKVD * HH], g_wqkvl[(size_t)QKVD * HH];
__device__ bf16  g_woh[(size_t)HH * HH],     g_wol[(size_t)HH * HH];
__device__ bf16  g_wguh[(size_t)NE * 2 * IM * HH], g_wgul[(size_t)NE * 2 * IM * HH];
__device__ bf16  g_wdh[(size_t)NE * HH * IM],      g_wdl[(size_t)NE * HH * IM];
__device__ int   g_cnt[NE];
__device__ int   g_tok[NE * TT];
__device__ float g_wgt[NE * TT];
__device__ int   g_topk_id[TT * TOPK];
__device__ float g_topk_w[TT * TOPK];

// ---------------- helpers ----------------
__device__ __forceinline__ uint32_t smem_u32(const void* p) {
    uint32_t a;
    asm("{ .reg .u64 t; cvta.to.shared.u64 t, %1; cvt.u32.u64 %0, t; }" : "=r"(a) : "l"(p));
    return a;
}
__device__ __forceinline__ void split_bf(float v, bf16& h, bf16& l) {
    h = __float2bfloat16_rn(v);
    l = __float2bfloat16_rn(v - __bfloat162float(h));
}
__device__ __forceinline__ uint32_t pack2(bf16 a, bf16 b) {
    return (uint32_t)__bfloat16_as_ushort(a) | ((uint32_t)__bfloat16_as_ushort(b) << 16);
}
__device__ __forceinline__ void cpa(uint32_t d, const void* s, int sz) {
    asm volatile("cp.async.cg.shared.global [%0], [%1], 16, %2;" :: "r"(d), "l"(s), "r"(sz));
}
__device__ __forceinline__ void cpcommit() { asm volatile("cp.async.commit_group;" ::: "memory"); }
__device__ __forceinline__ void cpwait1()  { asm volatile("cp.async.wait_group 1;" ::: "memory"); }
__device__ __forceinline__ void ldm4(uint32_t* r, uint32_t a) {
    asm volatile("ldmatrix.sync.aligned.m8n8.x4.shared.b16 {%0,%1,%2,%3}, [%4];"
                 : "=r"(r[0]), "=r"(r[1]), "=r"(r[2]), "=r"(r[3]) : "r"(a));
}
__device__ __forceinline__ void mma16816(float* c, const uint32_t* a, const uint32_t* b) {
    asm volatile(
        "mma.sync.aligned.m16n8k16.row.col.f32.bf16.bf16.f32 "
        "{%0,%1,%2,%3},{%4,%5,%6,%7},{%8,%9},{%0,%1,%2,%3};"
        : "+f"(c[0]), "+f"(c[1]), "+f"(c[2]), "+f"(c[3])
        : "r"(a[0]), "r"(a[1]), "r"(a[2]), "r"(a[3]), "r"(b[0]), "r"(b[1]));
}

// ---------------- mma.sync bf16x3 GEMM ----------------
// C[z][M][N] (+)= alpha * A[z] @ B[z]^T ; all operands bf16 hi/lo, B rows = N-index, K contiguous.
// EPI: 0 fp32 store, 1 causal tile-skip fp32 store, 2 add X, 3 atomicAdd scatter, 4 bf16 hi/lo split store.
#define BMT 128
#define BNT 128
#define BKT 32
#define AST 80u
#define STG_M 10240u
#define STG (4u * STG_M)
#define GSM (2 * 4 * 10240)

template <bool GA, int EPI, bool KLIM>
__global__ void __launch_bounds__(256, 2)
gemm_m(const bf16* __restrict__ Ah0, const bf16* __restrict__ Al0, int lda, long saz,
       const bf16* __restrict__ Bh0, const bf16* __restrict__ Bl0, int ldb, long sbz, int bdiv,
       float* __restrict__ C0, bf16* __restrict__ Oh0, bf16* __restrict__ Ol0, int ldc, long scz,
       int M0, int N, int K,
       const int* __restrict__ Mptr, const int* __restrict__ gidx0, int sgz,
       const float* __restrict__ X0, long sxz, float alpha) {
    int z = blockIdx.z;
    int M = Mptr ? Mptr[z] : M0;
    int row0 = blockIdx.y * BMT, col0 = blockIdx.x * BNT;
    if (row0 >= M) return;
    if (EPI == 1 && col0 > row0 + BMT - 1) return;

    extern __shared__ char smem[];
    uint32_t sb = smem_u32(smem);
    int tid = threadIdx.x, lane = tid & 31, wid = tid >> 5;
    const int m0w = (wid & 3) * 32, n0w = (wid >> 2) * 64;

    const int* gidxz = (GA || EPI == 3) ? gidx0 + (long)z * sgz : nullptr;
    const float* X = (EPI == 2 || EPI == 3) ? X0 + (long)z * sxz : nullptr;
    const bf16* Bh = Bh0 + (long)(z / bdiv) * sbz;
    const bf16* Bl = Bl0 + (long)(z / bdiv) * sbz;

    int Keff = K;
    if (KLIM) { int km = row0 + BMT; Keff = km < K ? km : K; }
    int nch = Keff / BKT;

    // loaders: row = tid>>1 (0..127), half = tid&1 (32B each)
    int lrow = tid >> 1, lhalf = tid & 1;
    int ari = row0 + lrow;
    bool av = ari < M;
    long agrow = ari;
    if (GA) agrow = av ? (long)gidxz[ari] : 0;
    const bf16* agh = Ah0 + (long)z * saz + agrow * (long)lda;
    const bf16* agl = Al0 + (long)z * saz + agrow * (long)lda;
    int asz = av ? 16 : 0;
    const bf16* bgh = Bh + (long)(col0 + lrow) * ldb;
    const bf16* bgl = Bl + (long)(col0 + lrow) * ldb;
    uint32_t dst_ab = sb + lrow * AST + lhalf * 32;
    uint32_t dst_bb = sb + 2 * STG_M + lrow * AST + lhalf * 32;

    auto cp_stage = [&](int buf, int k0) {
        uint32_t so = buf * STG;
        long ko = k0 + lhalf * 16;
        cpa(dst_ab + so,              agh + ko,     asz);
        cpa(dst_ab + so + 16,         agh + ko + 8, asz);
        cpa(dst_ab + so + STG_M,      agl + ko,     asz);
        cpa(dst_ab + so + STG_M + 16, agl + ko + 8, asz);
        cpa(dst_bb + so,              bgh + ko,     16);
        cpa(dst_bb + so + 16,         bgh + ko + 8, 16);
        cpa(dst_bb + so + STG_M,      bgl + ko,     16);
        cpa(dst_bb + so + STG_M + 16, bgl + ko + 8, 16);
    };

    float acc[2][8][4];
#pragma unroll
    for (int i = 0; i < 2; i++)
#pragma unroll
        for (int j = 0; j < 8; j++)
#pragma unroll
            for (int q = 0; q < 4; q++) acc[i][j][q] = 0.f;

    // per-lane ldmatrix offsets
    uint32_t a_off = (uint32_t)(m0w + (lane & 15)) * AST + (uint32_t)(lane >> 4) * 16;
    uint32_t b_off = (uint32_t)(n0w + ((lane >> 4) << 3) + (lane & 7)) * AST + (uint32_t)((lane >> 3) & 1) * 16;

    auto compute = [&](int buf) {
        uint32_t ab  = sb + buf * STG;
        uint32_t alb = ab + STG_M;
        uint32_t bhb = ab + 2 * STG_M;
        uint32_t blb = ab + 3 * STG_M;
#pragma unroll
        for (int s = 0; s < 2; s++) {
            uint32_t ka = s * 32;
            uint32_t ah0[4], ah1[4], al0[4], al1[4];
            ldm4(ah0, ab + a_off + ka);
            ldm4(ah1, ab + a_off + 16 * AST + ka);
            ldm4(al0, alb + a_off + ka);
            ldm4(al1, alb + a_off + 16 * AST + ka);
#pragma unroll
            for (int np = 0; np < 4; np++) {
                uint32_t bo = b_off + np * 16 * AST + ka;
                uint32_t bh[4], bl[4];
                ldm4(bh, bhb + bo);
                ldm4(bl, blb + bo);
                int ne = 2 * np, no = 2 * np + 1;
                mma16816(acc[0][ne], ah0, bh);     mma16816(acc[0][ne], ah0, bl);     mma16816(acc[0][ne], al0, bh);
                mma16816(acc[0][no], ah0, bh + 2); mma16816(acc[0][no], ah0, bl + 2); mma16816(acc[0][no], al0, bh + 2);
                mma16816(acc[1][ne], ah1, bh);     mma16816(acc[1][ne], ah1, bl);     mma16816(acc[1][ne], al1, bh);
                mma16816(acc[1][no], ah1, bh + 2); mma16816(acc[1][no], ah1, bl + 2); mma16816(acc[1][no], al1, bh + 2);
            }
        }
    };

    cp_stage(0, 0); cpcommit();
    cp_stage(1, BKT); cpcommit();
    cpwait1();
    __syncthreads();
    for (int c = 0; c < nch; c++) {
        int b = c & 1;
        compute(b);
        __syncthreads();
        if (c + 2 < nch) cp_stage(b, (c + 2) * BKT);
        cpcommit();
        cpwait1();
        __syncthreads();
    }

    // epilogue
    int lq = lane >> 2, lr = lane & 3;
#pragma unroll
    for (int mt = 0; mt < 2; mt++) {
        int r0 = row0 + m0w + mt * 16 + lq;
        int r1 = r0 + 8;
#pragma unroll
        for (int nt = 0; nt < 8; nt++) {
            long cc = (long)col0 + n0w + nt * 8 + 2 * lr;
            float v0 = acc[mt][nt][0] * alpha, v1 = acc[mt][nt][1] * alpha;
            float v2 = acc[mt][nt][2] * alpha, v3 = acc[mt][nt][3] * alpha;
            if (EPI == 4) {
                bf16 h0, l0, h1, l1;
                if (r0 < M) {
                    bf16* oh = Oh0 + (long)z * scz; bf16* ol = Ol0 + (long)z * scz;
                    split_bf(v0, h0, l0); split_bf(v1, h1, l1);
                    *(uint32_t*)&oh[(long)r0 * ldc + cc] = pack2(h0, h1);
                    *(uint32_t*)&ol[(long)r0 * ldc + cc] = pack2(l0, l1);
                }
                if (r1 < M) {
                    bf16* oh = Oh0 + (long)z * scz; bf16* ol = Ol0 + (long)z * scz;
                    split_bf(v2, h0, l0); split_bf(v3, h1, l1);
                    *(uint32_t*)&oh[(long)r1 * ldc + cc] = pack2(h0, h1);
                    *(uint32_t*)&ol[(long)r1 * ldc + cc] = pack2(l0, l1);
                }
            } else if (EPI == 3) {
                float* C = C0 + (long)z * scz;
                if (r0 < M) {
                    long gr = gidxz[r0]; float w = X[r0];
                    atomicAdd(&C[gr * ldc + cc], w * v0);
                    atomicAdd(&C[gr * ldc + cc + 1], w * v1);
                }
                if (r1 < M) {
                    long gr = gidxz[r1]; float w = X[r1];
                    atomicAdd(&C[gr * ldc + cc], w * v2);
                    atomicAdd(&C[gr * ldc + cc + 1], w * v3);
                }
            } else if (EPI == 2) {
                float* C = C0 + (long)z * scz;
                if (r0 < M) {
                    float2 xv = *(const float2*)&X[(long)r0 * ldc + cc];
                    *(float2*)&C[(long)r0 * ldc + cc] = make_float2(v0 + xv.x, v1 + xv.y);
                }
                if (r1 < M) {
                    float2 xv = *(const float2*)&X[(long)r1 * ldc + cc];
                    *(float2*)&C[(long)r1 * ldc + cc] = make_float2(v2 + xv.x, v3 + xv.y);
                }
            } else {
                float* C = C0 + (long)z * scz;
                if (r0 < M) *(float2*)&C[(long)r0 * ldc + cc] = make_float2(v0, v1);
                if (r1 < M) *(float2*)&C[(long)r1 * ldc + cc] = make_float2(v2, v3);
            }
        }
    }
}

// ---------------- transpose + convert fp32 -> bf16 hi/lo ----------------
__global__ void k_tconv(const float* __restrict__ in, long ldin, long sbin,
                        bf16* __restrict__ oh, bf16* __restrict__ ol, long ldo, long sbo,
                        int R, int C) {
    __shared__ float t[32][33];
    int z = blockIdx.z;
    const float* I = in + (long)z * sbin;
    int c0 = blockIdx.x * 32, r0 = blockIdx.y * 32;
#pragma unroll
    for (int i = 0; i < 4; i++) {
        int r = r0 + threadIdx.y + i * 8, c = c0 + threadIdx.x;
        t[threadIdx.y + i * 8][threadIdx.x] = (r < R && c < C) ? I[(long)r * ldin + c] : 0.f;
    }
    __syncthreads();
#pragma unroll
    for (int i = 0; i < 4; i++) {
        int orow = c0 + threadIdx.y + i * 8, ocol = r0 + threadIdx.x;
        if (orow < C && ocol < R) {
            bf16 h, l;
            split_bf(t[threadIdx.x][threadIdx.y + i * 8], h, l);
            oh[(long)z * sbo + (long)orow * ldo + ocol] = h;
            ol[(long)z * sbo + (long)orow * ldo + ocol] = l;
        }
    }
}

// ---------------- residual add + rmsnorm ----------------
__global__ void k_addnorm(const float* __restrict__ hs, const float* __restrict__ res,
                          const float* __restrict__ w, float* __restrict__ res_out) {
    int t = blockIdx.x;
    __shared__ float red[256];
    float ss = 0.f;
    for (int i = threadIdx.x; i < HH; i += 256) {
        float v = hs[(size_t)t * HH + i] + res[(size_t)t * HH + i];
        res_out[(size_t)t * HH + i] = v;
        ss += v * v;
    }
    red[threadIdx.x] = ss; __syncthreads();
    for (int s = 128; s > 0; s >>= 1) { if (threadIdx.x < s) red[threadIdx.x] += red[threadIdx.x + s]; __syncthreads(); }
    float inv = rsqrtf(red[0] / (float)HH + EPSV);
    for (int i = threadIdx.x; i < HH; i += 256) {
        float v = res_out[(size_t)t * HH + i] * inv * w[i];
        bf16 h, l; split_bf(v, h, l);
        g_xh[(size_t)t * HH + i] = h; g_xl[(size_t)t * HH + i] = l;
    }
}

__global__ void k_norm(const float* __restrict__ in, const float* __restrict__ w) {
    int t = blockIdx.x;
    __shared__ float red[256];
    float ss = 0.f;
    for (int i = threadIdx.x; i < HH; i += 256) { float v = in[(size_t)t * HH + i]; ss += v * v; }
    red[threadIdx.x] = ss; __syncthreads();
    for (int s = 128; s > 0; s >>= 1) { if (threadIdx.x < s) red[threadIdx.x] += red[threadIdx.x + s]; __syncthreads(); }
    float inv = rsqrtf(red[0] / (float)HH + EPSV);
    for (int i = threadIdx.x; i < HH; i += 256) {
        float v = in[(size_t)t * HH + i] * inv * w[i];
        g_x2[(size_t)t * HH + i] = v;
        bf16 h, l; split_bf(v, h, l);
        g_x2h[(size_t)t * HH + i] = h; g_x2l[(size_t)t * HH + i] = l;
    }
}

// ---------------- RoPE: emit q and k directly as bf16 hi/lo ----------------
__global__ void k_rope(const int* __restrict__ pos, const float* __restrict__ qkv) {
    int t = blockIdx.x;
    float fp = (float)pos[t];
    for (int idx = threadIdx.x; idx < (NH + NKV) * 64; idx += 256) {
        int hh = idx >> 6, d = idx & 63;
        float inv = powf(1e6f, -(float)d / 64.f);
        float ang = fp * inv;
        float c = cosf(ang), s = sinf(ang);
        const float* p = qkv + (size_t)t * QKVD + hh * HD;
        float x1 = p[d], x2 = p[d + 64];
        float v1 = x1 * c - x2 * s;
        float v2 = x2 * c + x1 * s;
        bf16 h1, l1, h2, l2;
        split_bf(v1, h1, l1); split_bf(v2, h2, l2);
        if (hh < NH) {
            size_t b = (size_t)t * (NH * HD) + hh * HD;
            g_qh[b + d] = h1; g_ql[b + d] = l1;
            g_qh[b + d + 64] = h2; g_ql[b + d + 64] = l2;
        } else {
            int kv = hh - NH;
            size_t b = (size_t)kv * TT * HD + (size_t)t * HD;
            g_kbh[b + d] = h1; g_kbl[b + d] = l1;
            g_kbh[b + d + 64] = h2; g_kbl[b + d + 64] = l2;
        }
    }
}

// ---------------- softmax (emit bf16 hi/lo probs) ----------------
__global__ void k_softmax(const float* __restrict__ sc) {
    int t = blockIdx.x, h = blockIdx.y;
    const float* row = sc + ((size_t)h * TT + t) * TT;
    bf16* oh = g_ph + ((size_t)h * TT + t) * TT;
    bf16* ol = g_pl + ((size_t)h * TT + t) * TT;
    int n = t + 1;
    __shared__ float red[256];
    int tid = threadIdx.x;
    float m = -3.4e38f;
    for (int i = tid; i < n; i += 256) m = fmaxf(m, row[i]);
    red[tid] = m; __syncthreads();
    for (int s = 128; s > 0; s >>= 1) { if (tid < s) red[tid] = fmaxf(red[tid], red[tid + s]); __syncthreads(); }
    m = red[0]; __syncthreads();
    float sum = 0.f;
    for (int i = tid; i < n; i += 256) sum += expf(row[i] - m);
    red[tid] = sum; __syncthreads();
    for (int s = 128; s > 0; s >>= 1) { if (tid < s) red[tid] += red[tid + s]; __syncthreads(); }
    float inv = 1.f / red[0];
    for (int i = tid; i < n; i += 256) {
        float p = expf(row[i] - m) * inv;
        bf16 ph, pl; split_bf(p, ph, pl);
        oh[i] = ph; ol[i] = pl;
    }
    bf16 zz = __float2bfloat16_rn(0.f);
    for (int i = n + tid; i < TT; i += 256) { oh[i] = zz; ol[i] = zz; }
}

// ---------------- MoE gating ----------------
__global__ void k_gate(const float* __restrict__ x2, const float* __restrict__ gw,
                       const float* __restrict__ gb,
                       int* __restrict__ ids, float* __restrict__ ws) {
    int t = blockIdx.x;
    int tid = threadIdx.x, wid = tid >> 5, lane = tid & 31;
    __shared__ float logit[NE];
    for (int e = wid; e < NE; e += 8) {
        float acc = 0.f;
        for (int i = lane; i < HH; i += 32)
            acc += x2[(size_t)t * HH + i] * gw[(size_t)e * HH + i];
#pragma unroll
        for (int o = 16; o > 0; o >>= 1) acc += __shfl_down_sync(0xffffffffu, acc, o);
        if (lane == 0) logit[e] = acc;
    }
    __syncthreads();
    if (tid == 0) {
        float s[NE], sc[NE];
        for (int e = 0; e < NE; e++) { s[e] = 1.f / (1.f + expf(-logit[e])); sc[e] = s[e] + gb[e]; }
        float gscore[NGRP];
        for (int g = 0; g < NGRP; g++) {
            float a = -3.4e38f, b = -3.4e38f;
            for (int j = 0; j < GSZ; j++) {
                float v = sc[g * GSZ + j];
                if (v > a) { b = a; a = v; } else if (v > b) b = v;
            }
            gscore[g] = a + b;
        }
        bool gsel[NGRP] = {false, false, false, false};
        for (int k = 0; k < TGRP; k++) {
            int best = -1; float bv = -3.4e38f;
            for (int g = 0; g < NGRP; g++)
                if (!gsel[g] && gscore[g] > bv) { bv = gscore[g]; best = g; }
            gsel[best] = true;
        }
        bool used[NE];
        for (int e = 0; e < NE; e++) used[e] = !gsel[e / GSZ];
        float tsum = 0.f;
        int pick[TOPK]; float pw[TOPK];
        for (int k = 0; k < TOPK; k++) {
            int best = -1; float bv = -3.4e38f;
            for (int e = 0; e < NE; e++)
                if (!used[e] && sc[e] > bv) { bv = sc[e]; best = e; }
            used[best] = true;
            pick[k] = best; pw[k] = s[best]; tsum += s[best];
        }
        float inv = 1.f / tsum;
        for (int k = 0; k < TOPK; k++) {
            ids[t * TOPK + k] = pick[k];
            ws[t * TOPK + k] = pw[k] * inv;
        }
    }
}

__global__ void k_scatter(const int* __restrict__ ids, const float* __restrict__ ws) {
    int i = blockIdx.x * 256 + threadIdx.x;
    if (i >= TT * TOPK) return;
    int e = ids[i];
    int slot = atomicAdd(&g_cnt[e], 1);
    g_tok[e * TT + slot] = i / TOPK;
    g_wgt[e * TT + slot] = ws[i];
}

// ---------------- SiLU(g)*u -> bf16 hi/lo ----------------
__global__ void k_act() {
    int e = blockIdx.y, m = blockIdx.x;
    if (m >= g_cnt[e]) return;
    const float* row = g_hbuf + ((size_t)e * TT + m) * (2 * IM);
    bf16* oh = g_acth + ((size_t)e * TT + m) * IM;
    bf16* ol = g_actl + ((size_t)e * TT + m) * IM;
    for (int j = threadIdx.x; j < IM; j += 256) {
        float gv = row[j], uv = row[j + IM];
        float v = gv / (1.f + expf(-gv)) * uv;
        bf16 h, l; split_bf(v, h, l);
        oh[j] = h; ol[j] = l;
    }
}

// ---------------- launch ----------------
extern "C" void kernel_launch(void* const* d_in, const int* in_sizes, int n_in,
                              void* d_out_, int out_size) {
    const int*   positions = (const int*)d_in[0];
    const float* hs   = (const float*)d_in[1];
    const float* res  = (const float*)d_in[2];
    const float* wln1 = (const float*)d_in[3];
    const float* wln2 = (const float*)d_in[4];
    const float* wqkv = (const float*)d_in[5];
    const float* wo   = (const float*)d_in[6];
    const float* gw   = (const float*)d_in[7];
    const float* gb   = (const float*)d_in[8];
    const float* wgu  = (const float*)d_in[9];
    const float* wd   = (const float*)d_in[10];
    float* out  = (float*)d_out_;
    float* res2 = out + (size_t)TT * HH;

    void* p;
    float *res1, *qkv, *scores, *x2, *hbuf, *wgt;
    bf16 *xh, *xl, *x2h, *x2l, *qh, *ql, *ph_, *pl_, *ath, *atl, *acth, *actl, *kbh, *kbl, *vth, *vtl;
    bf16 *wqkvh, *wqkvl, *woh, *wol, *wguh, *wgul, *wdh, *wdl;
    int *cnt, *tok, *tkid; float* tkw;
    cudaGetSymbolAddress(&p, g_res1);   res1 = (float*)p;
    cudaGetSymbolAddress(&p, g_qkv);    qkv = (float*)p;
    cudaGetSymbolAddress(&p, g_scores); scores = (float*)p;
    cudaGetSymbolAddress(&p, g_x2);     x2 = (float*)p;
    cudaGetSymbolAddress(&p, g_hbuf);   hbuf = (float*)p;
    cudaGetSymbolAddress(&p, g_xh);  xh = (bf16*)p;  cudaGetSymbolAddress(&p, g_xl);  xl = (bf16*)p;
    cudaGetSymbolAddress(&p, g_x2h); x2h = (bf16*)p; cudaGetSymbolAddress(&p, g_x2l); x2l = (bf16*)p;
    cudaGetSymbolAddress(&p, g_qh);  qh = (bf16*)p;  cudaGetSymbolAddress(&p, g_ql);  ql = (bf16*)p;
    cudaGetSymbolAddress(&p, g_ph);  ph_ = (bf16*)p; cudaGetSymbolAddress(&p, g_pl);  pl_ = (bf16*)p;
    cudaGetSymbolAddress(&p, g_attnh); ath = (bf16*)p; cudaGetSymbolAddress(&p, g_attnl); atl = (bf16*)p;
    cudaGetSymbolAddress(&p, g_acth); acth = (bf16*)p; cudaGetSymbolAddress(&p, g_actl); actl = (bf16*)p;
    cudaGetSymbolAddress(&p, g_kbh); kbh = (bf16*)p; cudaGetSymbolAddress(&p, g_kbl); kbl = (bf16*)p;
    cudaGetSymbolAddress(&p, g_vth); vth = (bf16*)p; cudaGetSymbolAddress(&p, g_vtl); vtl = (bf16*)p;
    cudaGetSymbolAddress(&p, g_wqkvh); wqkvh = (bf16*)p; cudaGetSymbolAddress(&p, g_wqkvl); wqkvl = (bf16*)p;
    cudaGetSymbolAddress(&p, g_woh);   woh = (bf16*)p;   cudaGetSymbolAddress(&p, g_wol);   wol = (bf16*)p;
    cudaGetSymbolAddress(&p, g_wguh);  wguh = (bf16*)p;  cudaGetSymbolAddress(&p, g_wgul);  wgul = (bf16*)p;
    cudaGetSymbolAddress(&p, g_wdh);   wdh = (bf16*)p;   cudaGetSymbolAddress(&p, g_wdl);   wdl = (bf16*)p;
    cudaGetSymbolAddress(&p, g_cnt); cnt = (int*)p;
    cudaGetSymbolAddress(&p, g_tok); tok = (int*)p;
    cudaGetSymbolAddress(&p, g_wgt); wgt = (float*)p;
    cudaGetSymbolAddress(&p, g_topk_id); tkid = (int*)p;
    cudaGetSymbolAddress(&p, g_topk_w);  tkw = (float*)p;

    cudaFuncSetAttribute(gemm_m<false, 0, false>, cudaFuncAttributeMaxDynamicSharedMemorySize, GSM);
    cudaFuncSetAttribute(gemm_m<false, 1, false>, cudaFuncAttributeMaxDynamicSharedMemorySize, GSM);
    cudaFuncSetAttribute(gemm_m<false, 4, true>,  cudaFuncAttributeMaxDynamicSharedMemorySize, GSM);
    cudaFuncSetAttribute(gemm_m<false, 2, false>, cudaFuncAttributeMaxDynamicSharedMemorySize, GSM);
    cudaFuncSetAttribute(gemm_m<true,  0, false>, cudaFuncAttributeMaxDynamicSharedMemorySize, GSM);
    cudaFuncSetAttribute(gemm_m<false, 3, false>, cudaFuncAttributeMaxDynamicSharedMemorySize, GSM);

    cudaMemsetAsync(out, 0, (size_t)TT * HH * sizeof(float));
    cudaMemsetAsync(cnt, 0, NE * sizeof(int));

    // ---- weight prepass: transpose + bf16 hi/lo ----
    { dim3 g(QKVD / 32, HH / 32, 1);  k_tconv<<<g, dim3(32, 8)>>>(wqkv, QKVD, 0, wqkvh, wqkvl, HH, 0, HH, QKVD); }
    { dim3 g(HH / 32, HH / 32, 1);    k_tconv<<<g, dim3(32, 8)>>>(wo, HH, 0, woh, wol, HH, 0, HH, HH); }
    { dim3 g((2 * IM) / 32, HH / 32, NE);
      k_tconv<<<g, dim3(32, 8)>>>(wgu, 2 * IM, (long)HH * 2 * IM, wguh, wgul, HH, (long)2 * IM * HH, HH, 2 * IM); }
    { dim3 g(HH / 32, IM / 32, NE);
      k_tconv<<<g, dim3(32, 8)>>>(wd, HH, (long)IM * HH, wdh, wdl, IM, (long)HH * IM, IM, HH); }

    // 1) residual add + ln1
    k_addnorm<<<TT, 256>>>(hs, res, wln1, res1);

    // 2) qkv = x @ wqkv
    { dim3 g(QKVD / BNT, TT / BMT, 1);
      gemm_m<false, 0, false><<<g, 256, GSM>>>(
          xh, xl, HH, 0, wqkvh, wqkvl, HH, 0, 1,
          qkv, nullptr, nullptr, QKVD, 0, TT, QKVD, HH,
          nullptr, nullptr, 0, nullptr, 0, 1.f); }

    // 3) rope -> q/k bf16 hi/lo ; V transpose+convert
    k_rope<<<TT, 256>>>(positions, qkv);
    { dim3 g(HD / 32, TT / 32, NKV);
      k_tconv<<<g, dim3(32, 8)>>>(qkv + (NH + NKV) * HD, QKVD, HD, vth, vtl, TT, (long)HD * TT, TT, HD); }

    // 4) scores = scale * q @ k^T (causal tiles only)
    { dim3 g(TT / BNT, TT / BMT, NH);
      gemm_m<false, 1, false><<<g, 256, GSM>>>(
          qh, ql, NH * HD, HD, kbh, kbl, HD, (long)TT * HD, 4,
          scores, nullptr, nullptr, TT, (long)TT * TT, TT, TT, HD,
          nullptr, nullptr, 0, nullptr, 0, ATT_SCALE); }

    // 5) softmax -> probs bf16 hi/lo
    { dim3 g(TT, NH); k_softmax<<<g, 256>>>(scores); }

    // 6) attn = probs @ V  (K-limit at causal frontier; emits bf16 hi/lo)
    { dim3 g(1, TT / BMT, NH);
      gemm_m<false, 4, true><<<g, 256, GSM>>>(
          ph_, pl_, TT, (long)TT * TT, vth, vtl, TT, (long)HD * TT, 4,
          nullptr, ath, atl, HH, HD, TT, HD, TT,
          nullptr, nullptr, 0, nullptr, 0, 1.f); }

    // 7) res2 = attn @ wo + res1
    { dim3 g(HH / BNT, TT / BMT, 1);
      gemm_m<false, 2, false><<<g, 256, GSM>>>(
          ath, atl, HH, 0, woh, wol, HH, 0, 1,
          res2, nullptr, nullptr, HH, 0, TT, HH, HH,
          nullptr, nullptr, 0, res1, 0, 1.f); }

    // 8) x2 = rmsnorm(res2)
    k_norm<<<TT, 256>>>(res2, wln2);

    // 9) gating + scatter
    k_gate<<<TT, 256>>>(x2, gw, gb, tkid, tkw);
    k_scatter<<<(TT * TOPK + 255) / 256, 256>>>(tkid, tkw);

    // 10) per-expert gate_up (gather rows of x2)
    { dim3 g((2 * IM) / BNT, TT / BMT, NE);
      gemm_m<true, 0, false><<<g, 256, GSM>>>(
          x2h, x2l, HH, 0, wguh, wgul, HH, (long)2 * IM * HH, 1,
          hbuf, nullptr, nullptr, 2 * IM, (long)TT * 2 * IM, TT, 2 * IM, HH,
          cnt, tok, TT, nullptr, 0, 1.f); }

    // 11) silu(g)*u -> bf16 hi/lo
    { dim3 g(TT, NE); k_act<<<g, 256>>>(); }

    // 12) per-expert down + weighted scatter-add
    { dim3 g(HH / BNT, TT / BMT, NE);
      gemm_m<false, 3, false><<<g, 256, GSM>>>(
          acth, actl, IM, (long)TT * IM, wdh, wdl, IM, (long)HH * IM, 1,
          out, nullptr, nullptr, HH, 0, TT, HH, IM,
          cnt, tok, TT, wgt, TT, 1.f); }
}

// round 6
// speedup vs baseline: 3.2958x; 1.0364x over previous
#include <cuda_runtime.h>
#include <cuda_bf16.h>
#include <math.h>
#include <stdint.h>

#define TT 2048
#define HH 2048
#define NH 16
#define NKV 4
#define HD 128
#define NE 16
#define TOPK 4
#define NGRP 4
#define GSZ 4
#define TGRP 2
#define IM 1024
#define QKVD 3072
#define ATT_SCALE 0.08838834764831845f
#define EPSV 1e-6f

typedef __nv_bfloat16 bf16;

// ---------------- scratch (device globals; no allocations) ----------------
__device__ float g_res1[(size_t)TT * HH];
__device__ float g_qkv[(size_t)TT * QKVD];
__device__ float g_x2[(size_t)TT * HH];
__device__ bf16  g_xh[(size_t)TT * HH],  g_xl[(size_t)TT * HH];
__device__ bf16  g_x2h[(size_t)TT * HH], g_x2l[(size_t)TT * HH];
__device__ bf16  g_qh[(size_t)TT * (NH * HD)], g_ql[(size_t)TT * (NH * HD)];
__device__ bf16  g_attnh[(size_t)TT * HH], g_attnl[(size_t)TT * HH];
__device__ bf16  g_acth[(size_t)NE * TT * IM], g_actl[(size_t)NE * TT * IM];
__device__ bf16  g_kbh[(size_t)NKV * TT * HD], g_kbl[(size_t)NKV * TT * HD];
__device__ bf16  g_vth[(size_t)NKV * HD * TT], g_vtl[(size_t)NKV * HD * TT];
__device__ bf16  g_wqkvh[(size_t)QKVD * HH], g_wqkvl[(size_t)QKVD * HH];
__device__ bf16  g_woh[(size_t)HH * HH],     g_wol[(size_t)HH * HH];
__device__ bf16  g_wguh[(size_t)NE * 2 * IM * HH], g_wgul[(size_t)NE * 2 * IM * HH];
__device__ bf16  g_wdh[(size_t)NE * HH * IM],      g_wdl[(size_t)NE * HH * IM];
__device__ int   g_cnt[NE];
__device__ int   g_tok[NE * TT];
__device__ float g_wgt[NE * TT];
__device__ int   g_topk_id[TT * TOPK];
__device__ float g_topk_w[TT * TOPK];

// ---------------- helpers ----------------
__device__ __forceinline__ uint32_t smem_u32(const void* p) {
    uint32_t a;
    asm("{ .reg .u64 t; cvta.to.shared.u64 t, %1; cvt.u32.u64 %0, t; }" : "=r"(a) : "l"(p));
    return a;
}
__device__ __forceinline__ void split_bf(float v, bf16& h, bf16& l) {
    h = __float2bfloat16_rn(v);
    l = __float2bfloat16_rn(v - __bfloat162float(h));
}
__device__ __forceinline__ uint32_t pack2(bf16 a, bf16 b) {
    return (uint32_t)__bfloat16_as_ushort(a) | ((uint32_t)__bfloat16_as_ushort(b) << 16);
}
__device__ __forceinline__ void cpa(uint32_t d, const void* s, int sz) {
    asm volatile("cp.async.cg.shared.global [%0], [%1], 16, %2;" :: "r"(d), "l"(s), "r"(sz));
}
__device__ __forceinline__ void cpcommit() { asm volatile("cp.async.commit_group;" ::: "memory"); }
__device__ __forceinline__ void cpwait1()  { asm volatile("cp.async.wait_group 1;" ::: "memory"); }
__device__ __forceinline__ void cpwaitN(int n) {
    if (n == 0)      asm volatile("cp.async.wait_group 0;" ::: "memory");
    else if (n == 1) asm volatile("cp.async.wait_group 1;" ::: "memory");
    else             asm volatile("cp.async.wait_group 2;" ::: "memory");
}
__device__ __forceinline__ void ldm4(uint32_t* r, uint32_t a) {
    asm volatile("ldmatrix.sync.aligned.m8n8.x4.shared.b16 {%0,%1,%2,%3}, [%4];"
                 : "=r"(r[0]), "=r"(r[1]), "=r"(r[2]), "=r"(r[3]) : "r"(a));
}
__device__ __forceinline__ void mma16816(float* c, const uint32_t* a, const uint32_t* b) {
    asm volatile(
        "mma.sync.aligned.m16n8k16.row.col.f32.bf16.bf16.f32 "
        "{%0,%1,%2,%3},{%4,%5,%6,%7},{%8,%9},{%0,%1,%2,%3};"
        : "+f"(c[0]), "+f"(c[1]), "+f"(c[2]), "+f"(c[3])
        : "r"(a[0]), "r"(a[1]), "r"(a[2]), "r"(a[3]), "r"(b[0]), "r"(b[1]));
}

// ---------------- mma.sync bf16x3 GEMM ----------------
// C[z][M][N] (+)= alpha * A[z] @ B[z]^T ; all operands bf16 hi/lo, B rows = N-index, K contiguous.
// EPI: 0 fp32 store, 2 add X, 3 atomicAdd scatter, 5 silu(even)*odd -> bf16 hi/lo store.
#define BMT 128
#define BNT 128
#define BKT 32
#define AST 80u
#define STG_M 10240u
#define STG (4u * STG_M)
#define GSM (2 * 4 * 10240)

template <bool GA, int EPI>
__global__ void __launch_bounds__(256, 2)
gemm_m(const bf16* __restrict__ Ah0, const bf16* __restrict__ Al0, int lda, long saz,
       const bf16* __restrict__ Bh0, const bf16* __restrict__ Bl0, int ldb, long sbz, int bdiv,
       float* __restrict__ C0, bf16* __restrict__ Oh0, bf16* __restrict__ Ol0, int ldc, long scz,
       int M0, int N, int K,
       const int* __restrict__ Mptr, const int* __restrict__ gidx0, int sgz,
       const float* __restrict__ X0, long sxz, float alpha) {
    int z = blockIdx.z;
    int M = Mptr ? Mptr[z] : M0;
    int row0 = blockIdx.y * BMT, col0 = blockIdx.x * BNT;
    if (row0 >= M) return;

    extern __shared__ char smem[];
    uint32_t sb = smem_u32(smem);
    int tid = threadIdx.x, lane = tid & 31, wid = tid >> 5;
    const int m0w = (wid & 3) * 32, n0w = (wid >> 2) * 64;

    const int* gidxz = (GA || EPI == 3) ? gidx0 + (long)z * sgz : nullptr;
    const float* X = (EPI == 2 || EPI == 3) ? X0 + (long)z * sxz : nullptr;
    const bf16* Bh = Bh0 + (long)(z / bdiv) * sbz;
    const bf16* Bl = Bl0 + (long)(z / bdiv) * sbz;

    int nch = K / BKT;

    // loaders: row = tid>>1 (0..127), half = tid&1 (32B each)
    int lrow = tid >> 1, lhalf = tid & 1;
    int ari = row0 + lrow;
    bool av = ari < M;
    long agrow = ari;
    if (GA) agrow = av ? (long)gidxz[ari] : 0;
    const bf16* agh = Ah0 + (long)z * saz + agrow * (long)lda;
    const bf16* agl = Al0 + (long)z * saz + agrow * (long)lda;
    int asz = av ? 16 : 0;
    const bf16* bgh = Bh + (long)(col0 + lrow) * ldb;
    const bf16* bgl = Bl + (long)(col0 + lrow) * ldb;
    uint32_t dst_ab = sb + lrow * AST + lhalf * 32;
    uint32_t dst_bb = sb + 2 * STG_M + lrow * AST + lhalf * 32;

    auto cp_stage = [&](int buf, int k0) {
        uint32_t so = buf * STG;
        long ko = k0 + lhalf * 16;
        cpa(dst_ab + so,              agh + ko,     asz);
        cpa(dst_ab + so + 16,         agh + ko + 8, asz);
        cpa(dst_ab + so + STG_M,      agl + ko,     asz);
        cpa(dst_ab + so + STG_M + 16, agl + ko + 8, asz);
        cpa(dst_bb + so,              bgh + ko,     16);
        cpa(dst_bb + so + 16,         bgh + ko + 8, 16);
        cpa(dst_bb + so + STG_M,      bgl + ko,     16);
        cpa(dst_bb + so + STG_M + 16, bgl + ko + 8, 16);
    };

    float acc[2][8][4];
#pragma unroll
    for (int i = 0; i < 2; i++)
#pragma unroll
        for (int j = 0; j < 8; j++)
#pragma unroll
            for (int q = 0; q < 4; q++) acc[i][j][q] = 0.f;

    uint32_t a_off = (uint32_t)(m0w + (lane & 15)) * AST + (uint32_t)(lane >> 4) * 16;
    uint32_t b_off = (uint32_t)(n0w + ((lane >> 4) << 3) + (lane & 7)) * AST + (uint32_t)((lane >> 3) & 1) * 16;

    auto compute = [&](int buf) {
        uint32_t ab  = sb + buf * STG;
        uint32_t alb = ab + STG_M;
        uint32_t bhb = ab + 2 * STG_M;
        uint32_t blb = ab + 3 * STG_M;
#pragma unroll
        for (int s = 0; s < 2; s++) {
            uint32_t ka = s * 32;
            uint32_t ah0[4], ah1[4], al0[4], al1[4];
            ldm4(ah0, ab + a_off + ka);
            ldm4(ah1, ab + a_off + 16 * AST + ka);
            ldm4(al0, alb + a_off + ka);
            ldm4(al1, alb + a_off + 16 * AST + ka);
#pragma unroll
            for (int np = 0; np < 4; np++) {
                uint32_t bo = b_off + np * 16 * AST + ka;
                uint32_t bh[4], bl[4];
                ldm4(bh, bhb + bo);
                ldm4(bl, blb + bo);
                int ne = 2 * np, no = 2 * np + 1;
                mma16816(acc[0][ne], ah0, bh);     mma16816(acc[0][ne], ah0, bl);     mma16816(acc[0][ne], al0, bh);
                mma16816(acc[0][no], ah0, bh + 2); mma16816(acc[0][no], ah0, bl + 2); mma16816(acc[0][no], al0, bh + 2);
                mma16816(acc[1][ne], ah1, bh);     mma16816(acc[1][ne], ah1, bl);     mma16816(acc[1][ne], al1, bh);
                mma16816(acc[1][no], ah1, bh + 2); mma16816(acc[1][no], ah1, bl + 2); mma16816(acc[1][no], al1, bh + 2);
            }
        }
    };

    cp_stage(0, 0); cpcommit();
    cp_stage(1, BKT); cpcommit();
    cpwait1();
    __syncthreads();
    for (int c = 0; c < nch; c++) {
        int b = c & 1;
        compute(b);
        __syncthreads();
        if (c + 2 < nch) cp_stage(b, (c + 2) * BKT);
        cpcommit();
        cpwait1();
        __syncthreads();
    }

    // epilogue
    int lq = lane >> 2, lr = lane & 3;
#pragma unroll
    for (int mt = 0; mt < 2; mt++) {
        int r0 = row0 + m0w + mt * 16 + lq;
        int r1 = r0 + 8;
#pragma unroll
        for (int nt = 0; nt < 8; nt++) {
            long cc = (long)col0 + n0w + nt * 8 + 2 * lr;
            float v0 = acc[mt][nt][0] * alpha, v1 = acc[mt][nt][1] * alpha;
            float v2 = acc[mt][nt][2] * alpha, v3 = acc[mt][nt][3] * alpha;
            if (EPI == 5) {
                bf16* oh = Oh0 + (long)z * scz; bf16* ol = Ol0 + (long)z * scz;
                long co = cc >> 1;
                if (r0 < M) {
                    float a = v0 / (1.f + expf(-v0)) * v1;
                    bf16 h, l; split_bf(a, h, l);
                    oh[(long)r0 * ldc + co] = h; ol[(long)r0 * ldc + co] = l;
                }
                if (r1 < M) {
                    float a = v2 / (1.f + expf(-v2)) * v3;
                    bf16 h, l; split_bf(a, h, l);
                    oh[(long)r1 * ldc + co] = h; ol[(long)r1 * ldc + co] = l;
                }
            } else if (EPI == 3) {
                float* C = C0 + (long)z * scz;
                if (r0 < M) {
                    long gr = gidxz[r0]; float w = X[r0];
                    atomicAdd(&C[gr * ldc + cc], w * v0);
                    atomicAdd(&C[gr * ldc + cc + 1], w * v1);
                }
                if (r1 < M) {
                    long gr = gidxz[r1]; float w = X[r1];
                    atomicAdd(&C[gr * ldc + cc], w * v2);
                    atomicAdd(&C[gr * ldc + cc + 1], w * v3);
                }
            } else if (EPI == 2) {
                float* C = C0 + (long)z * scz;
                if (r0 < M) {
                    float2 xv = *(const float2*)&X[(long)r0 * ldc + cc];
                    *(float2*)&C[(long)r0 * ldc + cc] = make_float2(v0 + xv.x, v1 + xv.y);
                }
                if (r1 < M) {
                    float2 xv = *(const float2*)&X[(long)r1 * ldc + cc];
                    *(float2*)&C[(long)r1 * ldc + cc] = make_float2(v2 + xv.x, v3 + xv.y);
                }
            } else {
                float* C = C0 + (long)z * scz;
                if (r0 < M) *(float2*)&C[(long)r0 * ldc + cc] = make_float2(v0, v1);
                if (r1 < M) *(float2*)&C[(long)r1 * ldc + cc] = make_float2(v2, v3);
            }
        }
    }
}

// ---------------- flash attention (bf16x3, online softmax) ----------------
#define FA_Q  0u
#define FA_QL 40960u
#define FA_K  81920u
#define FA_KL 122880u
#define FA_V  163840u
#define FA_VL 184320u
#define FA_SMEM 204800

__global__ void __launch_bounds__(256, 1) k_flash() {
    extern __shared__ char smem[];
    uint32_t sb = smem_u32(smem);
    int head = blockIdx.x;
    int qb = (int)gridDim.y - 1 - (int)blockIdx.y;   // heavy blocks first
    int row0 = qb * 128;
    int kv = head >> 2;
    int tid = threadIdx.x, lane = tid & 31, w = tid >> 5;
    int lq = lane >> 2, lr = lane & 3;
    int lrow = tid >> 1, lhalf = tid & 1;

    const bf16* qgh = g_qh + (size_t)(row0 + lrow) * (NH * HD) + head * HD + lhalf * 16;
    const bf16* qgl = g_ql + (size_t)(row0 + lrow) * (NH * HD) + head * HD + lhalf * 16;
    const bf16* kgh = g_kbh + (size_t)kv * TT * HD + (size_t)lrow * HD + lhalf * 16;
    const bf16* kgl = g_kbl + (size_t)kv * TT * HD + (size_t)lrow * HD + lhalf * 16;
    const bf16* vgh = g_vth + (size_t)kv * HD * TT + (size_t)lrow * TT + lhalf * 16;
    const bf16* vgl = g_vtl + (size_t)kv * HD * TT + (size_t)lrow * TT + lhalf * 16;

    // Q load (one group)
#pragma unroll
    for (int c = 0; c < 4; c++) {
        uint32_t d = sb + FA_Q + (uint32_t)((c * 128 + lrow) * 80) + lhalf * 32;
        cpa(d, qgh + c * 32, 16); cpa(d + 16, qgh + c * 32 + 8, 16);
        uint32_t dl = d + (FA_QL - FA_Q);
        cpa(dl, qgl + c * 32, 16); cpa(dl + 16, qgl + c * 32 + 8, 16);
    }
    cpcommit();

    auto issueK = [&](int s0) {
#pragma unroll
        for (int c = 0; c < 4; c++) {
            uint32_t d = sb + FA_K + (uint32_t)((c * 128 + lrow) * 80) + lhalf * 32;
            const bf16* s = kgh + (size_t)s0 * HD + c * 32;
            cpa(d, s, 16); cpa(d + 16, s + 8, 16);
            uint32_t dl = d + (FA_KL - FA_K);
            const bf16* sl = kgl + (size_t)s0 * HD + c * 32;
            cpa(dl, sl, 16); cpa(dl + 16, sl + 8, 16);
        }
        cpcommit();
    };
    auto issueV = [&](int s0, int c) {
        uint32_t d = sb + FA_V + (uint32_t)(((c & 1) * 128 + lrow) * 80) + lhalf * 32;
        const bf16* s = vgh + s0 + c * 32;
        cpa(d, s, 16); cpa(d + 16, s + 8, 16);
        uint32_t dl = d + (FA_VL - FA_V);
        const bf16* sl = vgl + s0 + c * 32;
        cpa(dl, sl, 16); cpa(dl + 16, sl + 8, 16);
        cpcommit();
    };
    issueK(0);

    float O[16][4];
#pragma unroll
    for (int i = 0; i < 16; i++) { O[i][0] = O[i][1] = O[i][2] = O[i][3] = 0.f; }
    float m_lo = -1e30f, m_hi = -1e30f, l_lo = 0.f, l_hi = 0.f;
    int ntl = qb + 1;
    uint32_t a_off = (uint32_t)((w * 16 + (lane & 15)) * 80) + (uint32_t)(lane >> 4) * 16;
    uint32_t b_off = (uint32_t)((((lane >> 4) << 3) + (lane & 7)) * 80) + (uint32_t)((lane >> 3) & 1) * 16;

    for (int st = 0; st < ntl; st++) {
        int s0 = st * 128;
        __syncthreads();                 // V/K buffers free for reuse
        issueV(s0, 0); issueV(s0, 1);
        asm volatile("cp.async.wait_group 2;" ::: "memory");  // Q+K ready
        __syncthreads();

        float S[16][4];
#pragma unroll
        for (int i = 0; i < 16; i++) { S[i][0] = S[i][1] = S[i][2] = S[i][3] = 0.f; }
#pragma unroll
        for (int kc = 0; kc < 4; kc++)
#pragma unroll
        for (int ks = 0; ks < 2; ks++) {
            uint32_t qa = sb + (uint32_t)(kc * 128 * 80) + a_off + ks * 32;
            uint32_t ah[4], al[4];
            ldm4(ah, qa + FA_Q);
            ldm4(al, qa + FA_QL);
#pragma unroll
            for (int j = 0; j < 8; j++) {
                uint32_t kb = sb + FA_K + (uint32_t)((kc * 128 + 16 * j) * 80) + b_off + ks * 32;
                uint32_t bh[4], bl[4];
                ldm4(bh, kb); ldm4(bl, kb + (FA_KL - FA_K));
                mma16816(S[2 * j],     ah, bh);     mma16816(S[2 * j],     ah, bl);     mma16816(S[2 * j],     al, bh);
                mma16816(S[2 * j + 1], ah, bh + 2); mma16816(S[2 * j + 1], ah, bl + 2); mma16816(S[2 * j + 1], al, bh + 2);
            }
        }

        // scale + causal mask
        bool dg = (st == qb);
        int rlo = row0 + w * 16 + lq, rhi = rlo + 8;
#pragma unroll
        for (int nt = 0; nt < 16; nt++) {
            int cbase = s0 + nt * 8 + 2 * lr;
#pragma unroll
            for (int q = 0; q < 4; q++) {
                float v = S[nt][q] * ATT_SCALE;
                int col = cbase + (q & 1);
                int rw = (q < 2) ? rlo : rhi;
                if (dg && col > rw) v = -1e30f;
                S[nt][q] = v;
            }
        }
        // online softmax
        float mx0 = -1e30f, mx1 = -1e30f;
#pragma unroll
        for (int nt = 0; nt < 16; nt++) {
            mx0 = fmaxf(mx0, fmaxf(S[nt][0], S[nt][1]));
            mx1 = fmaxf(mx1, fmaxf(S[nt][2], S[nt][3]));
        }
        mx0 = fmaxf(mx0, __shfl_xor_sync(0xffffffffu, mx0, 1));
        mx0 = fmaxf(mx0, __shfl_xor_sync(0xffffffffu, mx0, 2));
        mx1 = fmaxf(mx1, __shfl_xor_sync(0xffffffffu, mx1, 1));
        mx1 = fmaxf(mx1, __shfl_xor_sync(0xffffffffu, mx1, 2));
        float mn0 = fmaxf(m_lo, mx0), mn1 = fmaxf(m_hi, mx1);
        float sc0 = expf(m_lo - mn0), sc1 = expf(m_hi - mn1);
        float rs0 = 0.f, rs1 = 0.f;
#pragma unroll
        for (int nt = 0; nt < 16; nt++) {
            S[nt][0] = expf(S[nt][0] - mn0); S[nt][1] = expf(S[nt][1] - mn0);
            S[nt][2] = expf(S[nt][2] - mn1); S[nt][3] = expf(S[nt][3] - mn1);
            rs0 += S[nt][0] + S[nt][1];
            rs1 += S[nt][2] + S[nt][3];
        }
        rs0 += __shfl_xor_sync(0xffffffffu, rs0, 1); rs0 += __shfl_xor_sync(0xffffffffu, rs0, 2);
        rs1 += __shfl_xor_sync(0xffffffffu, rs1, 1); rs1 += __shfl_xor_sync(0xffffffffu, rs1, 2);
        l_lo = l_lo * sc0 + rs0; l_hi = l_hi * sc1 + rs1;
        m_lo = mn0; m_hi = mn1;
#pragma unroll
        for (int nt = 0; nt < 16; nt++) {
            O[nt][0] *= sc0; O[nt][1] *= sc0; O[nt][2] *= sc1; O[nt][3] *= sc1;
        }

        __syncthreads();                 // all warps done reading K
        bool haveK = (st + 1 < ntl);
        if (haveK) issueK(s0 + 128);

        // PV over 4 V chunks (32 s each)
#pragma unroll 1
        for (int c = 0; c < 4; c++) {
            int pend = haveK ? (c <= 1 ? 2 : (c == 2 ? 1 : 0)) : (c < 3 ? 1 : 0);
            cpwaitN(pend);
            __syncthreads();
#pragma unroll
            for (int ks = 0; ks < 2; ks++) {
                int t0 = 2 * (2 * c + ks), t1 = t0 + 1;
                uint32_t pah[4], pal[4];
                bf16 h0, l0, h1, l1;
                split_bf(S[t0][0], h0, l0); split_bf(S[t0][1], h1, l1);
                pah[0] = pack2(h0, h1); pal[0] = pack2(l0, l1);
                split_bf(S[t0][2], h0, l0); split_bf(S[t0][3], h1, l1);
                pah[1] = pack2(h0, h1); pal[1] = pack2(l0, l1);
                split_bf(S[t1][0], h0, l0); split_bf(S[t1][1], h1, l1);
                pah[2] = pack2(h0, h1); pal[2] = pack2(l0, l1);
                split_bf(S[t1][2], h0, l0); split_bf(S[t1][3], h1, l1);
                pah[3] = pack2(h0, h1); pal[3] = pack2(l0, l1);
#pragma unroll
                for (int j = 0; j < 8; j++) {
                    uint32_t vb = sb + FA_V + (uint32_t)((((c & 1) * 128) + 16 * j) * 80) + b_off + ks * 32;
                    uint32_t vh[4], vl[4];
                    ldm4(vh, vb); ldm4(vl, vb + (FA_VL - FA_V));
                    mma16816(O[2 * j],     pah, vh);     mma16816(O[2 * j],     pah, vl);     mma16816(O[2 * j],     pal, vh);
                    mma16816(O[2 * j + 1], pah, vh + 2); mma16816(O[2 * j + 1], pah, vl + 2); mma16816(O[2 * j + 1], pal, vh + 2);
                }
            }
            __syncthreads();
            if (c + 2 < 4) issueV(s0, c + 2);
        }
    }

    // normalize + write bf16 hi/lo
    float il0 = 1.f / l_lo, il1 = 1.f / l_hi;
    int rlo = row0 + w * 16 + lq, rhi = rlo + 8;
#pragma unroll
    for (int nt = 0; nt < 16; nt++) {
        long col = (long)head * HD + nt * 8 + 2 * lr;
        bf16 h0, l0, h1, l1;
        float v0 = O[nt][0] * il0, v1 = O[nt][1] * il0;
        split_bf(v0, h0, l0); split_bf(v1, h1, l1);
        *(uint32_t*)&g_attnh[(long)rlo * HH + col] = pack2(h0, h1);
        *(uint32_t*)&g_attnl[(long)rlo * HH + col] = pack2(l0, l1);
        float v2 = O[nt][2] * il1, v3 = O[nt][3] * il1;
        split_bf(v2, h0, l0); split_bf(v3, h1, l1);
        *(uint32_t*)&g_attnh[(long)rhi * HH + col] = pack2(h0, h1);
        *(uint32_t*)&g_attnl[(long)rhi * HH + col] = pack2(l0, l1);
    }
}

// ---------------- transpose + convert fp32 -> bf16 hi/lo (opt. gate/up interleave) --
__global__ void k_tconv(const float* __restrict__ in, long ldin, long sbin,
                        bf16* __restrict__ oh, bf16* __restrict__ ol, long ldo, long sbo,
                        int R, int C, int ilv) {
    __shared__ float t[32][33];
    int z = blockIdx.z;
    const float* I = in + (long)z * sbin;
    int c0 = blockIdx.x * 32, r0 = blockIdx.y * 32;
#pragma unroll
    for (int i = 0; i < 4; i++) {
        int r = r0 + threadIdx.y + i * 8, c = c0 + threadIdx.x;
        t[threadIdx.y + i * 8][threadIdx.x] = (r < R && c < C) ? I[(long)r * ldin + c] : 0.f;
    }
    __syncthreads();
#pragma unroll
    for (int i = 0; i < 4; i++) {
        int orow = c0 + threadIdx.y + i * 8, ocol = r0 + threadIdx.x;
        if (orow < C && ocol < R) {
            bf16 h, l;
            split_bf(t[threadIdx.x][threadIdx.y + i * 8], h, l);
            int orr = orow;
            if (ilv) orr = (orow < ilv) ? 2 * orow : 2 * (orow - ilv) + 1;
            oh[(long)z * sbo + (long)orr * ldo + ocol] = h;
            ol[(long)z * sbo + (long)orr * ldo + ocol] = l;
        }
    }
}

// ---------------- residual add + rmsnorm ----------------
__global__ void k_addnorm(const float* __restrict__ hs, const float* __restrict__ res,
                          const float* __restrict__ w, float* __restrict__ res_out) {
    int t = blockIdx.x;
    __shared__ float red[256];
    float ss = 0.f;
    for (int i = threadIdx.x; i < HH; i += 256) {
        float v = hs[(size_t)t * HH + i] + res[(size_t)t * HH + i];
        res_out[(size_t)t * HH + i] = v;
        ss += v * v;
    }
    red[threadIdx.x] = ss; __syncthreads();
    for (int s = 128; s > 0; s >>= 1) { if (threadIdx.x < s) red[threadIdx.x] += red[threadIdx.x + s]; __syncthreads(); }
    float inv = rsqrtf(red[0] / (float)HH + EPSV);
    for (int i = threadIdx.x; i < HH; i += 256) {
        float v = res_out[(size_t)t * HH + i] * inv * w[i];
        bf16 h, l; split_bf(v, h, l);
        g_xh[(size_t)t * HH + i] = h; g_xl[(size_t)t * HH + i] = l;
    }
}

__global__ void k_norm(const float* __restrict__ in, const float* __restrict__ w) {
    int t = blockIdx.x;
    __shared__ float red[256];
    float ss = 0.f;
    for (int i = threadIdx.x; i < HH; i += 256) { float v = in[(size_t)t * HH + i]; ss += v * v; }
    red[threadIdx.x] = ss; __syncthreads();
    for (int s = 128; s > 0; s >>= 1) { if (threadIdx.x < s) red[threadIdx.x] += red[threadIdx.x + s]; __syncthreads(); }
    float inv = rsqrtf(red[0] / (float)HH + EPSV);
    for (int i = threadIdx.x; i < HH; i += 256) {
        float v = in[(size_t)t * HH + i] * inv * w[i];
        g_x2[(size_t)t * HH + i] = v;
        bf16 h, l; split_bf(v, h, l);
        g_x2h[(size_t)t * HH + i] = h; g_x2l[(size_t)t * HH + i] = l;
    }
}

// ---------------- RoPE: emit q and k directly as bf16 hi/lo ----------------
__global__ void k_rope(const int* __restrict__ pos, const float* __restrict__ qkv) {
    int t = blockIdx.x;
    float fp = (float)pos[t];
    for (int idx = threadIdx.x; idx < (NH + NKV) * 64; idx += 256) {
        int hh = idx >> 6, d = idx & 63;
        float inv = powf(1e6f, -(float)d / 64.f);
        float ang = fp * inv;
        float c = cosf(ang), s = sinf(ang);
        const float* p = qkv + (size_t)t * QKVD + hh * HD;
        float x1 = p[d], x2 = p[d + 64];
        float v1 = x1 * c - x2 * s;
        float v2 = x2 * c + x1 * s;
        bf16 h1, l1, h2, l2;
        split_bf(v1, h1, l1); split_bf(v2, h2, l2);
        if (hh < NH) {
            size_t b = (size_t)t * (NH * HD) + hh * HD;
            g_qh[b + d] = h1; g_ql[b + d] = l1;
            g_qh[b + d + 64] = h2; g_ql[b + d + 64] = l2;
        } else {
            int kv = hh - NH;
            size_t b = (size_t)kv * TT * HD + (size_t)t * HD;
            g_kbh[b + d] = h1; g_kbl[b + d] = l1;
            g_kbh[b + d + 64] = h2; g_kbl[b + d + 64] = l2;
        }
    }
}

// ---------------- MoE gating ----------------
__global__ void k_gate(const float* __restrict__ x2, const float* __restrict__ gw,
                       const float* __restrict__ gb,
                       int* __restrict__ ids, float* __restrict__ ws) {
    int t = blockIdx.x;
    int tid = threadIdx.x, wid = tid >> 5, lane = tid & 31;
    __shared__ float logit[NE];
    for (int e = wid; e < NE; e += 8) {
        float acc = 0.f;
        for (int i = lane; i < HH; i += 32)
            acc += x2[(size_t)t * HH + i] * gw[(size_t)e * HH + i];
#pragma unroll
        for (int o = 16; o > 0; o >>= 1) acc += __shfl_down_sync(0xffffffffu, acc, o);
        if (lane == 0) logit[e] = acc;
    }
    __syncthreads();
    if (tid == 0) {
        float s[NE], sc[NE];
        for (int e = 0; e < NE; e++) { s[e] = 1.f / (1.f + expf(-logit[e])); sc[e] = s[e] + gb[e]; }
        float gscore[NGRP];
        for (int g = 0; g < NGRP; g++) {
            float a = -3.4e38f, b = -3.4e38f;
            for (int j = 0; j < GSZ; j++) {
                float v = sc[g * GSZ + j];
                if (v > a) { b = a; a = v; } else if (v > b) b = v;
            }
            gscore[g] = a + b;
        }
        bool gsel[NGRP] = {false, false, false, false};
        for (int k = 0; k < TGRP; k++) {
            int best = -1; float bv = -3.4e38f;
            for (int g = 0; g < NGRP; g++)
                if (!gsel[g] && gscore[g] > bv) { bv = gscore[g]; best = g; }
            gsel[best] = true;
        }
        bool used[NE];
        for (int e = 0; e < NE; e++) used[e] = !gsel[e / GSZ];
        float tsum = 0.f;
        int pick[TOPK]; float pw[TOPK];
        for (int k = 0; k < TOPK; k++) {
            int best = -1; float bv = -3.4e38f;
            for (int e = 0; e < NE; e++)
                if (!used[e] && sc[e] > bv) { bv = sc[e]; best = e; }
            used[best] = true;
            pick[k] = best; pw[k] = s[best]; tsum += s[best];
        }
        float inv = 1.f / tsum;
        for (int k = 0; k < TOPK; k++) {
            ids[t * TOPK + k] = pick[k];
            ws[t * TOPK + k] = pw[k] * inv;
        }
    }
}

__global__ void k_scatter(const int* __restrict__ ids, const float* __restrict__ ws) {
    int i = blockIdx.x * 256 + threadIdx.x;
    if (i >= TT * TOPK) return;
    int e = ids[i];
    int slot = atomicAdd(&g_cnt[e], 1);
    g_tok[e * TT + slot] = i / TOPK;
    g_wgt[e * TT + slot] = ws[i];
}

// ---------------- launch ----------------
extern "C" void kernel_launch(void* const* d_in, const int* in_sizes, int n_in,
                              void* d_out_, int out_size) {
    const int*   positions = (const int*)d_in[0];
    const float* hs   = (const float*)d_in[1];
    const float* res  = (const float*)d_in[2];
    const float* wln1 = (const float*)d_in[3];
    const float* wln2 = (const float*)d_in[4];
    const float* wqkv = (const float*)d_in[5];
    const float* wo   = (const float*)d_in[6];
    const float* gw   = (const float*)d_in[7];
    const float* gb   = (const float*)d_in[8];
    const float* wgu  = (const float*)d_in[9];
    const float* wd   = (const float*)d_in[10];
    float* out  = (float*)d_out_;
    float* res2 = out + (size_t)TT * HH;

    void* p;
    float *res1, *qkv, *x2, *wgt;
    bf16 *xh, *xl, *x2h, *x2l, *ath, *atl, *acth, *actl, *vth, *vtl;
    bf16 *wqkvh, *wqkvl, *woh, *wol, *wguh, *wgul, *wdh, *wdl;
    int *cnt, *tok, *tkid; float* tkw;
    cudaGetSymbolAddress(&p, g_res1);   res1 = (float*)p;
    cudaGetSymbolAddress(&p, g_qkv);    qkv = (float*)p;
    cudaGetSymbolAddress(&p, g_x2);     x2 = (float*)p;
    cudaGetSymbolAddress(&p, g_xh);  xh = (bf16*)p;  cudaGetSymbolAddress(&p, g_xl);  xl = (bf16*)p;
    cudaGetSymbolAddress(&p, g_x2h); x2h = (bf16*)p; cudaGetSymbolAddress(&p, g_x2l); x2l = (bf16*)p;
    cudaGetSymbolAddress(&p, g_attnh); ath = (bf16*)p; cudaGetSymbolAddress(&p, g_attnl); atl = (bf16*)p;
    cudaGetSymbolAddress(&p, g_acth); acth = (bf16*)p; cudaGetSymbolAddress(&p, g_actl); actl = (bf16*)p;
    cudaGetSymbolAddress(&p, g_vth); vth = (bf16*)p; cudaGetSymbolAddress(&p, g_vtl); vtl = (bf16*)p;
    cudaGetSymbolAddress(&p, g_wqkvh); wqkvh = (bf16*)p; cudaGetSymbolAddress(&p, g_wqkvl); wqkvl = (bf16*)p;
    cudaGetSymbolAddress(&p, g_woh);   woh = (bf16*)p;   cudaGetSymbolAddress(&p, g_wol);   wol = (bf16*)p;
    cudaGetSymbolAddress(&p, g_wguh);  wguh = (bf16*)p;  cudaGetSymbolAddress(&p, g_wgul);  wgul = (bf16*)p;
    cudaGetSymbolAddress(&p, g_wdh);   wdh = (bf16*)p;   cudaGetSymbolAddress(&p, g_wdl);   wdl = (bf16*)p;
    cudaGetSymbolAddress(&p, g_cnt); cnt = (int*)p;
    cudaGetSymbolAddress(&p, g_tok); tok = (int*)p;
    cudaGetSymbolAddress(&p, g_wgt); wgt = (float*)p;
    cudaGetSymbolAddress(&p, g_topk_id); tkid = (int*)p;
    cudaGetSymbolAddress(&p, g_topk_w);  tkw = (float*)p;

    cudaFuncSetAttribute(gemm_m<false, 0>, cudaFuncAttributeMaxDynamicSharedMemorySize, GSM);
    cudaFuncSetAttribute(gemm_m<false, 2>, cudaFuncAttributeMaxDynamicSharedMemorySize, GSM);
    cudaFuncSetAttribute(gemm_m<true,  5>, cudaFuncAttributeMaxDynamicSharedMemorySize, GSM);
    cudaFuncSetAttribute(gemm_m<false, 3>, cudaFuncAttributeMaxDynamicSharedMemorySize, GSM);
    cudaFuncSetAttribute(k_flash, cudaFuncAttributeMaxDynamicSharedMemorySize, FA_SMEM);

    cudaMemsetAsync(out, 0, (size_t)TT * HH * sizeof(float));
    cudaMemsetAsync(cnt, 0, NE * sizeof(int));

    // ---- weight prepass: transpose + bf16 hi/lo (wgu interleaved gate/up) ----
    { dim3 g(QKVD / 32, HH / 32, 1);  k_tconv<<<g, dim3(32, 8)>>>(wqkv, QKVD, 0, wqkvh, wqkvl, HH, 0, HH, QKVD, 0); }
    { dim3 g(HH / 32, HH / 32, 1);    k_tconv<<<g, dim3(32, 8)>>>(wo, HH, 0, woh, wol, HH, 0, HH, HH, 0); }
    { dim3 g((2 * IM) / 32, HH / 32, NE);
      k_tconv<<<g, dim3(32, 8)>>>(wgu, 2 * IM, (long)HH * 2 * IM, wguh, wgul, HH, (long)2 * IM * HH, HH, 2 * IM, IM); }
    { dim3 g(HH / 32, IM / 32, NE);
      k_tconv<<<g, dim3(32, 8)>>>(wd, HH, (long)IM * HH, wdh, wdl, IM, (long)HH * IM, IM, HH, 0); }

    // 1) residual add + ln1
    k_addnorm<<<TT, 256>>>(hs, res, wln1, res1);

    // 2) qkv = x @ wqkv
    { dim3 g(QKVD / BNT, TT / BMT, 1);
      gemm_m<false, 0><<<g, 256, GSM>>>(
          xh, xl, HH, 0, wqkvh, wqkvl, HH, 0, 1,
          qkv, nullptr, nullptr, QKVD, 0, TT, QKVD, HH,
          nullptr, nullptr, 0, nullptr, 0, 1.f); }

    // 3) rope -> q/k bf16 hi/lo ; V transpose+convert
    k_rope<<<TT, 256>>>(positions, qkv);
    { dim3 g(HD / 32, TT / 32, NKV);
      k_tconv<<<g, dim3(32, 8)>>>(qkv + (NH + NKV) * HD, QKVD, HD, vth, vtl, TT, (long)HD * TT, TT, HD, 0); }

    // 4-6) flash attention (fused scores/softmax/PV) -> attn bf16 hi/lo
    { dim3 g(NH, TT / 128); k_flash<<<g, 256, FA_SMEM>>>(); }

    // 7) res2 = attn @ wo + res1
    { dim3 g(HH / BNT, TT / BMT, 1);
      gemm_m<false, 2><<<g, 256, GSM>>>(
          ath, atl, HH, 0, woh, wol, HH, 0, 1,
          res2, nullptr, nullptr, HH, 0, TT, HH, HH,
          nullptr, nullptr, 0, res1, 0, 1.f); }

    // 8) x2 = rmsnorm(res2)
    k_norm<<<TT, 256>>>(res2, wln2);

    // 9) gating + scatter
    k_gate<<<TT, 256>>>(x2, gw, gb, tkid, tkw);
    k_scatter<<<(TT * TOPK + 255) / 256, 256>>>(tkid, tkw);

    // 10) per-expert gate_up + fused silu -> act bf16 hi/lo
    { dim3 g((2 * IM) / BNT, TT / BMT, NE);
      gemm_m<true, 5><<<g, 256, GSM>>>(
          x2h, x2l, HH, 0, wguh, wgul, HH, (long)2 * IM * HH, 1,
          nullptr, acth, actl, IM, (long)TT * IM, TT, 2 * IM, HH,
          cnt, tok, TT, nullptr, 0, 1.f); }

    // 11) per-expert down + weighted scatter-add
    { dim3 g(HH / BNT, TT / BMT, NE);
      gemm_m<false, 3><<<g, 256, GSM>>>(
          acth, actl, IM, (long)TT * IM, wdh, wdl, IM, (long)HH * IM, 1,
          out, nullptr, nullptr, HH, 0, TT, HH, IM,
          cnt, tok, TT, wgt, TT, 1.f); }
}

// round 7
// speedup vs baseline: 3.4424x; 1.0445x over previous
#include <cuda_runtime.h>
#include <cuda_bf16.h>
#include <math.h>
#include <stdint.h>

#define TT 2048
#define HH 2048
#define NH 16
#define NKV 4
#define HD 128
#define NE 16
#define TOPK 4
#define NGRP 4
#define GSZ 4
#define TGRP 2
#define IM 1024
#define QKVD 3072
#define ATT_SCALE 0.08838834764831845f
#define EPSV 1e-6f

typedef __nv_bfloat16 bf16;

// ---------------- scratch (device globals; no allocations) ----------------
__device__ float g_res1[(size_t)TT * HH];
__device__ float g_qkv[(size_t)TT * QKVD];
__device__ float g_x2[(size_t)TT * HH];
__device__ bf16  g_xh[(size_t)TT * HH],  g_xl[(size_t)TT * HH];
__device__ bf16  g_x2h[(size_t)TT * HH], g_x2l[(size_t)TT * HH];
__device__ bf16  g_qh[(size_t)TT * (NH * HD)], g_ql[(size_t)TT * (NH * HD)];
__device__ bf16  g_attnh[(size_t)TT * HH], g_attnl[(size_t)TT * HH];
__device__ bf16  g_acth[(size_t)NE * TT * IM], g_actl[(size_t)NE * TT * IM];
__device__ bf16  g_kbh[(size_t)NKV * TT * HD], g_kbl[(size_t)NKV * TT * HD];
__device__ bf16  g_vth[(size_t)NKV * HD * TT], g_vtl[(size_t)NKV * HD * TT];
__device__ bf16  g_wqkvh[(size_t)HH * QKVD], g_wqkvl[(size_t)HH * QKVD];
__device__ bf16  g_woh[(size_t)HH * HH],     g_wol[(size_t)HH * HH];
__device__ bf16  g_wguh[(size_t)NE * HH * 2 * IM], g_wgul[(size_t)NE * HH * 2 * IM];
__device__ bf16  g_wdh[(size_t)NE * IM * HH],      g_wdl[(size_t)NE * IM * HH];
__device__ int   g_cnt[NE];
__device__ int   g_tok[NE * TT];
__device__ float g_wgt[NE * TT];
__device__ int   g_topk_id[TT * TOPK];
__device__ float g_topk_w[TT * TOPK];

// ---------------- helpers ----------------
__device__ __forceinline__ uint32_t smem_u32(const void* p) {
    uint32_t a;
    asm("{ .reg .u64 t; cvta.to.shared.u64 t, %1; cvt.u32.u64 %0, t; }" : "=r"(a) : "l"(p));
    return a;
}
__device__ __forceinline__ void split_bf(float v, bf16& h, bf16& l) {
    h = __float2bfloat16_rn(v);
    l = __float2bfloat16_rn(v - __bfloat162float(h));
}
__device__ __forceinline__ uint32_t pack2(bf16 a, bf16 b) {
    return (uint32_t)__bfloat16_as_ushort(a) | ((uint32_t)__bfloat16_as_ushort(b) << 16);
}
__device__ __forceinline__ void cpa(uint32_t d, const void* s, int sz) {
    asm volatile("cp.async.cg.shared.global [%0], [%1], 16, %2;" :: "r"(d), "l"(s), "r"(sz));
}
__device__ __forceinline__ void cpcommit() { asm volatile("cp.async.commit_group;" ::: "memory"); }
__device__ __forceinline__ void cpwait1()  { asm volatile("cp.async.wait_group 1;" ::: "memory"); }
__device__ __forceinline__ void cpwaitN(int n) {
    if (n == 0)      asm volatile("cp.async.wait_group 0;" ::: "memory");
    else if (n == 1) asm volatile("cp.async.wait_group 1;" ::: "memory");
    else             asm volatile("cp.async.wait_group 2;" ::: "memory");
}
__device__ __forceinline__ void ldm4(uint32_t* r, uint32_t a) {
    asm volatile("ldmatrix.sync.aligned.m8n8.x4.shared.b16 {%0,%1,%2,%3}, [%4];"
                 : "=r"(r[0]), "=r"(r[1]), "=r"(r[2]), "=r"(r[3]) : "r"(a));
}
__device__ __forceinline__ void ldm4t(uint32_t* r, uint32_t a) {
    asm volatile("ldmatrix.sync.aligned.m8n8.x4.trans.shared.b16 {%0,%1,%2,%3}, [%4];"
                 : "=r"(r[0]), "=r"(r[1]), "=r"(r[2]), "=r"(r[3]) : "r"(a));
}
__device__ __forceinline__ void mma16816(float* c, const uint32_t* a, const uint32_t* b) {
    asm volatile(
        "mma.sync.aligned.m16n8k16.row.col.f32.bf16.bf16.f32 "
        "{%0,%1,%2,%3},{%4,%5,%6,%7},{%8,%9},{%0,%1,%2,%3};"
        : "+f"(c[0]), "+f"(c[1]), "+f"(c[2]), "+f"(c[3])
        : "r"(a[0]), "r"(a[1]), "r"(a[2]), "r"(a[3]), "r"(b[0]), "r"(b[1]));
}

// ---------------- mma.sync bf16x3 GEMM (B in K-major [K][N], trans fragments) ------
// C[z][M][N] (+)= alpha * A[z] @ W[z] ; W stored [K][N] row-major, bf16 hi/lo.
// EPI: 0 fp32 store, 2 add X, 3 atomicAdd scatter, 5 silu(even)*odd -> bf16 hi/lo.
#define BMT 128
#define BNT 128
#define BKT 32
#define AST 80u
#define BST 272u
#define A_SZ 10240u
#define B_SZ 8704u
#define STG2 (2u * A_SZ + 2u * B_SZ)   // 37888
#define GSM (2 * 37888)

template <bool GA, int EPI>
__global__ void __launch_bounds__(256, 2)
gemm_m(const bf16* __restrict__ Ah0, const bf16* __restrict__ Al0, int lda, long saz,
       const bf16* __restrict__ Bh0, const bf16* __restrict__ Bl0, int ldb, long sbz, int bdiv,
       float* __restrict__ C0, bf16* __restrict__ Oh0, bf16* __restrict__ Ol0, int ldc, long scz,
       int M0, int N, int K,
       const int* __restrict__ Mptr, const int* __restrict__ gidx0, int sgz,
       const float* __restrict__ X0, long sxz, float alpha) {
    int z = blockIdx.z;
    int M = Mptr ? Mptr[z] : M0;
    int row0 = blockIdx.y * BMT, col0 = blockIdx.x * BNT;
    if (row0 >= M) return;

    extern __shared__ char smem[];
    uint32_t sb = smem_u32(smem);
    int tid = threadIdx.x, lane = tid & 31, wid = tid >> 5;
    const int m0w = (wid & 3) * 32, n0w = (wid >> 2) * 64;

    const int* gidxz = (GA || EPI == 3) ? gidx0 + (long)z * sgz : nullptr;
    const float* X = (EPI == 2 || EPI == 3) ? X0 + (long)z * sxz : nullptr;
    const bf16* Bh = Bh0 + (long)(z / bdiv) * sbz + col0;
    const bf16* Bl = Bl0 + (long)(z / bdiv) * sbz + col0;

    int nch = K / BKT;

    // A loader: row = tid>>1 (0..127), half = tid&1 (32B each)
    int lrow = tid >> 1, lhalf = tid & 1;
    int ari = row0 + lrow;
    bool av = ari < M;
    long agrow = ari;
    if (GA) agrow = av ? (long)gidxz[ari] : 0;
    const bf16* agh = Ah0 + (long)z * saz + agrow * (long)lda;
    const bf16* agl = Al0 + (long)z * saz + agrow * (long)lda;
    int asz = av ? 16 : 0;
    uint32_t dst_a = sb + lrow * AST + lhalf * 32;
    // B loader: k-row = tid>>3 (0..31), th = tid&7 (16 elems each)
    int brow = tid >> 3, bth = tid & 7;
    uint32_t dst_b = sb + 2 * A_SZ + brow * BST + bth * 32;

    auto cp_stage = [&](int buf, int k0) {
        uint32_t so = buf * STG2;
        long ko = k0 + lhalf * 16;
        cpa(dst_a + so,             agh + ko,     asz);
        cpa(dst_a + so + 16,        agh + ko + 8, asz);
        cpa(dst_a + so + A_SZ,      agl + ko,     asz);
        cpa(dst_a + so + A_SZ + 16, agl + ko + 8, asz);
        long bko = (long)(k0 + brow) * ldb + bth * 16;
        cpa(dst_b + so,             Bh + bko,     16);
        cpa(dst_b + so + 16,        Bh + bko + 8, 16);
        cpa(dst_b + so + B_SZ,      Bl + bko,     16);
        cpa(dst_b + so + B_SZ + 16, Bl + bko + 8, 16);
    };

    float acc[2][8][4];
#pragma unroll
    for (int i = 0; i < 2; i++)
#pragma unroll
        for (int j = 0; j < 8; j++)
#pragma unroll
            for (int q = 0; q < 4; q++) acc[i][j][q] = 0.f;

    uint32_t a_off = (uint32_t)(m0w + (lane & 15)) * AST + (uint32_t)(lane >> 4) * 16;
    // B trans frag: lane l -> matrix j=l>>3: k-row (j&1)*8 + (l&7), n-col (j>>1)*8
    uint32_t b_off = (uint32_t)((lane & 7) + ((lane >> 3) & 1) * 8) * BST
                   + (uint32_t)(lane >> 4) * 16;

    auto compute = [&](int buf) {
        uint32_t ab  = sb + buf * STG2;
        uint32_t alb = ab + A_SZ;
        uint32_t bhb = ab + 2 * A_SZ;
        uint32_t blb = bhb + B_SZ;
#pragma unroll
        for (int s = 0; s < 2; s++) {
            uint32_t ka = s * 32;
            uint32_t ah0[4], ah1[4], al0[4], al1[4];
            ldm4(ah0, ab + a_off + ka);
            ldm4(ah1, ab + a_off + 16 * AST + ka);
            ldm4(al0, alb + a_off + ka);
            ldm4(al1, alb + a_off + 16 * AST + ka);
            uint32_t bs = b_off + s * (16 * BST);
#pragma unroll
            for (int np = 0; np < 4; np++) {
                uint32_t bo = bs + (uint32_t)((n0w + np * 16) * 2);
                uint32_t bh[4], bl[4];
                ldm4t(bh, bhb + bo);
                ldm4t(bl, blb + bo);
                int ne = 2 * np, no = 2 * np + 1;
                mma16816(acc[0][ne], ah0, bh);     mma16816(acc[0][ne], ah0, bl);     mma16816(acc[0][ne], al0, bh);
                mma16816(acc[0][no], ah0, bh + 2); mma16816(acc[0][no], ah0, bl + 2); mma16816(acc[0][no], al0, bh + 2);
                mma16816(acc[1][ne], ah1, bh);     mma16816(acc[1][ne], ah1, bl);     mma16816(acc[1][ne], al1, bh);
                mma16816(acc[1][no], ah1, bh + 2); mma16816(acc[1][no], ah1, bl + 2); mma16816(acc[1][no], al1, bh + 2);
            }
        }
    };

    cp_stage(0, 0); cpcommit();
    cp_stage(1, BKT); cpcommit();
    cpwait1();
    __syncthreads();
    for (int c = 0; c < nch; c++) {
        int b = c & 1;
        compute(b);
        __syncthreads();
        if (c + 2 < nch) cp_stage(b, (c + 2) * BKT);
        cpcommit();
        cpwait1();
        __syncthreads();
    }

    // epilogue
    int lq = lane >> 2, lr = lane & 3;
#pragma unroll
    for (int mt = 0; mt < 2; mt++) {
        int r0 = row0 + m0w + mt * 16 + lq;
        int r1 = r0 + 8;
#pragma unroll
        for (int nt = 0; nt < 8; nt++) {
            long cc = (long)col0 + n0w + nt * 8 + 2 * lr;
            float v0 = acc[mt][nt][0] * alpha, v1 = acc[mt][nt][1] * alpha;
            float v2 = acc[mt][nt][2] * alpha, v3 = acc[mt][nt][3] * alpha;
            if (EPI == 5) {
                bf16* oh = Oh0 + (long)z * scz; bf16* ol = Ol0 + (long)z * scz;
                long co = cc >> 1;
                if (r0 < M) {
                    float a = v0 / (1.f + expf(-v0)) * v1;
                    bf16 h, l; split_bf(a, h, l);
                    oh[(long)r0 * ldc + co] = h; ol[(long)r0 * ldc + co] = l;
                }
                if (r1 < M) {
                    float a = v2 / (1.f + expf(-v2)) * v3;
                    bf16 h, l; split_bf(a, h, l);
                    oh[(long)r1 * ldc + co] = h; ol[(long)r1 * ldc + co] = l;
                }
            } else if (EPI == 3) {
                float* C = C0 + (long)z * scz;
                if (r0 < M) {
                    long gr = gidxz[r0]; float w = X[r0];
                    atomicAdd(&C[gr * ldc + cc], w * v0);
                    atomicAdd(&C[gr * ldc + cc + 1], w * v1);
                }
                if (r1 < M) {
                    long gr = gidxz[r1]; float w = X[r1];
                    atomicAdd(&C[gr * ldc + cc], w * v2);
                    atomicAdd(&C[gr * ldc + cc + 1], w * v3);
                }
            } else if (EPI == 2) {
                float* C = C0 + (long)z * scz;
                if (r0 < M) {
                    float2 xv = *(const float2*)&X[(long)r0 * ldc + cc];
                    *(float2*)&C[(long)r0 * ldc + cc] = make_float2(v0 + xv.x, v1 + xv.y);
                }
                if (r1 < M) {
                    float2 xv = *(const float2*)&X[(long)r1 * ldc + cc];
                    *(float2*)&C[(long)r1 * ldc + cc] = make_float2(v2 + xv.x, v3 + xv.y);
                }
            } else {
                float* C = C0 + (long)z * scz;
                if (r0 < M) *(float2*)&C[(long)r0 * ldc + cc] = make_float2(v0, v1);
                if (r1 < M) *(float2*)&C[(long)r1 * ldc + cc] = make_float2(v2, v3);
            }
        }
    }
}

// ---------------- flash attention (bf16x3, online softmax) ----------------
#define FA_Q  0u
#define FA_QL 40960u
#define FA_K  81920u
#define FA_KL 122880u
#define FA_V  163840u
#define FA_VL 184320u
#define FA_SMEM 204800

__global__ void __launch_bounds__(256, 1) k_flash() {
    extern __shared__ char smem[];
    uint32_t sb = smem_u32(smem);
    int head = blockIdx.x;
    int qb = (int)gridDim.y - 1 - (int)blockIdx.y;
    int row0 = qb * 128;
    int kv = head >> 2;
    int tid = threadIdx.x, lane = tid & 31, w = tid >> 5;
    int lq = lane >> 2, lr = lane & 3;
    int lrow = tid >> 1, lhalf = tid & 1;

    const bf16* qgh = g_qh + (size_t)(row0 + lrow) * (NH * HD) + head * HD + lhalf * 16;
    const bf16* qgl = g_ql + (size_t)(row0 + lrow) * (NH * HD) + head * HD + lhalf * 16;
    const bf16* kgh = g_kbh + (size_t)kv * TT * HD + (size_t)lrow * HD + lhalf * 16;
    const bf16* kgl = g_kbl + (size_t)kv * TT * HD + (size_t)lrow * HD + lhalf * 16;
    const bf16* vgh = g_vth + (size_t)kv * HD * TT + (size_t)lrow * TT + lhalf * 16;
    const bf16* vgl = g_vtl + (size_t)kv * HD * TT + (size_t)lrow * TT + lhalf * 16;

#pragma unroll
    for (int c = 0; c < 4; c++) {
        uint32_t d = sb + FA_Q + (uint32_t)((c * 128 + lrow) * 80) + lhalf * 32;
        cpa(d, qgh + c * 32, 16); cpa(d + 16, qgh + c * 32 + 8, 16);
        uint32_t dl = d + (FA_QL - FA_Q);
        cpa(dl, qgl + c * 32, 16); cpa(dl + 16, qgl + c * 32 + 8, 16);
    }
    cpcommit();

    auto issueK = [&](int s0) {
#pragma unroll
        for (int c = 0; c < 4; c++) {
            uint32_t d = sb + FA_K + (uint32_t)((c * 128 + lrow) * 80) + lhalf * 32;
            const bf16* s = kgh + (size_t)s0 * HD + c * 32;
            cpa(d, s, 16); cpa(d + 16, s + 8, 16);
            uint32_t dl = d + (FA_KL - FA_K);
            const bf16* sl = kgl + (size_t)s0 * HD + c * 32;
            cpa(dl, sl, 16); cpa(dl + 16, sl + 8, 16);
        }
        cpcommit();
    };
    auto issueV = [&](int s0, int c) {
        uint32_t d = sb + FA_V + (uint32_t)(((c & 1) * 128 + lrow) * 80) + lhalf * 32;
        const bf16* s = vgh + s0 + c * 32;
        cpa(d, s, 16); cpa(d + 16, s + 8, 16);
        uint32_t dl = d + (FA_VL - FA_V);
        const bf16* sl = vgl + s0 + c * 32;
        cpa(dl, sl, 16); cpa(dl + 16, sl + 8, 16);
        cpcommit();
    };
    issueK(0);

    float O[16][4];
#pragma unroll
    for (int i = 0; i < 16; i++) { O[i][0] = O[i][1] = O[i][2] = O[i][3] = 0.f; }
    float m_lo = -1e30f, m_hi = -1e30f, l_lo = 0.f, l_hi = 0.f;
    int ntl = qb + 1;
    uint32_t a_off = (uint32_t)((w * 16 + (lane & 15)) * 80) + (uint32_t)(lane >> 4) * 16;
    uint32_t b_off = (uint32_t)((((lane >> 4) << 3) + (lane & 7)) * 80) + (uint32_t)((lane >> 3) & 1) * 16;

    for (int st = 0; st < ntl; st++) {
        int s0 = st * 128;
        __syncthreads();
        issueV(s0, 0); issueV(s0, 1);
        asm volatile("cp.async.wait_group 2;" ::: "memory");
        __syncthreads();

        float S[16][4];
#pragma unroll
        for (int i = 0; i < 16; i++) { S[i][0] = S[i][1] = S[i][2] = S[i][3] = 0.f; }
#pragma unroll
        for (int kc = 0; kc < 4; kc++)
#pragma unroll
        for (int ks = 0; ks < 2; ks++) {
            uint32_t qa = sb + (uint32_t)(kc * 128 * 80) + a_off + ks * 32;
            uint32_t ah[4], al[4];
            ldm4(ah, qa + FA_Q);
            ldm4(al, qa + FA_QL);
#pragma unroll
            for (int j = 0; j < 8; j++) {
                uint32_t kb = sb + FA_K + (uint32_t)((kc * 128 + 16 * j) * 80) + b_off + ks * 32;
                uint32_t bh[4], bl[4];
                ldm4(bh, kb); ldm4(bl, kb + (FA_KL - FA_K));
                mma16816(S[2 * j],     ah, bh);     mma16816(S[2 * j],     ah, bl);     mma16816(S[2 * j],     al, bh);
                mma16816(S[2 * j + 1], ah, bh + 2); mma16816(S[2 * j + 1], ah, bl + 2); mma16816(S[2 * j + 1], al, bh + 2);
            }
        }

        bool dg = (st == qb);
        int rlo = row0 + w * 16 + lq, rhi = rlo + 8;
#pragma unroll
        for (int nt = 0; nt < 16; nt++) {
            int cbase = s0 + nt * 8 + 2 * lr;
#pragma unroll
            for (int q = 0; q < 4; q++) {
                float v = S[nt][q] * ATT_SCALE;
                int col = cbase + (q & 1);
                int rw = (q < 2) ? rlo : rhi;
                if (dg && col > rw) v = -1e30f;
                S[nt][q] = v;
            }
        }
        float mx0 = -1e30f, mx1 = -1e30f;
#pragma unroll
        for (int nt = 0; nt < 16; nt++) {
            mx0 = fmaxf(mx0, fmaxf(S[nt][0], S[nt][1]));
            mx1 = fmaxf(mx1, fmaxf(S[nt][2], S[nt][3]));
        }
        mx0 = fmaxf(mx0, __shfl_xor_sync(0xffffffffu, mx0, 1));
        mx0 = fmaxf(mx0, __shfl_xor_sync(0xffffffffu, mx0, 2));
        mx1 = fmaxf(mx1, __shfl_xor_sync(0xffffffffu, mx1, 1));
        mx1 = fmaxf(mx1, __shfl_xor_sync(0xffffffffu, mx1, 2));
        float mn0 = fmaxf(m_lo, mx0), mn1 = fmaxf(m_hi, mx1);
        float sc0 = expf(m_lo - mn0), sc1 = expf(m_hi - mn1);
        float rs0 = 0.f, rs1 = 0.f;
#pragma unroll
        for (int nt = 0; nt < 16; nt++) {
            S[nt][0] = expf(S[nt][0] - mn0); S[nt][1] = expf(S[nt][1] - mn0);
            S[nt][2] = expf(S[nt][2] - mn1); S[nt][3] = expf(S[nt][3] - mn1);
            rs0 += S[nt][0] + S[nt][1];
            rs1 += S[nt][2] + S[nt][3];
        }
        rs0 += __shfl_xor_sync(0xffffffffu, rs0, 1); rs0 += __shfl_xor_sync(0xffffffffu, rs0, 2);
        rs1 += __shfl_xor_sync(0xffffffffu, rs1, 1); rs1 += __shfl_xor_sync(0xffffffffu, rs1, 2);
        l_lo = l_lo * sc0 + rs0; l_hi = l_hi * sc1 + rs1;
        m_lo = mn0; m_hi = mn1;
#pragma unroll
        for (int nt = 0; nt < 16; nt++) {
            O[nt][0] *= sc0; O[nt][1] *= sc0; O[nt][2] *= sc1; O[nt][3] *= sc1;
        }

        __syncthreads();
        bool haveK = (st + 1 < ntl);
        if (haveK) issueK(s0 + 128);

#pragma unroll 1
        for (int c = 0; c < 4; c++) {
            int pend = haveK ? (c <= 1 ? 2 : (c == 2 ? 1 : 0)) : (c < 3 ? 1 : 0);
            cpwaitN(pend);
            __syncthreads();
#pragma unroll
            for (int ks = 0; ks < 2; ks++) {
                int t0 = 2 * (2 * c + ks), t1 = t0 + 1;
                uint32_t pah[4], pal[4];
                bf16 h0, l0, h1, l1;
                split_bf(S[t0][0], h0, l0); split_bf(S[t0][1], h1, l1);
                pah[0] = pack2(h0, h1); pal[0] = pack2(l0, l1);
                split_bf(S[t0][2], h0, l0); split_bf(S[t0][3], h1, l1);
                pah[1] = pack2(h0, h1); pal[1] = pack2(l0, l1);
                split_bf(S[t1][0], h0, l0); split_bf(S[t1][1], h1, l1);
                pah[2] = pack2(h0, h1); pal[2] = pack2(l0, l1);
                split_bf(S[t1][2], h0, l0); split_bf(S[t1][3], h1, l1);
                pah[3] = pack2(h0, h1); pal[3] = pack2(l0, l1);
#pragma unroll
                for (int j = 0; j < 8; j++) {
                    uint32_t vb = sb + FA_V + (uint32_t)((((c & 1) * 128) + 16 * j) * 80) + b_off + ks * 32;
                    uint32_t vh[4], vl[4];
                    ldm4(vh, vb); ldm4(vl, vb + (FA_VL - FA_V));
                    mma16816(O[2 * j],     pah, vh);     mma16816(O[2 * j],     pah, vl);     mma16816(O[2 * j],     pal, vh);
                    mma16816(O[2 * j + 1], pah, vh + 2); mma16816(O[2 * j + 1], pah, vl + 2); mma16816(O[2 * j + 1], pal, vh + 2);
                }
            }
            __syncthreads();
            if (c + 2 < 4) issueV(s0, c + 2);
        }
    }

    float il0 = 1.f / l_lo, il1 = 1.f / l_hi;
    int rlo = row0 + w * 16 + lq, rhi = rlo + 8;
#pragma unroll
    for (int nt = 0; nt < 16; nt++) {
        long col = (long)head * HD + nt * 8 + 2 * lr;
        bf16 h0, l0, h1, l1;
        float v0 = O[nt][0] * il0, v1 = O[nt][1] * il0;
        split_bf(v0, h0, l0); split_bf(v1, h1, l1);
        *(uint32_t*)&g_attnh[(long)rlo * HH + col] = pack2(h0, h1);
        *(uint32_t*)&g_attnl[(long)rlo * HH + col] = pack2(l0, l1);
        float v2 = O[nt][2] * il1, v3 = O[nt][3] * il1;
        split_bf(v2, h0, l0); split_bf(v3, h1, l1);
        *(uint32_t*)&g_attnh[(long)rhi * HH + col] = pack2(h0, h1);
        *(uint32_t*)&g_attnl[(long)rhi * HH + col] = pack2(l0, l1);
    }
}

// ---------------- streaming convert fp32 -> bf16 hi/lo (no transpose) -------------
__global__ void k_conv(const float* __restrict__ in, bf16* __restrict__ oh,
                       bf16* __restrict__ ol, long n) {
    long i = ((long)blockIdx.x * 256 + threadIdx.x) * 8;
    if (i >= n) return;
    float4 a = *(const float4*)(in + i);
    float4 b = *(const float4*)(in + i + 4);
    bf16 h0, l0, h1, l1;
    uint32_t H[4], L[4];
    split_bf(a.x, h0, l0); split_bf(a.y, h1, l1); H[0] = pack2(h0, h1); L[0] = pack2(l0, l1);
    split_bf(a.z, h0, l0); split_bf(a.w, h1, l1); H[1] = pack2(h0, h1); L[1] = pack2(l0, l1);
    split_bf(b.x, h0, l0); split_bf(b.y, h1, l1); H[2] = pack2(h0, h1); L[2] = pack2(l0, l1);
    split_bf(b.z, h0, l0); split_bf(b.w, h1, l1); H[3] = pack2(h0, h1); L[3] = pack2(l0, l1);
    *(uint4*)(oh + i) = make_uint4(H[0], H[1], H[2], H[3]);
    *(uint4*)(ol + i) = make_uint4(L[0], L[1], L[2], L[3]);
}

// gate/up column interleave: out col 2j = gate j, 2j+1 = up j (in-register pairing)
__global__ void k_conv_gu(const float* __restrict__ in, bf16* __restrict__ oh,
                          bf16* __restrict__ ol) {
    long t = (long)blockIdx.x * 256 + threadIdx.x;
    long rows = (long)NE * HH;
    long perRow = IM / 8;
    if (t >= rows * perRow) return;
    long row = t / perRow;
    long c = (t % perRow) * 8;
    const float* base = in + row * (2 * IM);
    float4 gA = *(const float4*)(base + c);
    float4 gB = *(const float4*)(base + c + 4);
    float4 uA = *(const float4*)(base + IM + c);
    float4 uB = *(const float4*)(base + IM + c + 4);
    bf16 hg, lg, hu, lu;
    uint32_t H[8], L[8];
    split_bf(gA.x, hg, lg); split_bf(uA.x, hu, lu); H[0] = pack2(hg, hu); L[0] = pack2(lg, lu);
    split_bf(gA.y, hg, lg); split_bf(uA.y, hu, lu); H[1] = pack2(hg, hu); L[1] = pack2(lg, lu);
    split_bf(gA.z, hg, lg); split_bf(uA.z, hu, lu); H[2] = pack2(hg, hu); L[2] = pack2(lg, lu);
    split_bf(gA.w, hg, lg); split_bf(uA.w, hu, lu); H[3] = pack2(hg, hu); L[3] = pack2(lg, lu);
    split_bf(gB.x, hg, lg); split_bf(uB.x, hu, lu); H[4] = pack2(hg, hu); L[4] = pack2(lg, lu);
    split_bf(gB.y, hg, lg); split_bf(uB.y, hu, lu); H[5] = pack2(hg, hu); L[5] = pack2(lg, lu);
    split_bf(gB.z, hg, lg); split_bf(uB.z, hu, lu); H[6] = pack2(hg, hu); L[6] = pack2(lg, lu);
    split_bf(gB.w, hg, lg); split_bf(uB.w, hu, lu); H[7] = pack2(hg, hu); L[7] = pack2(lg, lu);
    bf16* po = oh + row * (2 * IM) + 2 * c;
    bf16* pl = ol + row * (2 * IM) + 2 * c;
    *(uint4*)po       = make_uint4(H[0], H[1], H[2], H[3]);
    *(uint4*)(po + 8) = make_uint4(H[4], H[5], H[6], H[7]);
    *(uint4*)pl       = make_uint4(L[0], L[1], L[2], L[3]);
    *(uint4*)(pl + 8) = make_uint4(L[4], L[5], L[6], L[7]);
}

// ---------------- transpose + convert (V only) ----------------
__global__ void k_tconv(const float* __restrict__ in, long ldin, long sbin,
                        bf16* __restrict__ oh, bf16* __restrict__ ol, long ldo, long sbo,
                        int R, int C) {
    __shared__ float t[32][33];
    int z = blockIdx.z;
    const float* I = in + (long)z * sbin;
    int c0 = blockIdx.x * 32, r0 = blockIdx.y * 32;
#pragma unroll
    for (int i = 0; i < 4; i++) {
        int r = r0 + threadIdx.y + i * 8, c = c0 + threadIdx.x;
        t[threadIdx.y + i * 8][threadIdx.x] = (r < R && c < C) ? I[(long)r * ldin + c] : 0.f;
    }
    __syncthreads();
#pragma unroll
    for (int i = 0; i < 4; i++) {
        int orow = c0 + threadIdx.y + i * 8, ocol = r0 + threadIdx.x;
        if (orow < C && ocol < R) {
            bf16 h, l;
            split_bf(t[threadIdx.x][threadIdx.y + i * 8], h, l);
            oh[(long)z * sbo + (long)orow * ldo + ocol] = h;
            ol[(long)z * sbo + (long)orow * ldo + ocol] = l;
        }
    }
}

// ---------------- residual add + rmsnorm ----------------
__global__ void k_addnorm(const float* __restrict__ hs, const float* __restrict__ res,
                          const float* __restrict__ w, float* __restrict__ res_out) {
    int t = blockIdx.x;
    __shared__ float red[256];
    float ss = 0.f;
    for (int i = threadIdx.x; i < HH; i += 256) {
        float v = hs[(size_t)t * HH + i] + res[(size_t)t * HH + i];
        res_out[(size_t)t * HH + i] = v;
        ss += v * v;
    }
    red[threadIdx.x] = ss; __syncthreads();
    for (int s = 128; s > 0; s >>= 1) { if (threadIdx.x < s) red[threadIdx.x] += red[threadIdx.x + s]; __syncthreads(); }
    float inv = rsqrtf(red[0] / (float)HH + EPSV);
    for (int i = threadIdx.x; i < HH; i += 256) {
        float v = res_out[(size_t)t * HH + i] * inv * w[i];
        bf16 h, l; split_bf(v, h, l);
        g_xh[(size_t)t * HH + i] = h; g_xl[(size_t)t * HH + i] = l;
    }
}

__global__ void k_norm(const float* __restrict__ in, const float* __restrict__ w) {
    int t = blockIdx.x;
    __shared__ float red[256];
    float ss = 0.f;
    for (int i = threadIdx.x; i < HH; i += 256) { float v = in[(size_t)t * HH + i]; ss += v * v; }
    red[threadIdx.x] = ss; __syncthreads();
    for (int s = 128; s > 0; s >>= 1) { if (threadIdx.x < s) red[threadIdx.x] += red[threadIdx.x + s]; __syncthreads(); }
    float inv = rsqrtf(red[0] / (float)HH + EPSV);
    for (int i = threadIdx.x; i < HH; i += 256) {
        float v = in[(size_t)t * HH + i] * inv * w[i];
        g_x2[(size_t)t * HH + i] = v;
        bf16 h, l; split_bf(v, h, l);
        g_x2h[(size_t)t * HH + i] = h; g_x2l[(size_t)t * HH + i] = l;
    }
}

// ---------------- RoPE: emit q and k directly as bf16 hi/lo ----------------
__global__ void k_rope(const int* __restrict__ pos, const float* __restrict__ qkv) {
    int t = blockIdx.x;
    float fp = (float)pos[t];
    for (int idx = threadIdx.x; idx < (NH + NKV) * 64; idx += 256) {
        int hh = idx >> 6, d = idx & 63;
        float inv = powf(1e6f, -(float)d / 64.f);
        float ang = fp * inv;
        float c = cosf(ang), s = sinf(ang);
        const float* p = qkv + (size_t)t * QKVD + hh * HD;
        float x1 = p[d], x2 = p[d + 64];
        float v1 = x1 * c - x2 * s;
        float v2 = x2 * c + x1 * s;
        bf16 h1, l1, h2, l2;
        split_bf(v1, h1, l1); split_bf(v2, h2, l2);
        if (hh < NH) {
            size_t b = (size_t)t * (NH * HD) + hh * HD;
            g_qh[b + d] = h1; g_ql[b + d] = l1;
            g_qh[b + d + 64] = h2; g_ql[b + d + 64] = l2;
        } else {
            int kv = hh - NH;
            size_t b = (size_t)kv * TT * HD + (size_t)t * HD;
            g_kbh[b + d] = h1; g_kbl[b + d] = l1;
            g_kbh[b + d + 64] = h2; g_kbl[b + d + 64] = l2;
        }
    }
}

// ---------------- MoE gating ----------------
__global__ void k_gate(const float* __restrict__ x2, const float* __restrict__ gw,
                       const float* __restrict__ gb,
                       int* __restrict__ ids, float* __restrict__ ws) {
    int t = blockIdx.x;
    int tid = threadIdx.x, wid = tid >> 5, lane = tid & 31;
    __shared__ float logit[NE];
    for (int e = wid; e < NE; e += 8) {
        float acc = 0.f;
        for (int i = lane; i < HH; i += 32)
            acc += x2[(size_t)t * HH + i] * gw[(size_t)e * HH + i];
#pragma unroll
        for (int o = 16; o > 0; o >>= 1) acc += __shfl_down_sync(0xffffffffu, acc, o);
        if (lane == 0) logit[e] = acc;
    }
    __syncthreads();
    if (tid == 0) {
        float s[NE], sc[NE];
        for (int e = 0; e < NE; e++) { s[e] = 1.f / (1.f + expf(-logit[e])); sc[e] = s[e] + gb[e]; }
        float gscore[NGRP];
        for (int g = 0; g < NGRP; g++) {
            float a = -3.4e38f, b = -3.4e38f;
            for (int j = 0; j < GSZ; j++) {
                float v = sc[g * GSZ + j];
                if (v > a) { b = a; a = v; } else if (v > b) b = v;
            }
            gscore[g] = a + b;
        }
        bool gsel[NGRP] = {false, false, false, false};
        for (int k = 0; k < TGRP; k++) {
            int best = -1; float bv = -3.4e38f;
            for (int g = 0; g < NGRP; g++)
                if (!gsel[g] && gscore[g] > bv) { bv = gscore[g]; best = g; }
            gsel[best] = true;
        }
        bool used[NE];
        for (int e = 0; e < NE; e++) used[e] = !gsel[e / GSZ];
        float tsum = 0.f;
        int pick[TOPK]; float pw[TOPK];
        for (int k = 0; k < TOPK; k++) {
            int best = -1; float bv = -3.4e38f;
            for (int e = 0; e < NE; e++)
                if (!used[e] && sc[e] > bv) { bv = sc[e]; best = e; }
            used[best] = true;
            pick[k] = best; pw[k] = s[best]; tsum += s[best];
        }
        float inv = 1.f / tsum;
        for (int k = 0; k < TOPK; k++) {
            ids[t * TOPK + k] = pick[k];
            ws[t * TOPK + k] = pw[k] * inv;
        }
    }
}

__global__ void k_scatter(const int* __restrict__ ids, const float* __restrict__ ws) {
    int i = blockIdx.x * 256 + threadIdx.x;
    if (i >= TT * TOPK) return;
    int e = ids[i];
    int slot = atomicAdd(&g_cnt[e], 1);
    g_tok[e * TT + slot] = i / TOPK;
    g_wgt[e * TT + slot] = ws[i];
}

// ---------------- launch ----------------
extern "C" void kernel_launch(void* const* d_in, const int* in_sizes, int n_in,
                              void* d_out_, int out_size) {
    const int*   positions = (const int*)d_in[0];
    const float* hs   = (const float*)d_in[1];
    const float* res  = (const float*)d_in[2];
    const float* wln1 = (const float*)d_in[3];
    const float* wln2 = (const float*)d_in[4];
    const float* wqkv = (const float*)d_in[5];
    const float* wo   = (const float*)d_in[6];
    const float* gw   = (const float*)d_in[7];
    const float* gb   = (const float*)d_in[8];
    const float* wgu  = (const float*)d_in[9];
    const float* wd   = (const float*)d_in[10];
    float* out  = (float*)d_out_;
    float* res2 = out + (size_t)TT * HH;

    void* p;
    float *res1, *qkv, *x2, *wgt;
    bf16 *xh, *xl, *x2h, *x2l, *ath, *atl, *acth, *actl, *vth, *vtl;
    bf16 *wqkvh, *wqkvl, *woh, *wol, *wguh, *wgul, *wdh, *wdl;
    int *cnt, *tok, *tkid; float* tkw;
    cudaGetSymbolAddress(&p, g_res1);   res1 = (float*)p;
    cudaGetSymbolAddress(&p, g_qkv);    qkv = (float*)p;
    cudaGetSymbolAddress(&p, g_x2);     x2 = (float*)p;
    cudaGetSymbolAddress(&p, g_xh);  xh = (bf16*)p;  cudaGetSymbolAddress(&p, g_xl);  xl = (bf16*)p;
    cudaGetSymbolAddress(&p, g_x2h); x2h = (bf16*)p; cudaGetSymbolAddress(&p, g_x2l); x2l = (bf16*)p;
    cudaGetSymbolAddress(&p, g_attnh); ath = (bf16*)p; cudaGetSymbolAddress(&p, g_attnl); atl = (bf16*)p;
    cudaGetSymbolAddress(&p, g_acth); acth = (bf16*)p; cudaGetSymbolAddress(&p, g_actl); actl = (bf16*)p;
    cudaGetSymbolAddress(&p, g_vth); vth = (bf16*)p; cudaGetSymbolAddress(&p, g_vtl); vtl = (bf16*)p;
    cudaGetSymbolAddress(&p, g_wqkvh); wqkvh = (bf16*)p; cudaGetSymbolAddress(&p, g_wqkvl); wqkvl = (bf16*)p;
    cudaGetSymbolAddress(&p, g_woh);   woh = (bf16*)p;   cudaGetSymbolAddress(&p, g_wol);   wol = (bf16*)p;
    cudaGetSymbolAddress(&p, g_wguh);  wguh = (bf16*)p;  cudaGetSymbolAddress(&p, g_wgul);  wgul = (bf16*)p;
    cudaGetSymbolAddress(&p, g_wdh);   wdh = (bf16*)p;   cudaGetSymbolAddress(&p, g_wdl);   wdl = (bf16*)p;
    cudaGetSymbolAddress(&p, g_cnt); cnt = (int*)p;
    cudaGetSymbolAddress(&p, g_tok); tok = (int*)p;
    cudaGetSymbolAddress(&p, g_wgt); wgt = (float*)p;
    cudaGetSymbolAddress(&p, g_topk_id); tkid = (int*)p;
    cudaGetSymbolAddress(&p, g_topk_w);  tkw = (float*)p;

    cudaFuncSetAttribute(gemm_m<false, 0>, cudaFuncAttributeMaxDynamicSharedMemorySize, GSM);
    cudaFuncSetAttribute(gemm_m<false, 2>, cudaFuncAttributeMaxDynamicSharedMemorySize, GSM);
    cudaFuncSetAttribute(gemm_m<true,  5>, cudaFuncAttributeMaxDynamicSharedMemorySize, GSM);
    cudaFuncSetAttribute(gemm_m<false, 3>, cudaFuncAttributeMaxDynamicSharedMemorySize, GSM);
    cudaFuncSetAttribute(k_flash, cudaFuncAttributeMaxDynamicSharedMemorySize, FA_SMEM);

    cudaMemsetAsync(out, 0, (size_t)TT * HH * sizeof(float));
    cudaMemsetAsync(cnt, 0, NE * sizeof(int));

    // prepass converts (no transpose): order chosen so ncu -s 5 profiles qkv GEMM
    { long n = (long)HH * QKVD; k_conv<<<(unsigned)((n / 8 + 255) / 256), 256>>>(wqkv, wqkvh, wqkvl, n); }
    k_addnorm<<<TT, 256>>>(hs, res, wln1, res1);
    { long n = (long)HH * HH;   k_conv<<<(unsigned)((n / 8 + 255) / 256), 256>>>(wo, woh, wol, n); }

    // qkv = x @ wqkv   (launch #6 -> ncu profile target)
    { dim3 g(QKVD / BNT, TT / BMT, 1);
      gemm_m<false, 0><<<g, 256, GSM>>>(
          xh, xl, HH, 0, wqkvh, wqkvl, QKVD, 0, 1,
          qkv, nullptr, nullptr, QKVD, 0, TT, QKVD, HH,
          nullptr, nullptr, 0, nullptr, 0, 1.f); }

    // remaining weight converts
    { long n = (long)NE * HH * (IM / 8); k_conv_gu<<<(unsigned)((n + 255) / 256), 256>>>(wgu, wguh, wgul); }
    { long n = (long)NE * IM * HH; k_conv<<<(unsigned)((n / 8 + 255) / 256), 256>>>(wd, wdh, wdl, n); }

    // rope -> q/k bf16 hi/lo ; V transpose+convert (small)
    k_rope<<<TT, 256>>>(positions, qkv);
    { dim3 g(HD / 32, TT / 32, NKV);
      k_tconv<<<g, dim3(32, 8)>>>(qkv + (NH + NKV) * HD, QKVD, HD, vth, vtl, TT, (long)HD * TT, TT, HD); }

    // flash attention -> attn bf16 hi/lo
    { dim3 g(NH, TT / 128); k_flash<<<g, 256, FA_SMEM>>>(); }

    // res2 = attn @ wo + res1
    { dim3 g(HH / BNT, TT / BMT, 1);
      gemm_m<false, 2><<<g, 256, GSM>>>(
          ath, atl, HH, 0, woh, wol, HH, 0, 1,
          res2, nullptr, nullptr, HH, 0, TT, HH, HH,
          nullptr, nullptr, 0, res1, 0, 1.f); }

    // x2 = rmsnorm(res2)
    k_norm<<<TT, 256>>>(res2, wln2);

    // gating + scatter
    k_gate<<<TT, 256>>>(x2, gw, gb, tkid, tkw);
    k_scatter<<<(TT * TOPK + 255) / 256, 256>>>(tkid, tkw);

    // per-expert gate_up + fused silu -> act bf16 hi/lo (wgu interleaved cols)
    { dim3 g((2 * IM) / BNT, TT / BMT, NE);
      gemm_m<true, 5><<<g, 256, GSM>>>(
          x2h, x2l, HH, 0, wguh, wgul, 2 * IM, (long)HH * 2 * IM, 1,
          nullptr, acth, actl, IM, (long)TT * IM, TT, 2 * IM, HH,
          cnt, tok, TT, nullptr, 0, 1.f); }

    // per-expert down + weighted scatter-add
    { dim3 g(HH / BNT, TT / BMT, NE);
      gemm_m<false, 3><<<g, 256, GSM>>>(
          acth, actl, IM, (long)TT * IM, wdh, wdl, HH, (long)IM * HH, 1,
          out, nullptr, nullptr, HH, 0, TT, HH, IM,
          cnt, tok, TT, wgt, TT, 1.f); }
}

// round 8
// speedup vs baseline: 3.7060x; 1.0766x over previous
#include <cuda_runtime.h>
#include <cuda_bf16.h>
#include <math.h>
#include <stdint.h>

#define TT 2048
#define HH 2048
#define NH 16
#define NKV 4
#define HD 128
#define NE 16
#define TOPK 4
#define NGRP 4
#define GSZ 4
#define TGRP 2
#define IM 1024
#define QKVD 3072
#define ATT_SCALE 0.08838834764831845f
#define EPSV 1e-6f

typedef __nv_bfloat16 bf16;

// ---------------- scratch (device globals; no allocations) ----------------
__device__ float g_res1[(size_t)TT * HH];
__device__ float g_qkv[(size_t)TT * QKVD];
__device__ float g_x2[(size_t)TT * HH];
__device__ bf16  g_xh[(size_t)TT * HH],  g_xl[(size_t)TT * HH];
__device__ bf16  g_x2h[(size_t)TT * HH], g_x2l[(size_t)TT * HH];
__device__ bf16  g_qh[(size_t)TT * (NH * HD)], g_ql[(size_t)TT * (NH * HD)];
__device__ bf16  g_attnh[(size_t)TT * HH], g_attnl[(size_t)TT * HH];
__device__ bf16  g_acth[(size_t)NE * TT * IM], g_actl[(size_t)NE * TT * IM];
__device__ bf16  g_kbh[(size_t)NKV * TT * HD], g_kbl[(size_t)NKV * TT * HD];
__device__ bf16  g_vth[(size_t)NKV * HD * TT], g_vtl[(size_t)NKV * HD * TT];
__device__ bf16  g_wqkvh[(size_t)HH * QKVD], g_wqkvl[(size_t)HH * QKVD];
__device__ bf16  g_woh[(size_t)HH * HH],     g_wol[(size_t)HH * HH];
__device__ bf16  g_wguh[(size_t)NE * HH * 2 * IM], g_wgul[(size_t)NE * HH * 2 * IM];
__device__ bf16  g_wdh[(size_t)NE * IM * HH],      g_wdl[(size_t)NE * IM * HH];
__device__ int   g_cnt[NE];
__device__ int   g_tok[NE * TT];
__device__ float g_wgt[NE * TT];
__device__ int   g_topk_id[TT * TOPK];
__device__ float g_topk_w[TT * TOPK];

// ---------------- helpers ----------------
__device__ __forceinline__ uint32_t smem_u32(const void* p) {
    uint32_t a;
    asm("{ .reg .u64 t; cvta.to.shared.u64 t, %1; cvt.u32.u64 %0, t; }" : "=r"(a) : "l"(p));
    return a;
}
__device__ __forceinline__ void split_bf(float v, bf16& h, bf16& l) {
    h = __float2bfloat16_rn(v);
    l = __float2bfloat16_rn(v - __bfloat162float(h));
}
__device__ __forceinline__ uint32_t pack2(bf16 a, bf16 b) {
    return (uint32_t)__bfloat16_as_ushort(a) | ((uint32_t)__bfloat16_as_ushort(b) << 16);
}
__device__ __forceinline__ void cpa(uint32_t d, const void* s, int sz) {
    asm volatile("cp.async.cg.shared.global [%0], [%1], 16, %2;" :: "r"(d), "l"(s), "r"(sz));
}
__device__ __forceinline__ void cpcommit() { asm volatile("cp.async.commit_group;" ::: "memory"); }
__device__ __forceinline__ void cpwaitN(int n) {
    if (n == 0)      asm volatile("cp.async.wait_group 0;" ::: "memory");
    else if (n == 1) asm volatile("cp.async.wait_group 1;" ::: "memory");
    else             asm volatile("cp.async.wait_group 2;" ::: "memory");
}
__device__ __forceinline__ void ldm4(uint32_t* r, uint32_t a) {
    asm volatile("ldmatrix.sync.aligned.m8n8.x4.shared.b16 {%0,%1,%2,%3}, [%4];"
                 : "=r"(r[0]), "=r"(r[1]), "=r"(r[2]), "=r"(r[3]) : "r"(a));
}
__device__ __forceinline__ void ldm4t(uint32_t* r, uint32_t a) {
    asm volatile("ldmatrix.sync.aligned.m8n8.x4.trans.shared.b16 {%0,%1,%2,%3}, [%4];"
                 : "=r"(r[0]), "=r"(r[1]), "=r"(r[2]), "=r"(r[3]) : "r"(a));
}
__device__ __forceinline__ void mma16816(float* c, const uint32_t* a, const uint32_t* b) {
    asm volatile(
        "mma.sync.aligned.m16n8k16.row.col.f32.bf16.bf16.f32 "
        "{%0,%1,%2,%3},{%4,%5,%6,%7},{%8,%9},{%0,%1,%2,%3};"
        : "+f"(c[0]), "+f"(c[1]), "+f"(c[2]), "+f"(c[3])
        : "r"(a[0]), "r"(a[1]), "r"(a[2]), "r"(a[3]), "r"(b[0]), "r"(b[1]));
}

// ---------------- mma.sync bf16x3 GEMM (B K-major, 3-stage single-sync) -----------
// C[z][M][N] (+)= alpha * A[z] @ W[z] ; W stored [K][N] row-major, bf16 hi/lo.
// EPI: 0 fp32 store, 2 add X, 3 atomicAdd scatter, 5 silu(even)*odd -> bf16 hi/lo.
#define BMT 128
#define BNT 128
#define BKT 32
#define AST 80u
#define BST 272u
#define A_SZ 10240u
#define B_SZ 8704u
#define STG2 (2u * A_SZ + 2u * B_SZ)   // 37888
#define NSTG 3
#define GSM (NSTG * 37888)             // 113664

template <bool GA, int EPI>
__global__ void __launch_bounds__(256, 2)
gemm_m(const bf16* __restrict__ Ah0, const bf16* __restrict__ Al0, int lda, long saz,
       const bf16* __restrict__ Bh0, const bf16* __restrict__ Bl0, int ldb, long sbz, int bdiv,
       float* __restrict__ C0, bf16* __restrict__ Oh0, bf16* __restrict__ Ol0, int ldc, long scz,
       int M0, int N, int K,
       const int* __restrict__ Mptr, const int* __restrict__ gidx0, int sgz,
       const float* __restrict__ X0, long sxz, float alpha) {
    int z = blockIdx.z;
    int M = Mptr ? Mptr[z] : M0;
    int row0 = blockIdx.y * BMT, col0 = blockIdx.x * BNT;
    if (row0 >= M) return;

    extern __shared__ char smem[];
    uint32_t sb = smem_u32(smem);
    int tid = threadIdx.x, lane = tid & 31, wid = tid >> 5;
    const int m0w = (wid & 3) * 32, n0w = (wid >> 2) * 64;

    const int* gidxz = (GA || EPI == 3) ? gidx0 + (long)z * sgz : nullptr;
    const float* X = (EPI == 2 || EPI == 3) ? X0 + (long)z * sxz : nullptr;
    const bf16* Bh = Bh0 + (long)(z / bdiv) * sbz + col0;
    const bf16* Bl = Bl0 + (long)(z / bdiv) * sbz + col0;

    int nch = K / BKT;

    int lrow = tid >> 1, lhalf = tid & 1;
    int ari = row0 + lrow;
    bool av = ari < M;
    long agrow = ari;
    if (GA) agrow = av ? (long)gidxz[ari] : 0;
    const bf16* agh = Ah0 + (long)z * saz + agrow * (long)lda;
    const bf16* agl = Al0 + (long)z * saz + agrow * (long)lda;
    int asz = av ? 16 : 0;
    uint32_t dst_a = sb + lrow * AST + lhalf * 32;
    int brow = tid >> 3, bth = tid & 7;
    uint32_t dst_b = sb + 2 * A_SZ + brow * BST + bth * 32;

    auto cp_stage = [&](int buf, int k0) {
        uint32_t so = buf * STG2;
        long ko = k0 + lhalf * 16;
        cpa(dst_a + so,             agh + ko,     asz);
        cpa(dst_a + so + 16,        agh + ko + 8, asz);
        cpa(dst_a + so + A_SZ,      agl + ko,     asz);
        cpa(dst_a + so + A_SZ + 16, agl + ko + 8, asz);
        long bko = (long)(k0 + brow) * ldb + bth * 16;
        cpa(dst_b + so,             Bh + bko,     16);
        cpa(dst_b + so + 16,        Bh + bko + 8, 16);
        cpa(dst_b + so + B_SZ,      Bl + bko,     16);
        cpa(dst_b + so + B_SZ + 16, Bl + bko + 8, 16);
    };

    float acc[2][8][4];
#pragma unroll
    for (int i = 0; i < 2; i++)
#pragma unroll
        for (int j = 0; j < 8; j++)
#pragma unroll
            for (int q = 0; q < 4; q++) acc[i][j][q] = 0.f;

    uint32_t a_off = (uint32_t)(m0w + (lane & 15)) * AST + (uint32_t)(lane >> 4) * 16;
    uint32_t b_off = (uint32_t)((lane & 7) + ((lane >> 3) & 1) * 8) * BST
                   + (uint32_t)(lane >> 4) * 16;

    auto compute = [&](int buf) {
        uint32_t ab  = sb + buf * STG2;
        uint32_t alb = ab + A_SZ;
        uint32_t bhb = ab + 2 * A_SZ;
        uint32_t blb = bhb + B_SZ;
#pragma unroll
        for (int s = 0; s < 2; s++) {
            uint32_t ka = s * 32;
            uint32_t ah0[4], ah1[4], al0[4], al1[4];
            ldm4(ah0, ab + a_off + ka);
            ldm4(ah1, ab + a_off + 16 * AST + ka);
            ldm4(al0, alb + a_off + ka);
            ldm4(al1, alb + a_off + 16 * AST + ka);
            uint32_t bs = b_off + s * (16 * BST);
#pragma unroll
            for (int np = 0; np < 4; np++) {
                uint32_t bo = bs + (uint32_t)((n0w + np * 16) * 2);
                uint32_t bh[4], bl[4];
                ldm4t(bh, bhb + bo);
                ldm4t(bl, blb + bo);
                int ne = 2 * np, no = 2 * np + 1;
                mma16816(acc[0][ne], ah0, bh);     mma16816(acc[0][ne], ah0, bl);     mma16816(acc[0][ne], al0, bh);
                mma16816(acc[0][no], ah0, bh + 2); mma16816(acc[0][no], ah0, bl + 2); mma16816(acc[0][no], al0, bh + 2);
                mma16816(acc[1][ne], ah1, bh);     mma16816(acc[1][ne], ah1, bl);     mma16816(acc[1][ne], al1, bh);
                mma16816(acc[1][no], ah1, bh + 2); mma16816(acc[1][no], ah1, bl + 2); mma16816(acc[1][no], al1, bh + 2);
            }
        }
    };

    // 3-stage, single-sync multistage pipeline (prologue: stages 0,1)
    cp_stage(0, 0); cpcommit();
    cp_stage(1, BKT); cpcommit();
    int buf = 0;
    for (int c = 0; c < nch; c++) {
        cpwaitN(1);
        __syncthreads();
        compute(buf);
        int nb = buf + 1; if (nb == NSTG) nb = 0;
        int pb = buf + 2; if (pb >= NSTG) pb -= NSTG;   // (buf-1) mod 3
        if (c + 2 < nch) cp_stage(pb, (c + 2) * BKT);
        cpcommit();
        buf = nb;
    }

    // epilogue
    int lq = lane >> 2, lr = lane & 3;
#pragma unroll
    for (int mt = 0; mt < 2; mt++) {
        int r0 = row0 + m0w + mt * 16 + lq;
        int r1 = r0 + 8;
#pragma unroll
        for (int nt = 0; nt < 8; nt++) {
            long cc = (long)col0 + n0w + nt * 8 + 2 * lr;
            float v0 = acc[mt][nt][0] * alpha, v1 = acc[mt][nt][1] * alpha;
            float v2 = acc[mt][nt][2] * alpha, v3 = acc[mt][nt][3] * alpha;
            if (EPI == 5) {
                bf16* oh = Oh0 + (long)z * scz; bf16* ol = Ol0 + (long)z * scz;
                long co = cc >> 1;
                if (r0 < M) {
                    float a = v0 / (1.f + expf(-v0)) * v1;
                    bf16 h, l; split_bf(a, h, l);
                    oh[(long)r0 * ldc + co] = h; ol[(long)r0 * ldc + co] = l;
                }
                if (r1 < M) {
                    float a = v2 / (1.f + expf(-v2)) * v3;
                    bf16 h, l; split_bf(a, h, l);
                    oh[(long)r1 * ldc + co] = h; ol[(long)r1 * ldc + co] = l;
                }
            } else if (EPI == 3) {
                float* C = C0 + (long)z * scz;
                if (r0 < M) {
                    long gr = gidxz[r0]; float w = X[r0];
                    atomicAdd(&C[gr * ldc + cc], w * v0);
                    atomicAdd(&C[gr * ldc + cc + 1], w * v1);
                }
                if (r1 < M) {
                    long gr = gidxz[r1]; float w = X[r1];
                    atomicAdd(&C[gr * ldc + cc], w * v2);
                    atomicAdd(&C[gr * ldc + cc + 1], w * v3);
                }
            } else if (EPI == 2) {
                float* C = C0 + (long)z * scz;
                if (r0 < M) {
                    float2 xv = *(const float2*)&X[(long)r0 * ldc + cc];
                    *(float2*)&C[(long)r0 * ldc + cc] = make_float2(v0 + xv.x, v1 + xv.y);
                }
                if (r1 < M) {
                    float2 xv = *(const float2*)&X[(long)r1 * ldc + cc];
                    *(float2*)&C[(long)r1 * ldc + cc] = make_float2(v2 + xv.x, v3 + xv.y);
                }
            } else {
                float* C = C0 + (long)z * scz;
                if (r0 < M) *(float2*)&C[(long)r0 * ldc + cc] = make_float2(v0, v1);
                if (r1 < M) *(float2*)&C[(long)r1 * ldc + cc] = make_float2(v2, v3);
            }
        }
    }
}

// ---------------- flash attention (bf16x3, online softmax) ----------------
#define FA_Q  0u
#define FA_QL 40960u
#define FA_K  81920u
#define FA_KL 122880u
#define FA_V  163840u
#define FA_VL 184320u
#define FA_SMEM 204800

__global__ void __launch_bounds__(256, 1) k_flash() {
    extern __shared__ char smem[];
    uint32_t sb = smem_u32(smem);
    int head = blockIdx.x;
    int qb = (int)gridDim.y - 1 - (int)blockIdx.y;
    int row0 = qb * 128;
    int kv = head >> 2;
    int tid = threadIdx.x, lane = tid & 31, w = tid >> 5;
    int lq = lane >> 2, lr = lane & 3;
    int lrow = tid >> 1, lhalf = tid & 1;

    const bf16* qgh = g_qh + (size_t)(row0 + lrow) * (NH * HD) + head * HD + lhalf * 16;
    const bf16* qgl = g_ql + (size_t)(row0 + lrow) * (NH * HD) + head * HD + lhalf * 16;
    const bf16* kgh = g_kbh + (size_t)kv * TT * HD + (size_t)lrow * HD + lhalf * 16;
    const bf16* kgl = g_kbl + (size_t)kv * TT * HD + (size_t)lrow * HD + lhalf * 16;
    const bf16* vgh = g_vth + (size_t)kv * HD * TT + (size_t)lrow * TT + lhalf * 16;
    const bf16* vgl = g_vtl + (size_t)kv * HD * TT + (size_t)lrow * TT + lhalf * 16;

#pragma unroll
    for (int c = 0; c < 4; c++) {
        uint32_t d = sb + FA_Q + (uint32_t)((c * 128 + lrow) * 80) + lhalf * 32;
        cpa(d, qgh + c * 32, 16); cpa(d + 16, qgh + c * 32 + 8, 16);
        uint32_t dl = d + (FA_QL - FA_Q);
        cpa(dl, qgl + c * 32, 16); cpa(dl + 16, qgl + c * 32 + 8, 16);
    }
    cpcommit();

    auto issueK = [&](int s0) {
#pragma unroll
        for (int c = 0; c < 4; c++) {
            uint32_t d = sb + FA_K + (uint32_t)((c * 128 + lrow) * 80) + lhalf * 32;
            const bf16* s = kgh + (size_t)s0 * HD + c * 32;
            cpa(d, s, 16); cpa(d + 16, s + 8, 16);
            uint32_t dl = d + (FA_KL - FA_K);
            const bf16* sl = kgl + (size_t)s0 * HD + c * 32;
            cpa(dl, sl, 16); cpa(dl + 16, sl + 8, 16);
        }
        cpcommit();
    };
    auto issueV = [&](int s0, int c) {
        uint32_t d = sb + FA_V + (uint32_t)(((c & 1) * 128 + lrow) * 80) + lhalf * 32;
        const bf16* s = vgh + s0 + c * 32;
        cpa(d, s, 16); cpa(d + 16, s + 8, 16);
        uint32_t dl = d + (FA_VL - FA_V);
        const bf16* sl = vgl + s0 + c * 32;
        cpa(dl, sl, 16); cpa(dl + 16, sl + 8, 16);
        cpcommit();
    };
    issueK(0);

    float O[16][4];
#pragma unroll
    for (int i = 0; i < 16; i++) { O[i][0] = O[i][1] = O[i][2] = O[i][3] = 0.f; }
    float m_lo = -1e30f, m_hi = -1e30f, l_lo = 0.f, l_hi = 0.f;
    int ntl = qb + 1;
    uint32_t a_off = (uint32_t)((w * 16 + (lane & 15)) * 80) + (uint32_t)(lane >> 4) * 16;
    uint32_t b_off = (uint32_t)((((lane >> 4) << 3) + (lane & 7)) * 80) + (uint32_t)((lane >> 3) & 1) * 16;

    for (int st = 0; st < ntl; st++) {
        int s0 = st * 128;
        __syncthreads();
        issueV(s0, 0); issueV(s0, 1);
        asm volatile("cp.async.wait_group 2;" ::: "memory");
        __syncthreads();

        float S[16][4];
#pragma unroll
        for (int i = 0; i < 16; i++) { S[i][0] = S[i][1] = S[i][2] = S[i][3] = 0.f; }
#pragma unroll
        for (int kc = 0; kc < 4; kc++)
#pragma unroll
        for (int ks = 0; ks < 2; ks++) {
            uint32_t qa = sb + (uint32_t)(kc * 128 * 80) + a_off + ks * 32;
            uint32_t ah[4], al[4];
            ldm4(ah, qa + FA_Q);
            ldm4(al, qa + FA_QL);
#pragma unroll
            for (int j = 0; j < 8; j++) {
                uint32_t kb = sb + FA_K + (uint32_t)((kc * 128 + 16 * j) * 80) + b_off + ks * 32;
                uint32_t bh[4], bl[4];
                ldm4(bh, kb); ldm4(bl, kb + (FA_KL - FA_K));
                mma16816(S[2 * j],     ah, bh);     mma16816(S[2 * j],     ah, bl);     mma16816(S[2 * j],     al, bh);
                mma16816(S[2 * j + 1], ah, bh + 2); mma16816(S[2 * j + 1], ah, bl + 2); mma16816(S[2 * j + 1], al, bh + 2);
            }
        }

        bool dg = (st == qb);
        int rlo = row0 + w * 16 + lq, rhi = rlo + 8;
#pragma unroll
        for (int nt = 0; nt < 16; nt++) {
            int cbase = s0 + nt * 8 + 2 * lr;
#pragma unroll
            for (int q = 0; q < 4; q++) {
                float v = S[nt][q] * ATT_SCALE;
                int col = cbase + (q & 1);
                int rw = (q < 2) ? rlo : rhi;
                if (dg && col > rw) v = -1e30f;
                S[nt][q] = v;
            }
        }
        float mx0 = -1e30f, mx1 = -1e30f;
#pragma unroll
        for (int nt = 0; nt < 16; nt++) {
            mx0 = fmaxf(mx0, fmaxf(S[nt][0], S[nt][1]));
            mx1 = fmaxf(mx1, fmaxf(S[nt][2], S[nt][3]));
        }
        mx0 = fmaxf(mx0, __shfl_xor_sync(0xffffffffu, mx0, 1));
        mx0 = fmaxf(mx0, __shfl_xor_sync(0xffffffffu, mx0, 2));
        mx1 = fmaxf(mx1, __shfl_xor_sync(0xffffffffu, mx1, 1));
        mx1 = fmaxf(mx1, __shfl_xor_sync(0xffffffffu, mx1, 2));
        float mn0 = fmaxf(m_lo, mx0), mn1 = fmaxf(m_hi, mx1);
        float sc0 = expf(m_lo - mn0), sc1 = expf(m_hi - mn1);
        float rs0 = 0.f, rs1 = 0.f;
#pragma unroll
        for (int nt = 0; nt < 16; nt++) {
            S[nt][0] = expf(S[nt][0] - mn0); S[nt][1] = expf(S[nt][1] - mn0);
            S[nt][2] = expf(S[nt][2] - mn1); S[nt][3] = expf(S[nt][3] - mn1);
            rs0 += S[nt][0] + S[nt][1];
            rs1 += S[nt][2] + S[nt][3];
        }
        rs0 += __shfl_xor_sync(0xffffffffu, rs0, 1); rs0 += __shfl_xor_sync(0xffffffffu, rs0, 2);
        rs1 += __shfl_xor_sync(0xffffffffu, rs1, 1); rs1 += __shfl_xor_sync(0xffffffffu, rs1, 2);
        l_lo = l_lo * sc0 + rs0; l_hi = l_hi * sc1 + rs1;
        m_lo = mn0; m_hi = mn1;
#pragma unroll
        for (int nt = 0; nt < 16; nt++) {
            O[nt][0] *= sc0; O[nt][1] *= sc0; O[nt][2] *= sc1; O[nt][3] *= sc1;
        }

        __syncthreads();
        bool haveK = (st + 1 < ntl);
        if (haveK) issueK(s0 + 128);

#pragma unroll 1
        for (int c = 0; c < 4; c++) {
            int pend = haveK ? (c <= 1 ? 2 : (c == 2 ? 1 : 0)) : (c < 3 ? 1 : 0);
            cpwaitN(pend);
            __syncthreads();
#pragma unroll
            for (int ks = 0; ks < 2; ks++) {
                int t0 = 2 * (2 * c + ks), t1 = t0 + 1;
                uint32_t pah[4], pal[4];
                bf16 h0, l0, h1, l1;
                split_bf(S[t0][0], h0, l0); split_bf(S[t0][1], h1, l1);
                pah[0] = pack2(h0, h1); pal[0] = pack2(l0, l1);
                split_bf(S[t0][2], h0, l0); split_bf(S[t0][3], h1, l1);
                pah[1] = pack2(h0, h1); pal[1] = pack2(l0, l1);
                split_bf(S[t1][0], h0, l0); split_bf(S[t1][1], h1, l1);
                pah[2] = pack2(h0, h1); pal[2] = pack2(l0, l1);
                split_bf(S[t1][2], h0, l0); split_bf(S[t1][3], h1, l1);
                pah[3] = pack2(h0, h1); pal[3] = pack2(l0, l1);
#pragma unroll
                for (int j = 0; j < 8; j++) {
                    uint32_t vb = sb + FA_V + (uint32_t)((((c & 1) * 128) + 16 * j) * 80) + b_off + ks * 32;
                    uint32_t vh[4], vl[4];
                    ldm4(vh, vb); ldm4(vl, vb + (FA_VL - FA_V));
                    mma16816(O[2 * j],     pah, vh);     mma16816(O[2 * j],     pah, vl);     mma16816(O[2 * j],     pal, vh);
                    mma16816(O[2 * j + 1], pah, vh + 2); mma16816(O[2 * j + 1], pah, vl + 2); mma16816(O[2 * j + 1], pal, vh + 2);
                }
            }
            __syncthreads();
            if (c + 2 < 4) issueV(s0, c + 2);
        }
    }

    float il0 = 1.f / l_lo, il1 = 1.f / l_hi;
    int rlo = row0 + w * 16 + lq, rhi = rlo + 8;
#pragma unroll
    for (int nt = 0; nt < 16; nt++) {
        long col = (long)head * HD + nt * 8 + 2 * lr;
        bf16 h0, l0, h1, l1;
        float v0 = O[nt][0] * il0, v1 = O[nt][1] * il0;
        split_bf(v0, h0, l0); split_bf(v1, h1, l1);
        *(uint32_t*)&g_attnh[(long)rlo * HH + col] = pack2(h0, h1);
        *(uint32_t*)&g_attnl[(long)rlo * HH + col] = pack2(l0, l1);
        float v2 = O[nt][2] * il1, v3 = O[nt][3] * il1;
        split_bf(v2, h0, l0); split_bf(v3, h1, l1);
        *(uint32_t*)&g_attnh[(long)rhi * HH + col] = pack2(h0, h1);
        *(uint32_t*)&g_attnl[(long)rhi * HH + col] = pack2(l0, l1);
    }
}

// ---------------- streaming convert fp32 -> bf16 hi/lo ----------------
__global__ void k_conv(const float* __restrict__ in, bf16* __restrict__ oh,
                       bf16* __restrict__ ol, long n) {
    long i = ((long)blockIdx.x * 256 + threadIdx.x) * 8;
    if (i >= n) return;
    float4 a = *(const float4*)(in + i);
    float4 b = *(const float4*)(in + i + 4);
    bf16 h0, l0, h1, l1;
    uint32_t H[4], L[4];
    split_bf(a.x, h0, l0); split_bf(a.y, h1, l1); H[0] = pack2(h0, h1); L[0] = pack2(l0, l1);
    split_bf(a.z, h0, l0); split_bf(a.w, h1, l1); H[1] = pack2(h0, h1); L[1] = pack2(l0, l1);
    split_bf(b.x, h0, l0); split_bf(b.y, h1, l1); H[2] = pack2(h0, h1); L[2] = pack2(l0, l1);
    split_bf(b.z, h0, l0); split_bf(b.w, h1, l1); H[3] = pack2(h0, h1); L[3] = pack2(l0, l1);
    *(uint4*)(oh + i) = make_uint4(H[0], H[1], H[2], H[3]);
    *(uint4*)(ol + i) = make_uint4(L[0], L[1], L[2], L[3]);
}

// gate/up column interleave
__global__ void k_conv_gu(const float* __restrict__ in, bf16* __restrict__ oh,
                          bf16* __restrict__ ol) {
    long t = (long)blockIdx.x * 256 + threadIdx.x;
    long rows = (long)NE * HH;
    long perRow = IM / 8;
    if (t >= rows * perRow) return;
    long row = t / perRow;
    long c = (t % perRow) * 8;
    const float* base = in + row * (2 * IM);
    float4 gA = *(const float4*)(base + c);
    float4 gB = *(const float4*)(base + c + 4);
    float4 uA = *(const float4*)(base + IM + c);
    float4 uB = *(const float4*)(base + IM + c + 4);
    bf16 hg, lg, hu, lu;
    uint32_t H[8], L[8];
    split_bf(gA.x, hg, lg); split_bf(uA.x, hu, lu); H[0] = pack2(hg, hu); L[0] = pack2(lg, lu);
    split_bf(gA.y, hg, lg); split_bf(uA.y, hu, lu); H[1] = pack2(hg, hu); L[1] = pack2(lg, lu);
    split_bf(gA.z, hg, lg); split_bf(uA.z, hu, lu); H[2] = pack2(hg, hu); L[2] = pack2(lg, lu);
    split_bf(gA.w, hg, lg); split_bf(uA.w, hu, lu); H[3] = pack2(hg, hu); L[3] = pack2(lg, lu);
    split_bf(gB.x, hg, lg); split_bf(uB.x, hu, lu); H[4] = pack2(hg, hu); L[4] = pack2(lg, lu);
    split_bf(gB.y, hg, lg); split_bf(uB.y, hu, lu); H[5] = pack2(hg, hu); L[5] = pack2(lg, lu);
    split_bf(gB.z, hg, lg); split_bf(uB.z, hu, lu); H[6] = pack2(hg, hu); L[6] = pack2(lg, lu);
    split_bf(gB.w, hg, lg); split_bf(uB.w, hu, lu); H[7] = pack2(hg, hu); L[7] = pack2(lg, lu);
    bf16* po = oh + row * (2 * IM) + 2 * c;
    bf16* pl = ol + row * (2 * IM) + 2 * c;
    *(uint4*)po       = make_uint4(H[0], H[1], H[2], H[3]);
    *(uint4*)(po + 8) = make_uint4(H[4], H[5], H[6], H[7]);
    *(uint4*)pl       = make_uint4(L[0], L[1], L[2], L[3]);
    *(uint4*)(pl + 8) = make_uint4(L[4], L[5], L[6], L[7]);
}

// ---------------- transpose + convert (V only) ----------------
__global__ void k_tconv(const float* __restrict__ in, long ldin, long sbin,
                        bf16* __restrict__ oh, bf16* __restrict__ ol, long ldo, long sbo,
                        int R, int C) {
    __shared__ float t[32][33];
    int z = blockIdx.z;
    const float* I = in + (long)z * sbin;
    int c0 = blockIdx.x * 32, r0 = blockIdx.y * 32;
#pragma unroll
    for (int i = 0; i < 4; i++) {
        int r = r0 + threadIdx.y + i * 8, c = c0 + threadIdx.x;
        t[threadIdx.y + i * 8][threadIdx.x] = (r < R && c < C) ? I[(long)r * ldin + c] : 0.f;
    }
    __syncthreads();
#pragma unroll
    for (int i = 0; i < 4; i++) {
        int orow = c0 + threadIdx.y + i * 8, ocol = r0 + threadIdx.x;
        if (orow < C && ocol < R) {
            bf16 h, l;
            split_bf(t[threadIdx.x][threadIdx.y + i * 8], h, l);
            oh[(long)z * sbo + (long)orow * ldo + ocol] = h;
            ol[(long)z * sbo + (long)orow * ldo + ocol] = l;
        }
    }
}

// ---------------- residual add + rmsnorm ----------------
__global__ void k_addnorm(const float* __restrict__ hs, const float* __restrict__ res,
                          const float* __restrict__ w, float* __restrict__ res_out) {
    int t = blockIdx.x;
    __shared__ float red[256];
    float ss = 0.f;
    for (int i = threadIdx.x; i < HH; i += 256) {
        float v = hs[(size_t)t * HH + i] + res[(size_t)t * HH + i];
        res_out[(size_t)t * HH + i] = v;
        ss += v * v;
    }
    red[threadIdx.x] = ss; __syncthreads();
    for (int s = 128; s > 0; s >>= 1) { if (threadIdx.x < s) red[threadIdx.x] += red[threadIdx.x + s]; __syncthreads(); }
    float inv = rsqrtf(red[0] / (float)HH + EPSV);
    for (int i = threadIdx.x; i < HH; i += 256) {
        float v = res_out[(size_t)t * HH + i] * inv * w[i];
        bf16 h, l; split_bf(v, h, l);
        g_xh[(size_t)t * HH + i] = h; g_xl[(size_t)t * HH + i] = l;
    }
}

__global__ void k_norm(const float* __restrict__ in, const float* __restrict__ w) {
    int t = blockIdx.x;
    __shared__ float red[256];
    float ss = 0.f;
    for (int i = threadIdx.x; i < HH; i += 256) { float v = in[(size_t)t * HH + i]; ss += v * v; }
    red[threadIdx.x] = ss; __syncthreads();
    for (int s = 128; s > 0; s >>= 1) { if (threadIdx.x < s) red[threadIdx.x] += red[threadIdx.x + s]; __syncthreads(); }
    float inv = rsqrtf(red[0] / (float)HH + EPSV);
    for (int i = threadIdx.x; i < HH; i += 256) {
        float v = in[(size_t)t * HH + i] * inv * w[i];
        g_x2[(size_t)t * HH + i] = v;
        bf16 h, l; split_bf(v, h, l);
        g_x2h[(size_t)t * HH + i] = h; g_x2l[(size_t)t * HH + i] = l;
    }
}

// ---------------- RoPE ----------------
__global__ void k_rope(const int* __restrict__ pos, const float* __restrict__ qkv) {
    int t = blockIdx.x;
    float fp = (float)pos[t];
    for (int idx = threadIdx.x; idx < (NH + NKV) * 64; idx += 256) {
        int hh = idx >> 6, d = idx & 63;
        float inv = powf(1e6f, -(float)d / 64.f);
        float ang = fp * inv;
        float c = cosf(ang), s = sinf(ang);
        const float* p = qkv + (size_t)t * QKVD + hh * HD;
        float x1 = p[d], x2 = p[d + 64];
        float v1 = x1 * c - x2 * s;
        float v2 = x2 * c + x1 * s;
        bf16 h1, l1, h2, l2;
        split_bf(v1, h1, l1); split_bf(v2, h2, l2);
        if (hh < NH) {
            size_t b = (size_t)t * (NH * HD) + hh * HD;
            g_qh[b + d] = h1; g_ql[b + d] = l1;
            g_qh[b + d + 64] = h2; g_ql[b + d + 64] = l2;
        } else {
            int kv = hh - NH;
            size_t b = (size_t)kv * TT * HD + (size_t)t * HD;
            g_kbh[b + d] = h1; g_kbl[b + d] = l1;
            g_kbh[b + d + 64] = h2; g_kbl[b + d + 64] = l2;
        }
    }
}

// ---------------- MoE gating ----------------
__global__ void k_gate(const float* __restrict__ x2, const float* __restrict__ gw,
                       const float* __restrict__ gb,
                       int* __restrict__ ids, float* __restrict__ ws) {
    int t = blockIdx.x;
    int tid = threadIdx.x, wid = tid >> 5, lane = tid & 31;
    __shared__ float logit[NE];
    for (int e = wid; e < NE; e += 8) {
        float acc = 0.f;
        for (int i = lane; i < HH; i += 32)
            acc += x2[(size_t)t * HH + i] * gw[(size_t)e * HH + i];
#pragma unroll
        for (int o = 16; o > 0; o >>= 1) acc += __shfl_down_sync(0xffffffffu, acc, o);
        if (lane == 0) logit[e] = acc;
    }
    __syncthreads();
    if (tid == 0) {
        float s[NE], sc[NE];
        for (int e = 0; e < NE; e++) { s[e] = 1.f / (1.f + expf(-logit[e])); sc[e] = s[e] + gb[e]; }
        float gscore[NGRP];
        for (int g = 0; g < NGRP; g++) {
            float a = -3.4e38f, b = -3.4e38f;
            for (int j = 0; j < GSZ; j++) {
                float v = sc[g * GSZ + j];
                if (v > a) { b = a; a = v; } else if (v > b) b = v;
            }
            gscore[g] = a + b;
        }
        bool gsel[NGRP] = {false, false, false, false};
        for (int k = 0; k < TGRP; k++) {
            int best = -1; float bv = -3.4e38f;
            for (int g = 0; g < NGRP; g++)
                if (!gsel[g] && gscore[g] > bv) { bv = gscore[g]; best = g; }
            gsel[best] = true;
        }
        bool used[NE];
        for (int e = 0; e < NE; e++) used[e] = !gsel[e / GSZ];
        float tsum = 0.f;
        int pick[TOPK]; float pw[TOPK];
        for (int k = 0; k < TOPK; k++) {
            int best = -1; float bv = -3.4e38f;
            for (int e = 0; e < NE; e++)
                if (!used[e] && sc[e] > bv) { bv = sc[e]; best = e; }
            used[best] = true;
            pick[k] = best; pw[k] = s[best]; tsum += s[best];
        }
        float inv = 1.f / tsum;
        for (int k = 0; k < TOPK; k++) {
            ids[t * TOPK + k] = pick[k];
            ws[t * TOPK + k] = pw[k] * inv;
        }
    }
}

__global__ void k_scatter(const int* __restrict__ ids, const float* __restrict__ ws) {
    int i = blockIdx.x * 256 + threadIdx.x;
    if (i >= TT * TOPK) return;
    int e = ids[i];
    int slot = atomicAdd(&g_cnt[e], 1);
    g_tok[e * TT + slot] = i / TOPK;
    g_wgt[e * TT + slot] = ws[i];
}

// ---------------- launch ----------------
extern "C" void kernel_launch(void* const* d_in, const int* in_sizes, int n_in,
                              void* d_out_, int out_size) {
    const int*   positions = (const int*)d_in[0];
    const float* hs   = (const float*)d_in[1];
    const float* res  = (const float*)d_in[2];
    const float* wln1 = (const float*)d_in[3];
    const float* wln2 = (const float*)d_in[4];
    const float* wqkv = (const float*)d_in[5];
    const float* wo   = (const float*)d_in[6];
    const float* gw   = (const float*)d_in[7];
    const float* gb   = (const float*)d_in[8];
    const float* wgu  = (const float*)d_in[9];
    const float* wd   = (const float*)d_in[10];
    float* out  = (float*)d_out_;
    float* res2 = out + (size_t)TT * HH;

    void* p;
    float *res1, *qkv, *x2, *wgt;
    bf16 *xh, *xl, *x2h, *x2l, *ath, *atl, *acth, *actl, *vth, *vtl;
    bf16 *wqkvh, *wqkvl, *woh, *wol, *wguh, *wgul, *wdh, *wdl;
    int *cnt, *tok, *tkid; float* tkw;
    cudaGetSymbolAddress(&p, g_res1);   res1 = (float*)p;
    cudaGetSymbolAddress(&p, g_qkv);    qkv = (float*)p;
    cudaGetSymbolAddress(&p, g_x2);     x2 = (float*)p;
    cudaGetSymbolAddress(&p, g_xh);  xh = (bf16*)p;  cudaGetSymbolAddress(&p, g_xl);  xl = (bf16*)p;
    cudaGetSymbolAddress(&p, g_x2h); x2h = (bf16*)p; cudaGetSymbolAddress(&p, g_x2l); x2l = (bf16*)p;
    cudaGetSymbolAddress(&p, g_attnh); ath = (bf16*)p; cudaGetSymbolAddress(&p, g_attnl); atl = (bf16*)p;
    cudaGetSymbolAddress(&p, g_acth); acth = (bf16*)p; cudaGetSymbolAddress(&p, g_actl); actl = (bf16*)p;
    cudaGetSymbolAddress(&p, g_vth); vth = (bf16*)p; cudaGetSymbolAddress(&p, g_vtl); vtl = (bf16*)p;
    cudaGetSymbolAddress(&p, g_wqkvh); wqkvh = (bf16*)p; cudaGetSymbolAddress(&p, g_wqkvl); wqkvl = (bf16*)p;
    cudaGetSymbolAddress(&p, g_woh);   woh = (bf16*)p;   cudaGetSymbolAddress(&p, g_wol);   wol = (bf16*)p;
    cudaGetSymbolAddress(&p, g_wguh);  wguh = (bf16*)p;  cudaGetSymbolAddress(&p, g_wgul);  wgul = (bf16*)p;
    cudaGetSymbolAddress(&p, g_wdh);   wdh = (bf16*)p;   cudaGetSymbolAddress(&p, g_wdl);   wdl = (bf16*)p;
    cudaGetSymbolAddress(&p, g_cnt); cnt = (int*)p;
    cudaGetSymbolAddress(&p, g_tok); tok = (int*)p;
    cudaGetSymbolAddress(&p, g_wgt); wgt = (float*)p;
    cudaGetSymbolAddress(&p, g_topk_id); tkid = (int*)p;
    cudaGetSymbolAddress(&p, g_topk_w);  tkw = (float*)p;

    cudaFuncSetAttribute(gemm_m<false, 0>, cudaFuncAttributeMaxDynamicSharedMemorySize, GSM);
    cudaFuncSetAttribute(gemm_m<false, 2>, cudaFuncAttributeMaxDynamicSharedMemorySize, GSM);
    cudaFuncSetAttribute(gemm_m<true,  5>, cudaFuncAttributeMaxDynamicSharedMemorySize, GSM);
    cudaFuncSetAttribute(gemm_m<false, 3>, cudaFuncAttributeMaxDynamicSharedMemorySize, GSM);
    cudaFuncSetAttribute(k_flash, cudaFuncAttributeMaxDynamicSharedMemorySize, FA_SMEM);

    cudaMemsetAsync(out, 0, (size_t)TT * HH * sizeof(float));
    cudaMemsetAsync(cnt, 0, NE * sizeof(int));

    // prepass converts (order keeps qkv GEMM at ncu launch #6)
    { long n = (long)HH * QKVD; k_conv<<<(unsigned)((n / 8 + 255) / 256), 256>>>(wqkv, wqkvh, wqkvl, n); }
    k_addnorm<<<TT, 256>>>(hs, res, wln1, res1);
    { long n = (long)HH * HH;   k_conv<<<(unsigned)((n / 8 + 255) / 256), 256>>>(wo, woh, wol, n); }

    // qkv = x @ wqkv
    { dim3 g(QKVD / BNT, TT / BMT, 1);
      gemm_m<false, 0><<<g, 256, GSM>>>(
          xh, xl, HH, 0, wqkvh, wqkvl, QKVD, 0, 1,
          qkv, nullptr, nullptr, QKVD, 0, TT, QKVD, HH,
          nullptr, nullptr, 0, nullptr, 0, 1.f); }

    // remaining weight converts
    { long n = (long)NE * HH * (IM / 8); k_conv_gu<<<(unsigned)((n + 255) / 256), 256>>>(wgu, wguh, wgul); }
    { long n = (long)NE * IM * HH; k_conv<<<(unsigned)((n / 8 + 255) / 256), 256>>>(wd, wdh, wdl, n); }

    // rope ; V transpose+convert
    k_rope<<<TT, 256>>>(positions, qkv);
    { dim3 g(HD / 32, TT / 32, NKV);
      k_tconv<<<g, dim3(32, 8)>>>(qkv + (NH + NKV) * HD, QKVD, HD, vth, vtl, TT, (long)HD * TT, TT, HD); }

    // flash attention
    { dim3 g(NH, TT / 128); k_flash<<<g, 256, FA_SMEM>>>(); }

    // res2 = attn @ wo + res1
    { dim3 g(HH / BNT, TT / BMT, 1);
      gemm_m<false, 2><<<g, 256, GSM>>>(
          ath, atl, HH, 0, woh, wol, HH, 0, 1,
          res2, nullptr, nullptr, HH, 0, TT, HH, HH,
          nullptr, nullptr, 0, res1, 0, 1.f); }

    // x2 = rmsnorm(res2)
    k_norm<<<TT, 256>>>(res2, wln2);

    // gating + scatter
    k_gate<<<TT, 256>>>(x2, gw, gb, tkid, tkw);
    k_scatter<<<(TT * TOPK + 255) / 256, 256>>>(tkid, tkw);

    // per-expert gate_up + fused silu
    { dim3 g((2 * IM) / BNT, TT / BMT, NE);
      gemm_m<true, 5><<<g, 256, GSM>>>(
          x2h, x2l, HH, 0, wguh, wgul, 2 * IM, (long)HH * 2 * IM, 1,
          nullptr, acth, actl, IM, (long)TT * IM, TT, 2 * IM, HH,
          cnt, tok, TT, nullptr, 0, 1.f); }

    // per-expert down + weighted scatter-add
    { dim3 g(HH / BNT, TT / BMT, NE);
      gemm_m<false, 3><<<g, 256, GSM>>>(
          acth, actl, IM, (long)TT * IM, wdh, wdl, HH, (long)IM * HH, 1,
          out, nullptr, nullptr, HH, 0, TT, HH, IM,
          cnt, tok, TT, wgt, TT, 1.f); }
}